// round 2
// baseline (speedup 1.0000x reference)
#include <cuda_runtime.h>
#include <cuda_bf16.h>
#include <math.h>

// ----------------------------------------------------------------------------
// Problem constants
// ----------------------------------------------------------------------------
#define B        4
#define S        2048
#define T        (B * S)          // 8192 tokens
#define DM       1024             // d_model
#define NH       16               // heads
#define DH       64               // head dim
#define QKV3     (3 * NH * DH)    // 3072
#define FFN      4096
#define FFN2     (2 * FFN)        // 8192

// ----------------------------------------------------------------------------
// Scratch (device globals -> no allocation inside kernel_launch)
// ----------------------------------------------------------------------------
__device__ float g_Xn  [(size_t)T * DM];    // layernorm output (reused for ln1/ln2)
__device__ float g_qkv [(size_t)T * QKV3];  // qkv projection (interleaved)
__device__ float g_q   [(size_t)T * DM];    // [b][h][s][d]
__device__ float g_k   [(size_t)T * DM];
__device__ float g_v   [(size_t)T * DM];
__device__ float g_att [(size_t)T * DM];    // attention output [t][h*64+d]
__device__ float g_X1  [(size_t)T * DM];    // X + attn @ Wo^T
__device__ float g_u   [(size_t)T * FFN2];  // fc1 output (a | g)
__device__ float g_h   [(size_t)T * FFN];   // a * gelu(g)

// ----------------------------------------------------------------------------
// LayerNorm: one block per row of 1024
// ----------------------------------------------------------------------------
__global__ __launch_bounds__(256) void ln_kernel(const float* __restrict__ X,
                                                 const float* __restrict__ w,
                                                 float* __restrict__ Y) {
    const int row = blockIdx.x;
    const int tid = threadIdx.x;
    const float4* xp = (const float4*)(X + (size_t)row * DM);
    float4 v = xp[tid];

    float s  = v.x + v.y + v.z + v.w;
    float sq = v.x * v.x + v.y * v.y + v.z * v.z + v.w * v.w;

    __shared__ float rs[256];
    __shared__ float rq[256];
    rs[tid] = s; rq[tid] = sq;
    __syncthreads();
    #pragma unroll
    for (int o = 128; o >= 1; o >>= 1) {
        if (tid < o) { rs[tid] += rs[tid + o]; rq[tid] += rq[tid + o]; }
        __syncthreads();
    }
    const float mu   = rs[0] * (1.0f / DM);
    const float var  = rq[0] * (1.0f / DM) - mu * mu;
    const float rstd = rsqrtf(var + 1e-5f);

    const float4 wv = ((const float4*)w)[tid];
    float4 o4;
    o4.x = (v.x - mu) * rstd * wv.x;
    o4.y = (v.y - mu) * rstd * wv.y;
    o4.z = (v.z - mu) * rstd * wv.z;
    o4.w = (v.w - mu) * rstd * wv.w;
    ((float4*)(Y + (size_t)row * DM))[tid] = o4;
}

// ----------------------------------------------------------------------------
// NT GEMM: C[m,n] = sum_k A[m,k] * B[n,k]   (A: [M,K], B: [N,K], row-major)
// Tile 128x128x8, 256 threads, 8x8 per thread, double-buffered smem.
// EPI 0: C = AB       EPI 1: C = R + AB
// Requires: M%128==0, N%128==0, K%8==0 (true for all our shapes)
// ----------------------------------------------------------------------------
template <int EPI>
__global__ __launch_bounds__(256) void gemm_nt(const float* __restrict__ A,
                                               const float* __restrict__ Bm,
                                               const float* __restrict__ R,
                                               float* __restrict__ C,
                                               int M, int N, int K) {
    __shared__ float As[2][8][128];
    __shared__ float Bs[2][8][128];

    const int tid = threadIdx.x;
    const int tx  = tid & 15;     // 0..15 (N dir)
    const int ty  = tid >> 4;     // 0..15 (M dir)
    const int m0  = blockIdx.y * 128;
    const int n0  = blockIdx.x * 128;

    // loader mapping: each thread loads one float4 of A tile + one of B tile
    const int lr = tid >> 1;          // 0..127 tile row
    const int lk = (tid & 1) * 4;     // 0 or 4 (k offset)

    const float* Ap = A  + (size_t)(m0 + lr) * K + lk;
    const float* Bp = Bm + (size_t)(n0 + lr) * K + lk;

    float acc[8][8];
    #pragma unroll
    for (int i = 0; i < 8; i++)
        #pragma unroll
        for (int j = 0; j < 8; j++) acc[i][j] = 0.0f;

    // prologue: load tile 0
    {
        const float4 a4 = *(const float4*)Ap;
        const float4 b4 = *(const float4*)Bp;
        As[0][lk + 0][lr] = a4.x; As[0][lk + 1][lr] = a4.y;
        As[0][lk + 2][lr] = a4.z; As[0][lk + 3][lr] = a4.w;
        Bs[0][lk + 0][lr] = b4.x; Bs[0][lk + 1][lr] = b4.y;
        Bs[0][lk + 2][lr] = b4.z; Bs[0][lk + 3][lr] = b4.w;
    }
    __syncthreads();

    const int ntiles = K >> 3;
    int buf = 0;
    for (int t = 0; t < ntiles; t++) {
        float4 an, bn;
        const bool hasNext = (t + 1 < ntiles);
        if (hasNext) {
            an = *(const float4*)(Ap + (size_t)(t + 1) * 8);
            bn = *(const float4*)(Bp + (size_t)(t + 1) * 8);
        }

        #pragma unroll
        for (int k = 0; k < 8; k++) {
            const float4 av0 = *(const float4*)&As[buf][k][ty * 8];
            const float4 av1 = *(const float4*)&As[buf][k][ty * 8 + 4];
            const float4 bv0 = *(const float4*)&Bs[buf][k][tx * 8];
            const float4 bv1 = *(const float4*)&Bs[buf][k][tx * 8 + 4];
            const float ar[8] = {av0.x, av0.y, av0.z, av0.w,
                                 av1.x, av1.y, av1.z, av1.w};
            const float br[8] = {bv0.x, bv0.y, bv0.z, bv0.w,
                                 bv1.x, bv1.y, bv1.z, bv1.w};
            #pragma unroll
            for (int i = 0; i < 8; i++)
                #pragma unroll
                for (int j = 0; j < 8; j++)
                    acc[i][j] += ar[i] * br[j];
        }

        if (hasNext) {
            buf ^= 1;
            As[buf][lk + 0][lr] = an.x; As[buf][lk + 1][lr] = an.y;
            As[buf][lk + 2][lr] = an.z; As[buf][lk + 3][lr] = an.w;
            Bs[buf][lk + 0][lr] = bn.x; Bs[buf][lk + 1][lr] = bn.y;
            Bs[buf][lk + 2][lr] = bn.z; Bs[buf][lk + 3][lr] = bn.w;
            __syncthreads();
        }
    }

    #pragma unroll
    for (int i = 0; i < 8; i++) {
        const size_t row = (size_t)(m0 + ty * 8 + i);
        float4 o0, o1;
        o0.x = acc[i][0]; o0.y = acc[i][1]; o0.z = acc[i][2]; o0.w = acc[i][3];
        o1.x = acc[i][4]; o1.y = acc[i][5]; o1.z = acc[i][6]; o1.w = acc[i][7];
        const size_t base = row * N + n0 + tx * 8;
        if (EPI == 1) {
            const float4 r0 = *(const float4*)(R + base);
            const float4 r1 = *(const float4*)(R + base + 4);
            o0.x += r0.x; o0.y += r0.y; o0.z += r0.z; o0.w += r0.w;
            o1.x += r1.x; o1.y += r1.y; o1.z += r1.z; o1.w += r1.w;
        }
        *(float4*)(C + base)     = o0;
        *(float4*)(C + base + 4) = o1;
    }
}

// ----------------------------------------------------------------------------
// De-interleave qkv[t, h*192 + d*3 + c] -> Q/K/V [b][h][s][d]
// ----------------------------------------------------------------------------
__global__ __launch_bounds__(256) void reshape_qkv(const float* __restrict__ qkv,
                                                   float* __restrict__ Q,
                                                   float* __restrict__ Kd,
                                                   float* __restrict__ V) {
    const size_t gid = (size_t)blockIdx.x * 256 + threadIdx.x; // t*1024 + h*64 + d
    const int t = (int)(gid >> 10);
    const int r = (int)(gid & 1023);
    const int h = r >> 6;
    const int d = r & 63;
    const int b = t >> 11;
    const int s = t & 2047;
    const float* src = qkv + (size_t)t * QKV3 + h * (DH * 3) + d * 3;
    const size_t dst = (((size_t)(b * NH + h)) * S + s) * DH + d;
    Q[dst]  = src[0];
    Kd[dst] = src[1];
    V[dst]  = src[2];
}

// ----------------------------------------------------------------------------
// Flash attention (fp32). One thread = one query row. 128 q rows / block.
// Grid: (S/128, NH, B). K/V tiles of 32 keys in smem.
// ----------------------------------------------------------------------------
__global__ __launch_bounds__(128) void flash_kernel(const float* __restrict__ Q,
                                                    const float* __restrict__ Kd,
                                                    const float* __restrict__ V,
                                                    float* __restrict__ out) {
    const int h = blockIdx.y;
    const int b = blockIdx.z;
    const int qrow = blockIdx.x * 128 + threadIdx.x;
    const int tid = threadIdx.x;

    __shared__ float4 Ks4[32][16];
    __shared__ float4 Vs4[32][16];

    const size_t bh = (size_t)(b * NH + h) * S;
    const float4* qp = (const float4*)(Q + (bh + qrow) * DH);
    float4 q4[16];
    #pragma unroll
    for (int i = 0; i < 16; i++) q4[i] = qp[i];

    float4 acc4[16];
    #pragma unroll
    for (int i = 0; i < 16; i++) acc4[i] = make_float4(0.f, 0.f, 0.f, 0.f);
    float m = -INFINITY;
    float l = 0.0f;

    for (int kt = 0; kt < S; kt += 32) {
        __syncthreads();
        const float4* kb = (const float4*)(Kd + (bh + kt) * DH);
        const float4* vb = (const float4*)(V  + (bh + kt) * DH);
        #pragma unroll
        for (int it = 0; it < 4; it++) {
            const int idx = it * 128 + tid;
            ((float4*)Ks4)[idx] = kb[idx];
            ((float4*)Vs4)[idx] = vb[idx];
        }
        __syncthreads();

        float sc[32];
        #pragma unroll
        for (int j = 0; j < 32; j++) {
            float sj = 0.0f;
            #pragma unroll
            for (int i = 0; i < 16; i++) {
                const float4 kk = Ks4[j][i];
                sj += q4[i].x * kk.x + q4[i].y * kk.y
                    + q4[i].z * kk.z + q4[i].w * kk.w;
            }
            sc[j] = sj * 0.125f; // 1/sqrt(64)
        }

        float tmax = sc[0];
        #pragma unroll
        for (int j = 1; j < 32; j++) tmax = fmaxf(tmax, sc[j]);
        const float mnew = fmaxf(m, tmax);
        const float corr = __expf(m - mnew);
        float lsum = 0.0f;
        #pragma unroll
        for (int j = 0; j < 32; j++) {
            sc[j] = __expf(sc[j] - mnew);
            lsum += sc[j];
        }
        l = l * corr + lsum;
        m = mnew;

        #pragma unroll
        for (int i = 0; i < 16; i++) {
            acc4[i].x *= corr; acc4[i].y *= corr;
            acc4[i].z *= corr; acc4[i].w *= corr;
        }
        #pragma unroll
        for (int j = 0; j < 32; j++) {
            const float p = sc[j];
            #pragma unroll
            for (int i = 0; i < 16; i++) {
                const float4 vv = Vs4[j][i];
                acc4[i].x += p * vv.x; acc4[i].y += p * vv.y;
                acc4[i].z += p * vv.z; acc4[i].w += p * vv.w;
            }
        }
    }

    const float inv = 1.0f / l;
    const int t = b * S + qrow;
    float4* op = (float4*)(out + (size_t)t * DM + h * DH);
    #pragma unroll
    for (int i = 0; i < 16; i++) {
        float4 o;
        o.x = acc4[i].x * inv; o.y = acc4[i].y * inv;
        o.z = acc4[i].z * inv; o.w = acc4[i].w * inv;
        op[i] = o;
    }
}

// ----------------------------------------------------------------------------
// GEGLU: h[t,j] = u[t,j] * gelu_tanh(u[t, 4096+j])
// ----------------------------------------------------------------------------
__global__ __launch_bounds__(256) void geglu_kernel(const float* __restrict__ u,
                                                    float* __restrict__ hh) {
    const size_t gid = (size_t)blockIdx.x * 256 + threadIdx.x;
    const size_t row = gid / FFN;
    const size_t col = gid % FFN;
    const float a = u[row * FFN2 + col];
    const float g = u[row * FFN2 + FFN + col];
    const float g3 = g * g * g;
    const float t = tanhf(0.7978845608028654f * (g + 0.044715f * g3));
    hh[row * FFN + col] = a * 0.5f * g * (1.0f + t);
}

// ----------------------------------------------------------------------------
// Launch (no static caching — resolve scratch addresses on every call)
// ----------------------------------------------------------------------------
extern "C" void kernel_launch(void* const* d_in, const int* in_sizes, int n_in,
                              void* d_out, int out_size) {
    const float* X     = (const float*)d_in[0];
    const float* W_qkv = (const float*)d_in[1];
    const float* W_o   = (const float*)d_in[2];
    const float* W_fc1 = (const float*)d_in[3];
    const float* W_fc2 = (const float*)d_in[4];
    const float* ln1_w = (const float*)d_in[5];
    const float* ln2_w = (const float*)d_in[6];
    float* out = (float*)d_out;

    float *p_Xn, *p_qkv, *p_q, *p_k, *p_v, *p_att, *p_X1, *p_u, *p_h;
    cudaGetSymbolAddress((void**)&p_Xn,  g_Xn);
    cudaGetSymbolAddress((void**)&p_qkv, g_qkv);
    cudaGetSymbolAddress((void**)&p_q,   g_q);
    cudaGetSymbolAddress((void**)&p_k,   g_k);
    cudaGetSymbolAddress((void**)&p_v,   g_v);
    cudaGetSymbolAddress((void**)&p_att, g_att);
    cudaGetSymbolAddress((void**)&p_X1,  g_X1);
    cudaGetSymbolAddress((void**)&p_u,   g_u);
    cudaGetSymbolAddress((void**)&p_h,   g_h);

    // 1. LN1
    ln_kernel<<<T, 256>>>(X, ln1_w, p_Xn);
    // 2. qkv = Xn @ W_qkv^T   [8192 x 3072]
    gemm_nt<0><<<dim3(QKV3 / 128, T / 128), 256>>>(p_Xn, W_qkv, nullptr, p_qkv, T, QKV3, DM);
    // 3. de-interleave
    reshape_qkv<<<(T * DM) / 256, 256>>>(p_qkv, p_q, p_k, p_v);
    // 4. attention
    flash_kernel<<<dim3(S / 128, NH, B), 128>>>(p_q, p_k, p_v, p_att);
    // 5. X1 = X + attn @ W_o^T   [8192 x 1024]
    gemm_nt<1><<<dim3(DM / 128, T / 128), 256>>>(p_att, W_o, X, p_X1, T, DM, DM);
    // 6. LN2
    ln_kernel<<<T, 256>>>(p_X1, ln2_w, p_Xn);
    // 7. u = Xn @ W_fc1^T   [8192 x 8192]
    gemm_nt<0><<<dim3(FFN2 / 128, T / 128), 256>>>(p_Xn, W_fc1, nullptr, p_u, T, FFN2, DM);
    // 8. h = a * gelu(g)
    geglu_kernel<<<((size_t)T * FFN) / 256, 256>>>(p_u, p_h);
    // 9. out = X1 + h @ W_fc2^T   [8192 x 1024]
    gemm_nt<1><<<dim3(DM / 128, T / 128), 256>>>(p_h, W_fc2, p_X1, out, T, DM, FFN);
}

// round 3
// speedup vs baseline: 1.6224x; 1.6224x over previous
#include <cuda_runtime.h>
#include <cuda_bf16.h>
#include <math.h>
#include <stdint.h>

// ----------------------------------------------------------------------------
// Problem constants
// ----------------------------------------------------------------------------
#define B        4
#define S        2048
#define T        (B * S)          // 8192 tokens
#define DM       1024             // d_model
#define NH       16               // heads
#define DH       64               // head dim
#define QKV3     (3 * NH * DH)    // 3072
#define FFN      4096
#define FFN2     (2 * FFN)        // 8192

// ----------------------------------------------------------------------------
// Scratch (device globals -> no allocation inside kernel_launch)
// ----------------------------------------------------------------------------
__device__ float g_qkv [(size_t)T * QKV3];  // qkv projection (fp32)
__device__ float g_q   [(size_t)T * DM];    // [b][h][s][d]
__device__ float g_k   [(size_t)T * DM];
__device__ float g_v   [(size_t)T * DM];
__device__ float g_X1  [(size_t)T * DM];    // X + attn @ Wo^T
__device__ float g_u   [(size_t)T * FFN2];  // fc1 output (a | g)

// bf16 hi/lo split operands
__device__ __nv_bfloat16 g_Xnh [(size_t)T * DM];
__device__ __nv_bfloat16 g_Xnl [(size_t)T * DM];
__device__ __nv_bfloat16 g_atth[(size_t)T * DM];
__device__ __nv_bfloat16 g_attl[(size_t)T * DM];
__device__ __nv_bfloat16 g_hh  [(size_t)T * FFN];
__device__ __nv_bfloat16 g_hl  [(size_t)T * FFN];
__device__ __nv_bfloat16 g_Wqh [(size_t)QKV3 * DM];
__device__ __nv_bfloat16 g_Wql [(size_t)QKV3 * DM];
__device__ __nv_bfloat16 g_Woh [(size_t)DM * DM];
__device__ __nv_bfloat16 g_Wol [(size_t)DM * DM];
__device__ __nv_bfloat16 g_Wf1h[(size_t)FFN2 * DM];
__device__ __nv_bfloat16 g_Wf1l[(size_t)FFN2 * DM];
__device__ __nv_bfloat16 g_Wf2h[(size_t)DM * FFN];
__device__ __nv_bfloat16 g_Wf2l[(size_t)DM * FFN];

// ----------------------------------------------------------------------------
// fp32 -> (hi, lo) bf16 split
// ----------------------------------------------------------------------------
__device__ __forceinline__ void split1(float x, __nv_bfloat16& h, __nv_bfloat16& l) {
    h = __float2bfloat16_rn(x);
    l = __float2bfloat16_rn(x - __bfloat162float(h));
}

// ----------------------------------------------------------------------------
// Weight split: float4-vectorized
// ----------------------------------------------------------------------------
__global__ __launch_bounds__(256) void split_kernel(const float* __restrict__ X,
                                                    __nv_bfloat16* __restrict__ H,
                                                    __nv_bfloat16* __restrict__ L,
                                                    int n4) {
    const int gid = blockIdx.x * 256 + threadIdx.x;
    if (gid >= n4) return;
    const float4 v = ((const float4*)X)[gid];
    __nv_bfloat16 h0, h1, h2, h3, l0, l1, l2, l3;
    split1(v.x, h0, l0); split1(v.y, h1, l1);
    split1(v.z, h2, l2); split1(v.w, h3, l3);
    __nv_bfloat162* Hp = (__nv_bfloat162*)H;
    __nv_bfloat162* Lp = (__nv_bfloat162*)L;
    Hp[gid * 2]     = __nv_bfloat162(h0, h1);
    Hp[gid * 2 + 1] = __nv_bfloat162(h2, h3);
    Lp[gid * 2]     = __nv_bfloat162(l0, l1);
    Lp[gid * 2 + 1] = __nv_bfloat162(l2, l3);
}

// ----------------------------------------------------------------------------
// LayerNorm with fused hi/lo split output
// ----------------------------------------------------------------------------
__global__ __launch_bounds__(256) void ln_split_kernel(const float* __restrict__ X,
                                                       const float* __restrict__ w,
                                                       __nv_bfloat16* __restrict__ Hh,
                                                       __nv_bfloat16* __restrict__ Hl) {
    const int row = blockIdx.x;
    const int tid = threadIdx.x;
    const float4* xp = (const float4*)(X + (size_t)row * DM);
    float4 v = xp[tid];

    float s  = v.x + v.y + v.z + v.w;
    float sq = v.x * v.x + v.y * v.y + v.z * v.z + v.w * v.w;

    __shared__ float rs[256];
    __shared__ float rq[256];
    rs[tid] = s; rq[tid] = sq;
    __syncthreads();
    #pragma unroll
    for (int o = 128; o >= 1; o >>= 1) {
        if (tid < o) { rs[tid] += rs[tid + o]; rq[tid] += rq[tid + o]; }
        __syncthreads();
    }
    const float mu   = rs[0] * (1.0f / DM);
    const float var  = rq[0] * (1.0f / DM) - mu * mu;
    const float rstd = rsqrtf(var + 1e-5f);

    const float4 wv = ((const float4*)w)[tid];
    float y0 = (v.x - mu) * rstd * wv.x;
    float y1 = (v.y - mu) * rstd * wv.y;
    float y2 = (v.z - mu) * rstd * wv.z;
    float y3 = (v.w - mu) * rstd * wv.w;

    __nv_bfloat16 h0, h1, h2, h3, l0, l1, l2, l3;
    split1(y0, h0, l0); split1(y1, h1, l1);
    split1(y2, h2, l2); split1(y3, h3, l3);
    __nv_bfloat162* Hp = (__nv_bfloat162*)(Hh + (size_t)row * DM);
    __nv_bfloat162* Lp = (__nv_bfloat162*)(Hl + (size_t)row * DM);
    Hp[tid * 2]     = __nv_bfloat162(h0, h1);
    Hp[tid * 2 + 1] = __nv_bfloat162(h2, h3);
    Lp[tid * 2]     = __nv_bfloat162(l0, l1);
    Lp[tid * 2 + 1] = __nv_bfloat162(l2, l3);
}

// ----------------------------------------------------------------------------
// mma.sync m16n8k16 bf16 -> fp32
// ----------------------------------------------------------------------------
__device__ __forceinline__ void mma16816(float* c, const uint32_t* a, const uint32_t* b) {
    asm volatile(
        "mma.sync.aligned.m16n8k16.row.col.f32.bf16.bf16.f32 "
        "{%0,%1,%2,%3},{%4,%5,%6,%7},{%8,%9},{%0,%1,%2,%3};"
        : "+f"(c[0]), "+f"(c[1]), "+f"(c[2]), "+f"(c[3])
        : "r"(a[0]), "r"(a[1]), "r"(a[2]), "r"(a[3]), "r"(b[0]), "r"(b[1]));
}

// ----------------------------------------------------------------------------
// Split-bf16 NT GEMM: C[m,n] = sum_k A[m,k]*B[n,k] with A,B given as hi/lo bf16.
// acc = Ah*Bh + Al*Bh + Ah*Bl  (fp32 accumulate)
// Block tile 128x128x32, 256 threads (8 warps, 2x4), warp tile 64x32.
// EPI 0: C = AB      EPI 1: C = R + AB
// Requires M%128==0, N%128==0, K%32==0.
// ----------------------------------------------------------------------------
#define PITCH 40                      // 32 + 8 pad: conflict-free fragment rows
#define SEG   (128 * PITCH)           // one buffer of one array

template <int EPI>
__global__ __launch_bounds__(256) void gemm_bf16s(const __nv_bfloat16* __restrict__ Ah,
                                                  const __nv_bfloat16* __restrict__ Al,
                                                  const __nv_bfloat16* __restrict__ Bh,
                                                  const __nv_bfloat16* __restrict__ Bl,
                                                  const float* __restrict__ R,
                                                  float* __restrict__ C,
                                                  int M, int N, int K) {
    extern __shared__ __nv_bfloat16 smem[];
    __nv_bfloat16* sAh = smem;
    __nv_bfloat16* sAl = smem + 2 * SEG;
    __nv_bfloat16* sBh = smem + 4 * SEG;
    __nv_bfloat16* sBl = smem + 6 * SEG;

    const int tid  = threadIdx.x;
    const int lane = tid & 31;
    const int warp = tid >> 5;
    const int wm   = warp >> 2;       // 0..1
    const int wn   = warp & 3;        // 0..3
    const int g    = lane >> 2;       // 0..7
    const int kq   = (lane & 3) * 2;  // 0,2,4,6

    const int m0 = blockIdx.y * 128;
    const int n0 = blockIdx.x * 128;

    // loader: 2 uint4 per array per thread (128 rows x 32 k = 512 uint4)
    const int q0 = tid, q1 = tid + 256;
    const int r0 = q0 >> 2, c0 = (q0 & 3) * 8;
    const int r1 = q1 >> 2, c1 = (q1 & 3) * 8;

    float acc[4][4][4];
    #pragma unroll
    for (int i = 0; i < 4; i++)
        #pragma unroll
        for (int j = 0; j < 4; j++)
            #pragma unroll
            for (int r = 0; r < 4; r++) acc[i][j][r] = 0.0f;

    const size_t aOff0 = (size_t)(m0 + r0) * K + c0;
    const size_t aOff1 = (size_t)(m0 + r1) * K + c1;
    const size_t bOff0 = (size_t)(n0 + r0) * K + c0;
    const size_t bOff1 = (size_t)(n0 + r1) * K + c1;

    // prologue: tile 0 -> buffer 0
    {
        uint4 vah0 = *(const uint4*)(Ah + aOff0), vah1 = *(const uint4*)(Ah + aOff1);
        uint4 val0 = *(const uint4*)(Al + aOff0), val1 = *(const uint4*)(Al + aOff1);
        uint4 vbh0 = *(const uint4*)(Bh + bOff0), vbh1 = *(const uint4*)(Bh + bOff1);
        uint4 vbl0 = *(const uint4*)(Bl + bOff0), vbl1 = *(const uint4*)(Bl + bOff1);
        *(uint4*)(sAh + r0 * PITCH + c0) = vah0; *(uint4*)(sAh + r1 * PITCH + c1) = vah1;
        *(uint4*)(sAl + r0 * PITCH + c0) = val0; *(uint4*)(sAl + r1 * PITCH + c1) = val1;
        *(uint4*)(sBh + r0 * PITCH + c0) = vbh0; *(uint4*)(sBh + r1 * PITCH + c1) = vbh1;
        *(uint4*)(sBl + r0 * PITCH + c0) = vbl0; *(uint4*)(sBl + r1 * PITCH + c1) = vbl1;
    }
    __syncthreads();

    const int ntiles = K >> 5;
    int buf = 0;
    for (int t = 0; t < ntiles; t++) {
        uint4 sreg[8];
        const bool hasNext = (t + 1 < ntiles);
        if (hasNext) {
            const int k0 = (t + 1) * 32;
            sreg[0] = *(const uint4*)(Ah + aOff0 + k0);
            sreg[1] = *(const uint4*)(Ah + aOff1 + k0);
            sreg[2] = *(const uint4*)(Al + aOff0 + k0);
            sreg[3] = *(const uint4*)(Al + aOff1 + k0);
            sreg[4] = *(const uint4*)(Bh + bOff0 + k0);
            sreg[5] = *(const uint4*)(Bh + bOff1 + k0);
            sreg[6] = *(const uint4*)(Bl + bOff0 + k0);
            sreg[7] = *(const uint4*)(Bl + bOff1 + k0);
        }

        const __nv_bfloat16* pAh = sAh + buf * SEG;
        const __nv_bfloat16* pAl = sAl + buf * SEG;
        const __nv_bfloat16* pBh = sBh + buf * SEG;
        const __nv_bfloat16* pBl = sBl + buf * SEG;

        #pragma unroll
        for (int kc = 0; kc < 32; kc += 16) {
            uint32_t ah[4][4], al[4][4], bh[4][2], bl[4][2];
            #pragma unroll
            for (int i = 0; i < 4; i++) {
                const int row = wm * 64 + i * 16 + g;
                const int o0 = row * PITCH + kc + kq;
                const int o1 = (row + 8) * PITCH + kc + kq;
                ah[i][0] = *(const uint32_t*)(pAh + o0);
                ah[i][1] = *(const uint32_t*)(pAh + o1);
                ah[i][2] = *(const uint32_t*)(pAh + o0 + 8);
                ah[i][3] = *(const uint32_t*)(pAh + o1 + 8);
                al[i][0] = *(const uint32_t*)(pAl + o0);
                al[i][1] = *(const uint32_t*)(pAl + o1);
                al[i][2] = *(const uint32_t*)(pAl + o0 + 8);
                al[i][3] = *(const uint32_t*)(pAl + o1 + 8);
            }
            #pragma unroll
            for (int j = 0; j < 4; j++) {
                const int nr = wn * 32 + j * 8 + g;
                const int o = nr * PITCH + kc + kq;
                bh[j][0] = *(const uint32_t*)(pBh + o);
                bh[j][1] = *(const uint32_t*)(pBh + o + 8);
                bl[j][0] = *(const uint32_t*)(pBl + o);
                bl[j][1] = *(const uint32_t*)(pBl + o + 8);
            }
            #pragma unroll
            for (int i = 0; i < 4; i++)
                #pragma unroll
                for (int j = 0; j < 4; j++) {
                    mma16816(acc[i][j], ah[i], bh[j]);
                    mma16816(acc[i][j], al[i], bh[j]);
                    mma16816(acc[i][j], ah[i], bl[j]);
                }
        }

        if (hasNext) {
            buf ^= 1;
            __nv_bfloat16* dAh = sAh + buf * SEG;
            __nv_bfloat16* dAl = sAl + buf * SEG;
            __nv_bfloat16* dBh = sBh + buf * SEG;
            __nv_bfloat16* dBl = sBl + buf * SEG;
            *(uint4*)(dAh + r0 * PITCH + c0) = sreg[0];
            *(uint4*)(dAh + r1 * PITCH + c1) = sreg[1];
            *(uint4*)(dAl + r0 * PITCH + c0) = sreg[2];
            *(uint4*)(dAl + r1 * PITCH + c1) = sreg[3];
            *(uint4*)(dBh + r0 * PITCH + c0) = sreg[4];
            *(uint4*)(dBh + r1 * PITCH + c1) = sreg[5];
            *(uint4*)(dBl + r0 * PITCH + c0) = sreg[6];
            *(uint4*)(dBl + r1 * PITCH + c1) = sreg[7];
            __syncthreads();
        }
    }

    // epilogue
    #pragma unroll
    for (int i = 0; i < 4; i++) {
        const int row = m0 + wm * 64 + i * 16 + g;
        #pragma unroll
        for (int j = 0; j < 4; j++) {
            const int col = n0 + wn * 32 + j * 8 + (lane & 3) * 2;
            const size_t o0 = (size_t)row * N + col;
            const size_t o1 = (size_t)(row + 8) * N + col;
            float2 v0 = {acc[i][j][0], acc[i][j][1]};
            float2 v1 = {acc[i][j][2], acc[i][j][3]};
            if (EPI == 1) {
                const float2 r0v = *(const float2*)(R + o0);
                const float2 r1v = *(const float2*)(R + o1);
                v0.x += r0v.x; v0.y += r0v.y;
                v1.x += r1v.x; v1.y += r1v.y;
            }
            *(float2*)(C + o0) = v0;
            *(float2*)(C + o1) = v1;
        }
    }
}

// ----------------------------------------------------------------------------
// De-interleave qkv[t, h*192 + d*3 + c] -> Q/K/V [b][h][s][d]
// ----------------------------------------------------------------------------
__global__ __launch_bounds__(256) void reshape_qkv(const float* __restrict__ qkv,
                                                   float* __restrict__ Q,
                                                   float* __restrict__ Kd,
                                                   float* __restrict__ V) {
    const size_t gid = (size_t)blockIdx.x * 256 + threadIdx.x; // t*1024 + h*64 + d
    const int t = (int)(gid >> 10);
    const int r = (int)(gid & 1023);
    const int h = r >> 6;
    const int d = r & 63;
    const int b = t >> 11;
    const int s = t & 2047;
    const float* src = qkv + (size_t)t * QKV3 + h * (DH * 3) + d * 3;
    const size_t dst = (((size_t)(b * NH + h)) * S + s) * DH + d;
    Q[dst]  = src[0];
    Kd[dst] = src[1];
    V[dst]  = src[2];
}

// ----------------------------------------------------------------------------
// Flash attention (fp32), hi/lo bf16 split output for the o-projection.
// ----------------------------------------------------------------------------
__global__ __launch_bounds__(128) void flash_kernel(const float* __restrict__ Q,
                                                    const float* __restrict__ Kd,
                                                    const float* __restrict__ V,
                                                    __nv_bfloat16* __restrict__ Oh,
                                                    __nv_bfloat16* __restrict__ Ol) {
    const int h = blockIdx.y;
    const int b = blockIdx.z;
    const int qrow = blockIdx.x * 128 + threadIdx.x;
    const int tid = threadIdx.x;

    __shared__ float4 Ks4[32][16];
    __shared__ float4 Vs4[32][16];

    const size_t bh = (size_t)(b * NH + h) * S;
    const float4* qp = (const float4*)(Q + (bh + qrow) * DH);
    float4 q4[16];
    #pragma unroll
    for (int i = 0; i < 16; i++) q4[i] = qp[i];

    float4 acc4[16];
    #pragma unroll
    for (int i = 0; i < 16; i++) acc4[i] = make_float4(0.f, 0.f, 0.f, 0.f);
    float m = -INFINITY;
    float l = 0.0f;

    for (int kt = 0; kt < S; kt += 32) {
        __syncthreads();
        const float4* kb = (const float4*)(Kd + (bh + kt) * DH);
        const float4* vb = (const float4*)(V  + (bh + kt) * DH);
        #pragma unroll
        for (int it = 0; it < 4; it++) {
            const int idx = it * 128 + tid;
            ((float4*)Ks4)[idx] = kb[idx];
            ((float4*)Vs4)[idx] = vb[idx];
        }
        __syncthreads();

        float sc[32];
        #pragma unroll
        for (int j = 0; j < 32; j++) {
            float sj = 0.0f;
            #pragma unroll
            for (int i = 0; i < 16; i++) {
                const float4 kk = Ks4[j][i];
                sj += q4[i].x * kk.x + q4[i].y * kk.y
                    + q4[i].z * kk.z + q4[i].w * kk.w;
            }
            sc[j] = sj * 0.125f; // 1/sqrt(64)
        }

        float tmax = sc[0];
        #pragma unroll
        for (int j = 1; j < 32; j++) tmax = fmaxf(tmax, sc[j]);
        const float mnew = fmaxf(m, tmax);
        const float corr = __expf(m - mnew);
        float lsum = 0.0f;
        #pragma unroll
        for (int j = 0; j < 32; j++) {
            sc[j] = __expf(sc[j] - mnew);
            lsum += sc[j];
        }
        l = l * corr + lsum;
        m = mnew;

        #pragma unroll
        for (int i = 0; i < 16; i++) {
            acc4[i].x *= corr; acc4[i].y *= corr;
            acc4[i].z *= corr; acc4[i].w *= corr;
        }
        #pragma unroll
        for (int j = 0; j < 32; j++) {
            const float p = sc[j];
            #pragma unroll
            for (int i = 0; i < 16; i++) {
                const float4 vv = Vs4[j][i];
                acc4[i].x += p * vv.x; acc4[i].y += p * vv.y;
                acc4[i].z += p * vv.z; acc4[i].w += p * vv.w;
            }
        }
    }

    const float inv = 1.0f / l;
    const int t = b * S + qrow;
    __nv_bfloat162* ohp = (__nv_bfloat162*)(Oh + (size_t)t * DM + h * DH);
    __nv_bfloat162* olp = (__nv_bfloat162*)(Ol + (size_t)t * DM + h * DH);
    #pragma unroll
    for (int i = 0; i < 16; i++) {
        const float o0 = acc4[i].x * inv, o1 = acc4[i].y * inv;
        const float o2 = acc4[i].z * inv, o3 = acc4[i].w * inv;
        __nv_bfloat16 h0, h1, h2, h3, l0, l1, l2, l3;
        split1(o0, h0, l0); split1(o1, h1, l1);
        split1(o2, h2, l2); split1(o3, h3, l3);
        ohp[i * 2]     = __nv_bfloat162(h0, h1);
        ohp[i * 2 + 1] = __nv_bfloat162(h2, h3);
        olp[i * 2]     = __nv_bfloat162(l0, l1);
        olp[i * 2 + 1] = __nv_bfloat162(l2, l3);
    }
}

// ----------------------------------------------------------------------------
// GEGLU with fused hi/lo split output
// ----------------------------------------------------------------------------
__global__ __launch_bounds__(256) void geglu_kernel(const float* __restrict__ u,
                                                    __nv_bfloat16* __restrict__ Hh,
                                                    __nv_bfloat16* __restrict__ Hl) {
    const size_t gid = (size_t)blockIdx.x * 256 + threadIdx.x;
    const size_t row = gid / FFN;
    const size_t col = gid % FFN;
    const float a = u[row * FFN2 + col];
    const float g = u[row * FFN2 + FFN + col];
    const float g3 = g * g * g;
    const float t = tanhf(0.7978845608028654f * (g + 0.044715f * g3));
    const float v = a * 0.5f * g * (1.0f + t);
    __nv_bfloat16 h, l;
    split1(v, h, l);
    Hh[gid] = h;
    Hl[gid] = l;
}

// ----------------------------------------------------------------------------
// Launch
// ----------------------------------------------------------------------------
extern "C" void kernel_launch(void* const* d_in, const int* in_sizes, int n_in,
                              void* d_out, int out_size) {
    const float* X     = (const float*)d_in[0];
    const float* W_qkv = (const float*)d_in[1];
    const float* W_o   = (const float*)d_in[2];
    const float* W_fc1 = (const float*)d_in[3];
    const float* W_fc2 = (const float*)d_in[4];
    const float* ln1_w = (const float*)d_in[5];
    const float* ln2_w = (const float*)d_in[6];
    float* out = (float*)d_out;

    float *p_qkv, *p_q, *p_k, *p_v, *p_X1, *p_u;
    __nv_bfloat16 *p_Xnh, *p_Xnl, *p_atth, *p_attl, *p_hh, *p_hl;
    __nv_bfloat16 *p_Wqh, *p_Wql, *p_Woh, *p_Wol, *p_Wf1h, *p_Wf1l, *p_Wf2h, *p_Wf2l;
    cudaGetSymbolAddress((void**)&p_qkv, g_qkv);
    cudaGetSymbolAddress((void**)&p_q,   g_q);
    cudaGetSymbolAddress((void**)&p_k,   g_k);
    cudaGetSymbolAddress((void**)&p_v,   g_v);
    cudaGetSymbolAddress((void**)&p_X1,  g_X1);
    cudaGetSymbolAddress((void**)&p_u,   g_u);
    cudaGetSymbolAddress((void**)&p_Xnh,  g_Xnh);
    cudaGetSymbolAddress((void**)&p_Xnl,  g_Xnl);
    cudaGetSymbolAddress((void**)&p_atth, g_atth);
    cudaGetSymbolAddress((void**)&p_attl, g_attl);
    cudaGetSymbolAddress((void**)&p_hh,   g_hh);
    cudaGetSymbolAddress((void**)&p_hl,   g_hl);
    cudaGetSymbolAddress((void**)&p_Wqh,  g_Wqh);
    cudaGetSymbolAddress((void**)&p_Wql,  g_Wql);
    cudaGetSymbolAddress((void**)&p_Woh,  g_Woh);
    cudaGetSymbolAddress((void**)&p_Wol,  g_Wol);
    cudaGetSymbolAddress((void**)&p_Wf1h, g_Wf1h);
    cudaGetSymbolAddress((void**)&p_Wf1l, g_Wf1l);
    cudaGetSymbolAddress((void**)&p_Wf2h, g_Wf2h);
    cudaGetSymbolAddress((void**)&p_Wf2l, g_Wf2l);

    const int smemBytes = 8 * SEG * (int)sizeof(__nv_bfloat16); // 81920
    cudaFuncSetAttribute(gemm_bf16s<0>, cudaFuncAttributeMaxDynamicSharedMemorySize, smemBytes);
    cudaFuncSetAttribute(gemm_bf16s<1>, cudaFuncAttributeMaxDynamicSharedMemorySize, smemBytes);

    // weight splits
    split_kernel<<<(QKV3 * DM / 4 + 255) / 256, 256>>>(W_qkv, p_Wqh, p_Wql, QKV3 * DM / 4);
    split_kernel<<<(DM * DM / 4 + 255) / 256, 256>>>(W_o, p_Woh, p_Wol, DM * DM / 4);
    split_kernel<<<(FFN2 * DM / 4 + 255) / 256, 256>>>(W_fc1, p_Wf1h, p_Wf1l, FFN2 * DM / 4);
    split_kernel<<<(DM * FFN / 4 + 255) / 256, 256>>>(W_fc2, p_Wf2h, p_Wf2l, DM * FFN / 4);

    // 1. LN1 (split output)
    ln_split_kernel<<<T, 256>>>(X, ln1_w, p_Xnh, p_Xnl);
    // 2. qkv = Xn @ W_qkv^T   [8192 x 3072]
    gemm_bf16s<0><<<dim3(QKV3 / 128, T / 128), 256, smemBytes>>>(
        p_Xnh, p_Xnl, p_Wqh, p_Wql, nullptr, p_qkv, T, QKV3, DM);
    // 3. de-interleave
    reshape_qkv<<<(T * DM) / 256, 256>>>(p_qkv, p_q, p_k, p_v);
    // 4. attention (split output)
    flash_kernel<<<dim3(S / 128, NH, B), 128>>>(p_q, p_k, p_v, p_atth, p_attl);
    // 5. X1 = X + attn @ W_o^T   [8192 x 1024]
    gemm_bf16s<1><<<dim3(DM / 128, T / 128), 256, smemBytes>>>(
        p_atth, p_attl, p_Woh, p_Wol, X, p_X1, T, DM, DM);
    // 6. LN2 (split output)
    ln_split_kernel<<<T, 256>>>(p_X1, ln2_w, p_Xnh, p_Xnl);
    // 7. u = Xn @ W_fc1^T   [8192 x 8192]
    gemm_bf16s<0><<<dim3(FFN2 / 128, T / 128), 256, smemBytes>>>(
        p_Xnh, p_Xnl, p_Wf1h, p_Wf1l, nullptr, p_u, T, FFN2, DM);
    // 8. h = a * gelu(g) (split output)
    geglu_kernel<<<((size_t)T * FFN) / 256, 256>>>(p_u, p_hh, p_hl);
    // 9. out = X1 + h @ W_fc2^T   [8192 x 1024]
    gemm_bf16s<1><<<dim3(DM / 128, T / 128), 256, smemBytes>>>(
        p_hh, p_hl, p_Wf2h, p_Wf2l, p_X1, out, T, DM, FFN);
}

// round 5
// speedup vs baseline: 2.2454x; 1.3840x over previous
#include <cuda_runtime.h>
#include <cuda_bf16.h>
#include <math.h>
#include <stdint.h>

// ----------------------------------------------------------------------------
// Problem constants
// ----------------------------------------------------------------------------
#define B        4
#define S        2048
#define T        (B * S)          // 8192 tokens
#define DM       1024             // d_model
#define NH       16               // heads
#define DH       64               // head dim
#define QKV3     (3 * NH * DH)    // 3072
#define FFN      4096
#define FFN2     (2 * FFN)        // 8192

// ----------------------------------------------------------------------------
// Scratch (device globals -> no allocation inside kernel_launch)
// ----------------------------------------------------------------------------
__device__ float g_qkv [(size_t)T * QKV3];  // qkv projection (fp32)
__device__ float g_X1  [(size_t)T * DM];    // X + attn @ Wo^T
__device__ float g_u   [(size_t)T * FFN2];  // fc1 output (a | g)

// bf16 hi/lo split operands
__device__ __nv_bfloat16 g_Xnh [(size_t)T * DM];
__device__ __nv_bfloat16 g_Xnl [(size_t)T * DM];
__device__ __nv_bfloat16 g_atth[(size_t)T * DM];
__device__ __nv_bfloat16 g_attl[(size_t)T * DM];
__device__ __nv_bfloat16 g_hh  [(size_t)T * FFN];
__device__ __nv_bfloat16 g_hl  [(size_t)T * FFN];
__device__ __nv_bfloat16 g_Wqh [(size_t)QKV3 * DM];
__device__ __nv_bfloat16 g_Wql [(size_t)QKV3 * DM];
__device__ __nv_bfloat16 g_Woh [(size_t)DM * DM];
__device__ __nv_bfloat16 g_Wol [(size_t)DM * DM];
__device__ __nv_bfloat16 g_Wf1h[(size_t)FFN2 * DM];
__device__ __nv_bfloat16 g_Wf1l[(size_t)FFN2 * DM];
__device__ __nv_bfloat16 g_Wf2h[(size_t)DM * FFN];
__device__ __nv_bfloat16 g_Wf2l[(size_t)DM * FFN];
// attention operands (bf16 hi/lo)
__device__ __nv_bfloat16 g_Qh [(size_t)T * DM];   // [b,h,s,d]  (pre-scaled 1/8)
__device__ __nv_bfloat16 g_Ql [(size_t)T * DM];
__device__ __nv_bfloat16 g_Kh [(size_t)T * DM];   // [b,h,s,d]
__device__ __nv_bfloat16 g_Kl [(size_t)T * DM];
__device__ __nv_bfloat16 g_Vth[(size_t)T * DM];   // [b,h,d,s]  (transposed)
__device__ __nv_bfloat16 g_Vtl[(size_t)T * DM];

// ----------------------------------------------------------------------------
// fp32 -> (hi, lo) bf16 split
// ----------------------------------------------------------------------------
__device__ __forceinline__ void split1(float x, __nv_bfloat16& h, __nv_bfloat16& l) {
    h = __float2bfloat16_rn(x);
    l = __float2bfloat16_rn(x - __bfloat162float(h));
}

// ----------------------------------------------------------------------------
// Fast exp on FMA pipe (no MUFU). rel err < 3e-8 on clamped range.
// ----------------------------------------------------------------------------
__device__ __forceinline__ float fexp(float x) {
    x = fminf(fmaxf(x, -87.0f), 87.0f);
    const float y = x * 1.4426950408889634f;          // log2(e)
    const float z = y + 12582912.0f;                  // 1.5 * 2^23
    const int   n = __float_as_int(z) - 0x4B400000;   // round-to-nearest int
    const float f = y - (z - 12582912.0f);            // f in [-0.5, 0.5]
    // 2^f, degree-6 Taylor in ln2
    float p = 1.5403530393381609e-4f;
    p = fmaf(p, f, 1.3333558146428443e-3f);
    p = fmaf(p, f, 9.6181291076284772e-3f);
    p = fmaf(p, f, 5.5504108664821580e-2f);
    p = fmaf(p, f, 2.4022650695910072e-1f);
    p = fmaf(p, f, 6.9314718055994531e-1f);
    p = fmaf(p, f, 1.0f);
    return __int_as_float(__float_as_int(p) + (n << 23));
}

__device__ __forceinline__ float frcp(float x) {
    float r;
    asm("rcp.approx.f32 %0, %1;" : "=f"(r) : "f"(x));
    return r;
}

// ----------------------------------------------------------------------------
// Weight split: float4-vectorized
// ----------------------------------------------------------------------------
__global__ __launch_bounds__(256) void split_kernel(const float* __restrict__ X,
                                                    __nv_bfloat16* __restrict__ H,
                                                    __nv_bfloat16* __restrict__ L,
                                                    int n4) {
    const int gid = blockIdx.x * 256 + threadIdx.x;
    if (gid >= n4) return;
    const float4 v = ((const float4*)X)[gid];
    __nv_bfloat16 h0, h1, h2, h3, l0, l1, l2, l3;
    split1(v.x, h0, l0); split1(v.y, h1, l1);
    split1(v.z, h2, l2); split1(v.w, h3, l3);
    __nv_bfloat162* Hp = (__nv_bfloat162*)H;
    __nv_bfloat162* Lp = (__nv_bfloat162*)L;
    Hp[gid * 2]     = __nv_bfloat162(h0, h1);
    Hp[gid * 2 + 1] = __nv_bfloat162(h2, h3);
    Lp[gid * 2]     = __nv_bfloat162(l0, l1);
    Lp[gid * 2 + 1] = __nv_bfloat162(l2, l3);
}

// ----------------------------------------------------------------------------
// LayerNorm with fused hi/lo split output
// ----------------------------------------------------------------------------
__global__ __launch_bounds__(256) void ln_split_kernel(const float* __restrict__ X,
                                                       const float* __restrict__ w,
                                                       __nv_bfloat16* __restrict__ Hh,
                                                       __nv_bfloat16* __restrict__ Hl) {
    const int row = blockIdx.x;
    const int tid = threadIdx.x;
    const float4* xp = (const float4*)(X + (size_t)row * DM);
    float4 v = xp[tid];

    float s  = v.x + v.y + v.z + v.w;
    float sq = v.x * v.x + v.y * v.y + v.z * v.z + v.w * v.w;

    __shared__ float rs[256];
    __shared__ float rq[256];
    rs[tid] = s; rq[tid] = sq;
    __syncthreads();
    #pragma unroll
    for (int o = 128; o >= 1; o >>= 1) {
        if (tid < o) { rs[tid] += rs[tid + o]; rq[tid] += rq[tid + o]; }
        __syncthreads();
    }
    const float mu   = rs[0] * (1.0f / DM);
    const float var  = rq[0] * (1.0f / DM) - mu * mu;
    const float rstd = rsqrtf(var + 1e-5f);

    const float4 wv = ((const float4*)w)[tid];
    float y0 = (v.x - mu) * rstd * wv.x;
    float y1 = (v.y - mu) * rstd * wv.y;
    float y2 = (v.z - mu) * rstd * wv.z;
    float y3 = (v.w - mu) * rstd * wv.w;

    __nv_bfloat16 h0, h1, h2, h3, l0, l1, l2, l3;
    split1(y0, h0, l0); split1(y1, h1, l1);
    split1(y2, h2, l2); split1(y3, h3, l3);
    __nv_bfloat162* Hp = (__nv_bfloat162*)(Hh + (size_t)row * DM);
    __nv_bfloat162* Lp = (__nv_bfloat162*)(Hl + (size_t)row * DM);
    Hp[tid * 2]     = __nv_bfloat162(h0, h1);
    Hp[tid * 2 + 1] = __nv_bfloat162(h2, h3);
    Lp[tid * 2]     = __nv_bfloat162(l0, l1);
    Lp[tid * 2 + 1] = __nv_bfloat162(l2, l3);
}

// ----------------------------------------------------------------------------
// mma.sync m16n8k16 bf16 -> fp32
// ----------------------------------------------------------------------------
__device__ __forceinline__ void mma16816(float* c, const uint32_t* a, const uint32_t* b) {
    asm volatile(
        "mma.sync.aligned.m16n8k16.row.col.f32.bf16.bf16.f32 "
        "{%0,%1,%2,%3},{%4,%5,%6,%7},{%8,%9},{%0,%1,%2,%3};"
        : "+f"(c[0]), "+f"(c[1]), "+f"(c[2]), "+f"(c[3])
        : "r"(a[0]), "r"(a[1]), "r"(a[2]), "r"(a[3]), "r"(b[0]), "r"(b[1]));
}

// ----------------------------------------------------------------------------
// Split-bf16 NT GEMM (validated round 3)
// ----------------------------------------------------------------------------
#define PITCH 40
#define SEG   (128 * PITCH)

template <int EPI>
__global__ __launch_bounds__(256) void gemm_bf16s(const __nv_bfloat16* __restrict__ Ah,
                                                  const __nv_bfloat16* __restrict__ Al,
                                                  const __nv_bfloat16* __restrict__ Bh,
                                                  const __nv_bfloat16* __restrict__ Bl,
                                                  const float* __restrict__ R,
                                                  float* __restrict__ C,
                                                  int M, int N, int K) {
    extern __shared__ __nv_bfloat16 smem[];
    __nv_bfloat16* sAh = smem;
    __nv_bfloat16* sAl = smem + 2 * SEG;
    __nv_bfloat16* sBh = smem + 4 * SEG;
    __nv_bfloat16* sBl = smem + 6 * SEG;

    const int tid  = threadIdx.x;
    const int lane = tid & 31;
    const int warp = tid >> 5;
    const int wm   = warp >> 2;
    const int wn   = warp & 3;
    const int g    = lane >> 2;
    const int kq   = (lane & 3) * 2;

    const int m0 = blockIdx.y * 128;
    const int n0 = blockIdx.x * 128;

    const int q0 = tid, q1 = tid + 256;
    const int r0 = q0 >> 2, c0 = (q0 & 3) * 8;
    const int r1 = q1 >> 2, c1 = (q1 & 3) * 8;

    float acc[4][4][4];
    #pragma unroll
    for (int i = 0; i < 4; i++)
        #pragma unroll
        for (int j = 0; j < 4; j++)
            #pragma unroll
            for (int r = 0; r < 4; r++) acc[i][j][r] = 0.0f;

    const size_t aOff0 = (size_t)(m0 + r0) * K + c0;
    const size_t aOff1 = (size_t)(m0 + r1) * K + c1;
    const size_t bOff0 = (size_t)(n0 + r0) * K + c0;
    const size_t bOff1 = (size_t)(n0 + r1) * K + c1;

    {
        uint4 vah0 = *(const uint4*)(Ah + aOff0), vah1 = *(const uint4*)(Ah + aOff1);
        uint4 val0 = *(const uint4*)(Al + aOff0), val1 = *(const uint4*)(Al + aOff1);
        uint4 vbh0 = *(const uint4*)(Bh + bOff0), vbh1 = *(const uint4*)(Bh + bOff1);
        uint4 vbl0 = *(const uint4*)(Bl + bOff0), vbl1 = *(const uint4*)(Bl + bOff1);
        *(uint4*)(sAh + r0 * PITCH + c0) = vah0; *(uint4*)(sAh + r1 * PITCH + c1) = vah1;
        *(uint4*)(sAl + r0 * PITCH + c0) = val0; *(uint4*)(sAl + r1 * PITCH + c1) = val1;
        *(uint4*)(sBh + r0 * PITCH + c0) = vbh0; *(uint4*)(sBh + r1 * PITCH + c1) = vbh1;
        *(uint4*)(sBl + r0 * PITCH + c0) = vbl0; *(uint4*)(sBl + r1 * PITCH + c1) = vbl1;
    }
    __syncthreads();

    const int ntiles = K >> 5;
    int buf = 0;
    for (int t = 0; t < ntiles; t++) {
        uint4 sreg[8];
        const bool hasNext = (t + 1 < ntiles);
        if (hasNext) {
            const int k0 = (t + 1) * 32;
            sreg[0] = *(const uint4*)(Ah + aOff0 + k0);
            sreg[1] = *(const uint4*)(Ah + aOff1 + k0);
            sreg[2] = *(const uint4*)(Al + aOff0 + k0);
            sreg[3] = *(const uint4*)(Al + aOff1 + k0);
            sreg[4] = *(const uint4*)(Bh + bOff0 + k0);
            sreg[5] = *(const uint4*)(Bh + bOff1 + k0);
            sreg[6] = *(const uint4*)(Bl + bOff0 + k0);
            sreg[7] = *(const uint4*)(Bl + bOff1 + k0);
        }

        const __nv_bfloat16* pAh = sAh + buf * SEG;
        const __nv_bfloat16* pAl = sAl + buf * SEG;
        const __nv_bfloat16* pBh = sBh + buf * SEG;
        const __nv_bfloat16* pBl = sBl + buf * SEG;

        #pragma unroll
        for (int kc = 0; kc < 32; kc += 16) {
            uint32_t ah[4][4], al[4][4], bh[4][2], bl[4][2];
            #pragma unroll
            for (int i = 0; i < 4; i++) {
                const int row = wm * 64 + i * 16 + g;
                const int o0 = row * PITCH + kc + kq;
                const int o1 = (row + 8) * PITCH + kc + kq;
                ah[i][0] = *(const uint32_t*)(pAh + o0);
                ah[i][1] = *(const uint32_t*)(pAh + o1);
                ah[i][2] = *(const uint32_t*)(pAh + o0 + 8);
                ah[i][3] = *(const uint32_t*)(pAh + o1 + 8);
                al[i][0] = *(const uint32_t*)(pAl + o0);
                al[i][1] = *(const uint32_t*)(pAl + o1);
                al[i][2] = *(const uint32_t*)(pAl + o0 + 8);
                al[i][3] = *(const uint32_t*)(pAl + o1 + 8);
            }
            #pragma unroll
            for (int j = 0; j < 4; j++) {
                const int nr = wn * 32 + j * 8 + g;
                const int o = nr * PITCH + kc + kq;
                bh[j][0] = *(const uint32_t*)(pBh + o);
                bh[j][1] = *(const uint32_t*)(pBh + o + 8);
                bl[j][0] = *(const uint32_t*)(pBl + o);
                bl[j][1] = *(const uint32_t*)(pBl + o + 8);
            }
            #pragma unroll
            for (int i = 0; i < 4; i++)
                #pragma unroll
                for (int j = 0; j < 4; j++) {
                    mma16816(acc[i][j], ah[i], bh[j]);
                    mma16816(acc[i][j], al[i], bh[j]);
                    mma16816(acc[i][j], ah[i], bl[j]);
                }
        }

        if (hasNext) {
            buf ^= 1;
            __nv_bfloat16* dAh = sAh + buf * SEG;
            __nv_bfloat16* dAl = sAl + buf * SEG;
            __nv_bfloat16* dBh = sBh + buf * SEG;
            __nv_bfloat16* dBl = sBl + buf * SEG;
            *(uint4*)(dAh + r0 * PITCH + c0) = sreg[0];
            *(uint4*)(dAh + r1 * PITCH + c1) = sreg[1];
            *(uint4*)(dAl + r0 * PITCH + c0) = sreg[2];
            *(uint4*)(dAl + r1 * PITCH + c1) = sreg[3];
            *(uint4*)(dBh + r0 * PITCH + c0) = sreg[4];
            *(uint4*)(dBh + r1 * PITCH + c1) = sreg[5];
            *(uint4*)(dBl + r0 * PITCH + c0) = sreg[6];
            *(uint4*)(dBl + r1 * PITCH + c1) = sreg[7];
            __syncthreads();
        }
    }

    #pragma unroll
    for (int i = 0; i < 4; i++) {
        const int row = m0 + wm * 64 + i * 16 + g;
        #pragma unroll
        for (int j = 0; j < 4; j++) {
            const int col = n0 + wn * 32 + j * 8 + (lane & 3) * 2;
            const size_t o0 = (size_t)row * N + col;
            const size_t o1 = (size_t)(row + 8) * N + col;
            float2 v0 = {acc[i][j][0], acc[i][j][1]};
            float2 v1 = {acc[i][j][2], acc[i][j][3]};
            if (EPI == 1) {
                const float2 r0v = *(const float2*)(R + o0);
                const float2 r1v = *(const float2*)(R + o1);
                v0.x += r0v.x; v0.y += r0v.y;
                v1.x += r1v.x; v1.y += r1v.y;
            }
            *(float2*)(C + o0) = v0;
            *(float2*)(C + o1) = v1;
        }
    }
}

// ----------------------------------------------------------------------------
// De-interleave qkv -> split bf16 Q/K ([b,h,s,d], Q pre-scaled 1/8) and
// V^T ([b,h,d,s]).
// ----------------------------------------------------------------------------
__global__ __launch_bounds__(256) void reshape_split(const float* __restrict__ qkv,
                                                     __nv_bfloat16* __restrict__ Qh,
                                                     __nv_bfloat16* __restrict__ Ql,
                                                     __nv_bfloat16* __restrict__ Kh,
                                                     __nv_bfloat16* __restrict__ Kl,
                                                     __nv_bfloat16* __restrict__ Vth,
                                                     __nv_bfloat16* __restrict__ Vtl) {
    const size_t gid = (size_t)blockIdx.x * 256 + threadIdx.x; // t*1024 + h*64 + d
    const int t = (int)(gid >> 10);
    const int r = (int)(gid & 1023);
    const int h = r >> 6;
    const int d = r & 63;
    const int b = t >> 11;
    const int s = t & 2047;
    const float* src = qkv + (size_t)t * QKV3 + h * (DH * 3) + d * 3;
    const float qv = src[0] * 0.125f;
    const float kv = src[1];
    const float vv = src[2];
    const size_t qk = (((size_t)(b * NH + h)) * S + s) * DH + d;
    const size_t vt = (((size_t)(b * NH + h)) * DH + d) * S + s;
    __nv_bfloat16 hh, ll;
    split1(qv, hh, ll); Qh[qk] = hh; Ql[qk] = ll;
    split1(kv, hh, ll); Kh[qk] = hh; Kl[qk] = ll;
    split1(vv, hh, ll); Vth[vt] = hh; Vtl[vt] = ll;
}

// ----------------------------------------------------------------------------
// Tensor-core flash attention, split-bf16 MMAs, FMA-pipe exp.
// Block: 128 q rows x one (b,h). 8 warps; warp w owns q rows [w*16, w*16+16).
// Key tiles of 64; K tile [64 keys x 64 d], V^T tile [64 d x 64 keys] in smem.
// ----------------------------------------------------------------------------
#define FP   72
#define FSEG (64 * FP)

__global__ __launch_bounds__(256) void flash_mma(const __nv_bfloat16* __restrict__ Qh,
                                                 const __nv_bfloat16* __restrict__ Ql,
                                                 const __nv_bfloat16* __restrict__ Kh,
                                                 const __nv_bfloat16* __restrict__ Kl,
                                                 const __nv_bfloat16* __restrict__ Vth,
                                                 const __nv_bfloat16* __restrict__ Vtl,
                                                 __nv_bfloat16* __restrict__ Oh,
                                                 __nv_bfloat16* __restrict__ Ol) {
    __shared__ __nv_bfloat16 sKh[FSEG], sKl[FSEG], sVh[FSEG], sVl[FSEG];

    const int tid  = threadIdx.x;
    const int lane = tid & 31;
    const int w    = tid >> 5;
    const int h    = blockIdx.y;
    const int b    = blockIdx.z;
    const int q0   = blockIdx.x * 128;
    const size_t bh  = (size_t)(b * NH + h) * S;   // token base (Q/K rows)
    const size_t bhd = (size_t)(b * NH + h) * DH;  // d-row base (V^T rows)
    const int g  = lane >> 2;
    const int kq = (lane & 3) * 2;

    // Q fragments (registers, whole kernel)
    uint32_t qfh[4][4], qfl[4][4];
    {
        const int row = q0 + w * 16 + g;
        const __nv_bfloat16* b0h = Qh + (bh + row) * DH;
        const __nv_bfloat16* b8h = Qh + (bh + row + 8) * DH;
        const __nv_bfloat16* b0l = Ql + (bh + row) * DH;
        const __nv_bfloat16* b8l = Ql + (bh + row + 8) * DH;
        #pragma unroll
        for (int kc = 0; kc < 4; kc++) {
            const int o = kc * 16 + kq;
            qfh[kc][0] = *(const uint32_t*)(b0h + o);
            qfh[kc][1] = *(const uint32_t*)(b8h + o);
            qfh[kc][2] = *(const uint32_t*)(b0h + o + 8);
            qfh[kc][3] = *(const uint32_t*)(b8h + o + 8);
            qfl[kc][0] = *(const uint32_t*)(b0l + o);
            qfl[kc][1] = *(const uint32_t*)(b8l + o);
            qfl[kc][2] = *(const uint32_t*)(b0l + o + 8);
            qfl[kc][3] = *(const uint32_t*)(b8l + o + 8);
        }
    }

    float o[8][4];
    #pragma unroll
    for (int j = 0; j < 8; j++)
        #pragma unroll
        for (int r = 0; r < 4; r++) o[j][r] = 0.0f;
    float m0 = -INFINITY, m1 = -INFINITY;
    float l0 = 0.0f, l1 = 0.0f;

    // tile loader mapping: 512 uint4 per array, 2 per thread
    const int i0 = tid, i1 = tid + 256;
    const int lr0 = i0 >> 3, lc0 = (i0 & 7) * 8;
    const int lr1 = i1 >> 3, lc1 = (i1 & 7) * 8;

    for (int kt = 0; kt < S; kt += 64) {
        __syncthreads();
        *(uint4*)(sKh + lr0 * FP + lc0) = *(const uint4*)(Kh + (bh + kt + lr0) * DH + lc0);
        *(uint4*)(sKh + lr1 * FP + lc1) = *(const uint4*)(Kh + (bh + kt + lr1) * DH + lc1);
        *(uint4*)(sKl + lr0 * FP + lc0) = *(const uint4*)(Kl + (bh + kt + lr0) * DH + lc0);
        *(uint4*)(sKl + lr1 * FP + lc1) = *(const uint4*)(Kl + (bh + kt + lr1) * DH + lc1);
        *(uint4*)(sVh + lr0 * FP + lc0) = *(const uint4*)(Vth + (bhd + lr0) * S + kt + lc0);
        *(uint4*)(sVh + lr1 * FP + lc1) = *(const uint4*)(Vth + (bhd + lr1) * S + kt + lc1);
        *(uint4*)(sVl + lr0 * FP + lc0) = *(const uint4*)(Vtl + (bhd + lr0) * S + kt + lc0);
        *(uint4*)(sVl + lr1 * FP + lc1) = *(const uint4*)(Vtl + (bhd + lr1) * S + kt + lc1);
        __syncthreads();

        // S = Q K^T  (scores pre-scaled via Q)
        float sc[8][4];
        #pragma unroll
        for (int j = 0; j < 8; j++)
            #pragma unroll
            for (int r = 0; r < 4; r++) sc[j][r] = 0.0f;

        #pragma unroll
        for (int kc = 0; kc < 4; kc++) {
            #pragma unroll
            for (int j = 0; j < 8; j++) {
                const int off = (j * 8 + g) * FP + kc * 16 + kq;
                uint32_t kb[2], klo[2];
                kb[0]  = *(const uint32_t*)(sKh + off);
                kb[1]  = *(const uint32_t*)(sKh + off + 8);
                klo[0] = *(const uint32_t*)(sKl + off);
                klo[1] = *(const uint32_t*)(sKl + off + 8);
                mma16816(sc[j], qfh[kc], kb);
                mma16816(sc[j], qfl[kc], kb);
                mma16816(sc[j], qfh[kc], klo);
            }
        }

        // online softmax (rows g and g+8)
        float mx0 = sc[0][0], mx1 = sc[0][2];
        #pragma unroll
        for (int j = 0; j < 8; j++) {
            mx0 = fmaxf(mx0, fmaxf(sc[j][0], sc[j][1]));
            mx1 = fmaxf(mx1, fmaxf(sc[j][2], sc[j][3]));
        }
        mx0 = fmaxf(mx0, __shfl_xor_sync(0xffffffffu, mx0, 1));
        mx0 = fmaxf(mx0, __shfl_xor_sync(0xffffffffu, mx0, 2));
        mx1 = fmaxf(mx1, __shfl_xor_sync(0xffffffffu, mx1, 1));
        mx1 = fmaxf(mx1, __shfl_xor_sync(0xffffffffu, mx1, 2));

        const float mn0 = fmaxf(m0, mx0);
        const float mn1 = fmaxf(m1, mx1);
        const float c0 = fexp(m0 - mn0);
        const float c1 = fexp(m1 - mn1);
        m0 = mn0; m1 = mn1;

        float s0 = 0.0f, s1 = 0.0f;
        #pragma unroll
        for (int j = 0; j < 8; j++) {
            sc[j][0] = fexp(sc[j][0] - mn0);
            sc[j][1] = fexp(sc[j][1] - mn0);
            sc[j][2] = fexp(sc[j][2] - mn1);
            sc[j][3] = fexp(sc[j][3] - mn1);
            s0 += sc[j][0] + sc[j][1];
            s1 += sc[j][2] + sc[j][3];
        }
        s0 += __shfl_xor_sync(0xffffffffu, s0, 1);
        s0 += __shfl_xor_sync(0xffffffffu, s0, 2);
        s1 += __shfl_xor_sync(0xffffffffu, s1, 1);
        s1 += __shfl_xor_sync(0xffffffffu, s1, 2);
        l0 = l0 * c0 + s0;
        l1 = l1 * c1 + s1;

        #pragma unroll
        for (int j = 0; j < 8; j++) {
            o[j][0] *= c0; o[j][1] *= c0;
            o[j][2] *= c1; o[j][3] *= c1;
        }

        // O += P V  (P split hi/lo in registers)
        #pragma unroll
        for (int t2 = 0; t2 < 4; t2++) {
            uint32_t ph[4], pl[4];
            {
                const float* e = sc[2 * t2];
                const float* f = sc[2 * t2 + 1];
                __nv_bfloat16 hv[8], lv[8];
                split1(e[0], hv[0], lv[0]); split1(e[1], hv[1], lv[1]);
                split1(e[2], hv[2], lv[2]); split1(e[3], hv[3], lv[3]);
                split1(f[0], hv[4], lv[4]); split1(f[1], hv[5], lv[5]);
                split1(f[2], hv[6], lv[6]); split1(f[3], hv[7], lv[7]);
                __nv_bfloat162 t0 = __nv_bfloat162(hv[0], hv[1]);
                __nv_bfloat162 t1 = __nv_bfloat162(hv[2], hv[3]);
                __nv_bfloat162 t2v = __nv_bfloat162(hv[4], hv[5]);
                __nv_bfloat162 t3 = __nv_bfloat162(hv[6], hv[7]);
                ph[0] = *(uint32_t*)&t0; ph[1] = *(uint32_t*)&t1;
                ph[2] = *(uint32_t*)&t2v; ph[3] = *(uint32_t*)&t3;
                t0 = __nv_bfloat162(lv[0], lv[1]);
                t1 = __nv_bfloat162(lv[2], lv[3]);
                t2v = __nv_bfloat162(lv[4], lv[5]);
                t3 = __nv_bfloat162(lv[6], lv[7]);
                pl[0] = *(uint32_t*)&t0; pl[1] = *(uint32_t*)&t1;
                pl[2] = *(uint32_t*)&t2v; pl[3] = *(uint32_t*)&t3;
            }
            #pragma unroll
            for (int j = 0; j < 8; j++) {
                const int off = (j * 8 + g) * FP + t2 * 16 + kq;
                uint32_t vh[2], vl[2];
                vh[0] = *(const uint32_t*)(sVh + off);
                vh[1] = *(const uint32_t*)(sVh + off + 8);
                vl[0] = *(const uint32_t*)(sVl + off);
                vl[1] = *(const uint32_t*)(sVl + off + 8);
                mma16816(o[j], ph, vh);
                mma16816(o[j], pl, vh);
                mma16816(o[j], ph, vl);
            }
        }
    }

    // epilogue: normalize and write hi/lo bf16
    const float inv0 = 1.0f / l0;
    const float inv1 = 1.0f / l1;
    const int row = q0 + w * 16 + g;
    const size_t t0 = (size_t)(b * S + row);
    const size_t t8 = t0 + 8;
    #pragma unroll
    for (int j = 0; j < 8; j++) {
        const int col = h * DH + j * 8 + kq;
        float v0 = o[j][0] * inv0, v1 = o[j][1] * inv0;
        float v2 = o[j][2] * inv1, v3 = o[j][3] * inv1;
        __nv_bfloat16 h0, h1, h2, h3, l0b, l1b, l2b, l3b;
        split1(v0, h0, l0b); split1(v1, h1, l1b);
        split1(v2, h2, l2b); split1(v3, h3, l3b);
        *(__nv_bfloat162*)(Oh + t0 * DM + col) = __nv_bfloat162(h0, h1);
        *(__nv_bfloat162*)(Ol + t0 * DM + col) = __nv_bfloat162(l0b, l1b);
        *(__nv_bfloat162*)(Oh + t8 * DM + col) = __nv_bfloat162(h2, h3);
        *(__nv_bfloat162*)(Ol + t8 * DM + col) = __nv_bfloat162(l2b, l3b);
    }
}

// ----------------------------------------------------------------------------
// GEGLU: h = a * g * sigmoid(2 * 0.79788456*(g + 0.044715 g^3)); split output
// ----------------------------------------------------------------------------
__global__ __launch_bounds__(256) void geglu_kernel(const float* __restrict__ u,
                                                    __nv_bfloat16* __restrict__ Hh,
                                                    __nv_bfloat16* __restrict__ Hl) {
    const size_t gid = (size_t)blockIdx.x * 256 + threadIdx.x;
    const size_t row = gid / FFN;
    const size_t col = gid % FFN;
    const float a = u[row * FFN2 + col];
    const float g = u[row * FFN2 + FFN + col];
    const float z = 0.7978845608028654f * (g + 0.044715f * g * g * g);
    const float ew = fexp(-2.0f * z);
    const float v = a * g * frcp(1.0f + ew);
    __nv_bfloat16 h, l;
    split1(v, h, l);
    Hh[gid] = h;
    Hl[gid] = l;
}

// ----------------------------------------------------------------------------
// Launch
// ----------------------------------------------------------------------------
extern "C" void kernel_launch(void* const* d_in, const int* in_sizes, int n_in,
                              void* d_out, int out_size) {
    const float* X     = (const float*)d_in[0];
    const float* W_qkv = (const float*)d_in[1];
    const float* W_o   = (const float*)d_in[2];
    const float* W_fc1 = (const float*)d_in[3];
    const float* W_fc2 = (const float*)d_in[4];
    const float* ln1_w = (const float*)d_in[5];
    const float* ln2_w = (const float*)d_in[6];
    float* out = (float*)d_out;

    float *p_qkv, *p_X1, *p_u;
    __nv_bfloat16 *p_Xnh, *p_Xnl, *p_atth, *p_attl, *p_hh, *p_hl;
    __nv_bfloat16 *p_Wqh, *p_Wql, *p_Woh, *p_Wol, *p_Wf1h, *p_Wf1l, *p_Wf2h, *p_Wf2l;
    __nv_bfloat16 *p_Qh, *p_Ql, *p_Kh, *p_Kl, *p_Vth, *p_Vtl;
    cudaGetSymbolAddress((void**)&p_qkv, g_qkv);
    cudaGetSymbolAddress((void**)&p_X1,  g_X1);
    cudaGetSymbolAddress((void**)&p_u,   g_u);
    cudaGetSymbolAddress((void**)&p_Xnh,  g_Xnh);
    cudaGetSymbolAddress((void**)&p_Xnl,  g_Xnl);
    cudaGetSymbolAddress((void**)&p_atth, g_atth);
    cudaGetSymbolAddress((void**)&p_attl, g_attl);
    cudaGetSymbolAddress((void**)&p_hh,   g_hh);
    cudaGetSymbolAddress((void**)&p_hl,   g_hl);
    cudaGetSymbolAddress((void**)&p_Wqh,  g_Wqh);
    cudaGetSymbolAddress((void**)&p_Wql,  g_Wql);
    cudaGetSymbolAddress((void**)&p_Woh,  g_Woh);
    cudaGetSymbolAddress((void**)&p_Wol,  g_Wol);
    cudaGetSymbolAddress((void**)&p_Wf1h, g_Wf1h);
    cudaGetSymbolAddress((void**)&p_Wf1l, g_Wf1l);
    cudaGetSymbolAddress((void**)&p_Wf2h, g_Wf2h);
    cudaGetSymbolAddress((void**)&p_Wf2l, g_Wf2l);
    cudaGetSymbolAddress((void**)&p_Qh,  g_Qh);
    cudaGetSymbolAddress((void**)&p_Ql,  g_Ql);
    cudaGetSymbolAddress((void**)&p_Kh,  g_Kh);
    cudaGetSymbolAddress((void**)&p_Kl,  g_Kl);
    cudaGetSymbolAddress((void**)&p_Vth, g_Vth);
    cudaGetSymbolAddress((void**)&p_Vtl, g_Vtl);

    const int smemBytes = 8 * SEG * (int)sizeof(__nv_bfloat16); // 81920
    cudaFuncSetAttribute(gemm_bf16s<0>, cudaFuncAttributeMaxDynamicSharedMemorySize, smemBytes);
    cudaFuncSetAttribute(gemm_bf16s<1>, cudaFuncAttributeMaxDynamicSharedMemorySize, smemBytes);

    // weight splits
    split_kernel<<<(QKV3 * DM / 4 + 255) / 256, 256>>>(W_qkv, p_Wqh, p_Wql, QKV3 * DM / 4);
    split_kernel<<<(DM * DM / 4 + 255) / 256, 256>>>(W_o, p_Woh, p_Wol, DM * DM / 4);
    split_kernel<<<(FFN2 * DM / 4 + 255) / 256, 256>>>(W_fc1, p_Wf1h, p_Wf1l, FFN2 * DM / 4);
    split_kernel<<<(DM * FFN / 4 + 255) / 256, 256>>>(W_fc2, p_Wf2h, p_Wf2l, DM * FFN / 4);

    // 1. LN1 (split output)
    ln_split_kernel<<<T, 256>>>(X, ln1_w, p_Xnh, p_Xnl);
    // 2. qkv = Xn @ W_qkv^T
    gemm_bf16s<0><<<dim3(QKV3 / 128, T / 128), 256, smemBytes>>>(
        p_Xnh, p_Xnl, p_Wqh, p_Wql, nullptr, p_qkv, T, QKV3, DM);
    // 3. de-interleave + split (+ V transpose)
    reshape_split<<<(T * DM) / 256, 256>>>(p_qkv, p_Qh, p_Ql, p_Kh, p_Kl, p_Vth, p_Vtl);
    // 4. attention (tensor-core, split output)
    flash_mma<<<dim3(S / 128, NH, B), 256>>>(p_Qh, p_Ql, p_Kh, p_Kl, p_Vth, p_Vtl,
                                             p_atth, p_attl);
    // 5. X1 = X + attn @ W_o^T
    gemm_bf16s<1><<<dim3(DM / 128, T / 128), 256, smemBytes>>>(
        p_atth, p_attl, p_Woh, p_Wol, X, p_X1, T, DM, DM);
    // 6. LN2 (split output)
    ln_split_kernel<<<T, 256>>>(p_X1, ln2_w, p_Xnh, p_Xnl);
    // 7. u = Xn @ W_fc1^T
    gemm_bf16s<0><<<dim3(FFN2 / 128, T / 128), 256, smemBytes>>>(
        p_Xnh, p_Xnl, p_Wf1h, p_Wf1l, nullptr, p_u, T, FFN2, DM);
    // 8. h = a * gelu(g) (split output)
    geglu_kernel<<<((size_t)T * FFN) / 256, 256>>>(p_u, p_hh, p_hl);
    // 9. out = X1 + h @ W_fc2^T
    gemm_bf16s<1><<<dim3(DM / 128, T / 128), 256, smemBytes>>>(
        p_hh, p_hl, p_Wf2h, p_Wf2l, p_X1, out, T, DM, FFN);
}

// round 7
// speedup vs baseline: 2.3651x; 1.0533x over previous
#include <cuda_runtime.h>
#include <cuda_bf16.h>
#include <math.h>
#include <stdint.h>

// ----------------------------------------------------------------------------
// Problem constants
// ----------------------------------------------------------------------------
#define B        4
#define S        2048
#define T        (B * S)          // 8192 tokens
#define DM       1024             // d_model
#define NH       16               // heads
#define DH       64               // head dim
#define QKV3     (3 * NH * DH)    // 3072
#define FFN      4096
#define FFN2     (2 * FFN)        // 8192

// ----------------------------------------------------------------------------
// Scratch (device globals -> no allocation inside kernel_launch)
// ----------------------------------------------------------------------------
__device__ float g_qkv [(size_t)T * QKV3];  // qkv projection (fp32)
__device__ float g_X1  [(size_t)T * DM];    // X + attn @ Wo^T
__device__ float g_u   [(size_t)T * FFN2];  // fc1 output (a | g)

// bf16 hi/lo split operands
__device__ __nv_bfloat16 g_Xnh [(size_t)T * DM];
__device__ __nv_bfloat16 g_Xnl [(size_t)T * DM];
__device__ __nv_bfloat16 g_atth[(size_t)T * DM];
__device__ __nv_bfloat16 g_attl[(size_t)T * DM];
__device__ __nv_bfloat16 g_hh  [(size_t)T * FFN];
__device__ __nv_bfloat16 g_hl  [(size_t)T * FFN];
__device__ __nv_bfloat16 g_Wqh [(size_t)QKV3 * DM];
__device__ __nv_bfloat16 g_Wql [(size_t)QKV3 * DM];
__device__ __nv_bfloat16 g_Woh [(size_t)DM * DM];
__device__ __nv_bfloat16 g_Wol [(size_t)DM * DM];
__device__ __nv_bfloat16 g_Wf1h[(size_t)FFN2 * DM];
__device__ __nv_bfloat16 g_Wf1l[(size_t)FFN2 * DM];
__device__ __nv_bfloat16 g_Wf2h[(size_t)DM * FFN];
__device__ __nv_bfloat16 g_Wf2l[(size_t)DM * FFN];
// attention operands (bf16 hi/lo)
__device__ __nv_bfloat16 g_Qh [(size_t)T * DM];   // [b,h,s,d]  (pre-scaled 1/8)
__device__ __nv_bfloat16 g_Ql [(size_t)T * DM];
__device__ __nv_bfloat16 g_Kh [(size_t)T * DM];   // [b,h,s,d]
__device__ __nv_bfloat16 g_Kl [(size_t)T * DM];
__device__ __nv_bfloat16 g_Vth[(size_t)T * DM];   // [b,h,d,s]  (transposed)
__device__ __nv_bfloat16 g_Vtl[(size_t)T * DM];

// ----------------------------------------------------------------------------
// fp32 -> (hi, lo) bf16 split
// ----------------------------------------------------------------------------
__device__ __forceinline__ void split1(float x, __nv_bfloat16& h, __nv_bfloat16& l) {
    h = __float2bfloat16_rn(x);
    l = __float2bfloat16_rn(x - __bfloat162float(h));
}

// ----------------------------------------------------------------------------
// Fast exp on FMA pipe (no MUFU). rel err < 3e-8 on clamped range.
// ----------------------------------------------------------------------------
__device__ __forceinline__ float fexp(float x) {
    x = fminf(fmaxf(x, -87.0f), 87.0f);
    const float y = x * 1.4426950408889634f;          // log2(e)
    const float z = y + 12582912.0f;                  // 1.5 * 2^23
    const int   n = __float_as_int(z) - 0x4B400000;   // round-to-nearest int
    const float f = y - (z - 12582912.0f);            // f in [-0.5, 0.5]
    float p = 1.5403530393381609e-4f;
    p = fmaf(p, f, 1.3333558146428443e-3f);
    p = fmaf(p, f, 9.6181291076284772e-3f);
    p = fmaf(p, f, 5.5504108664821580e-2f);
    p = fmaf(p, f, 2.4022650695910072e-1f);
    p = fmaf(p, f, 6.9314718055994531e-1f);
    p = fmaf(p, f, 1.0f);
    return __int_as_float(__float_as_int(p) + (n << 23));
}

__device__ __forceinline__ float frcp(float x) {
    float r;
    asm("rcp.approx.f32 %0, %1;" : "=f"(r) : "f"(x));
    return r;
}

// ----------------------------------------------------------------------------
// Async copy + ldmatrix helpers
// ----------------------------------------------------------------------------
__device__ __forceinline__ void cpasync16(uint32_t dst, const void* src) {
    asm volatile("cp.async.cg.shared.global [%0], [%1], 16;" :: "r"(dst), "l"(src));
}
__device__ __forceinline__ void cp_commit() {
    asm volatile("cp.async.commit_group;");
}
__device__ __forceinline__ void ldsm4(uint32_t* r, uint32_t a) {
    asm volatile("ldmatrix.sync.aligned.m8n8.x4.shared.b16 {%0,%1,%2,%3}, [%4];"
        : "=r"(r[0]), "=r"(r[1]), "=r"(r[2]), "=r"(r[3]) : "r"(a));
}
__device__ __forceinline__ void ldsm2(uint32_t* r, uint32_t a) {
    asm volatile("ldmatrix.sync.aligned.m8n8.x2.shared.b16 {%0,%1}, [%2];"
        : "=r"(r[0]), "=r"(r[1]) : "r"(a));
}

// ----------------------------------------------------------------------------
// Weight split: float4-vectorized
// ----------------------------------------------------------------------------
__global__ __launch_bounds__(256) void split_kernel(const float* __restrict__ X,
                                                    __nv_bfloat16* __restrict__ H,
                                                    __nv_bfloat16* __restrict__ L,
                                                    int n4) {
    const int gid = blockIdx.x * 256 + threadIdx.x;
    if (gid >= n4) return;
    const float4 v = ((const float4*)X)[gid];
    __nv_bfloat16 h0, h1, h2, h3, l0, l1, l2, l3;
    split1(v.x, h0, l0); split1(v.y, h1, l1);
    split1(v.z, h2, l2); split1(v.w, h3, l3);
    __nv_bfloat162* Hp = (__nv_bfloat162*)H;
    __nv_bfloat162* Lp = (__nv_bfloat162*)L;
    Hp[gid * 2]     = __nv_bfloat162(h0, h1);
    Hp[gid * 2 + 1] = __nv_bfloat162(h2, h3);
    Lp[gid * 2]     = __nv_bfloat162(l0, l1);
    Lp[gid * 2 + 1] = __nv_bfloat162(l2, l3);
}

// ----------------------------------------------------------------------------
// LayerNorm with fused hi/lo split output
// ----------------------------------------------------------------------------
__global__ __launch_bounds__(256) void ln_split_kernel(const float* __restrict__ X,
                                                       const float* __restrict__ w,
                                                       __nv_bfloat16* __restrict__ Hh,
                                                       __nv_bfloat16* __restrict__ Hl) {
    const int row = blockIdx.x;
    const int tid = threadIdx.x;
    const float4* xp = (const float4*)(X + (size_t)row * DM);
    float4 v = xp[tid];

    float s  = v.x + v.y + v.z + v.w;
    float sq = v.x * v.x + v.y * v.y + v.z * v.z + v.w * v.w;

    __shared__ float rs[256];
    __shared__ float rq[256];
    rs[tid] = s; rq[tid] = sq;
    __syncthreads();
    #pragma unroll
    for (int o = 128; o >= 1; o >>= 1) {
        if (tid < o) { rs[tid] += rs[tid + o]; rq[tid] += rq[tid + o]; }
        __syncthreads();
    }
    const float mu   = rs[0] * (1.0f / DM);
    const float var  = rq[0] * (1.0f / DM) - mu * mu;
    const float rstd = rsqrtf(var + 1e-5f);

    const float4 wv = ((const float4*)w)[tid];
    float y0 = (v.x - mu) * rstd * wv.x;
    float y1 = (v.y - mu) * rstd * wv.y;
    float y2 = (v.z - mu) * rstd * wv.z;
    float y3 = (v.w - mu) * rstd * wv.w;

    __nv_bfloat16 h0, h1, h2, h3, l0, l1, l2, l3;
    split1(y0, h0, l0); split1(y1, h1, l1);
    split1(y2, h2, l2); split1(y3, h3, l3);
    __nv_bfloat162* Hp = (__nv_bfloat162*)(Hh + (size_t)row * DM);
    __nv_bfloat162* Lp = (__nv_bfloat162*)(Hl + (size_t)row * DM);
    Hp[tid * 2]     = __nv_bfloat162(h0, h1);
    Hp[tid * 2 + 1] = __nv_bfloat162(h2, h3);
    Lp[tid * 2]     = __nv_bfloat162(l0, l1);
    Lp[tid * 2 + 1] = __nv_bfloat162(l2, l3);
}

// ----------------------------------------------------------------------------
// mma.sync m16n8k16 bf16 -> fp32
// ----------------------------------------------------------------------------
__device__ __forceinline__ void mma16816(float* c, const uint32_t* a, const uint32_t* b) {
    asm volatile(
        "mma.sync.aligned.m16n8k16.row.col.f32.bf16.bf16.f32 "
        "{%0,%1,%2,%3},{%4,%5,%6,%7},{%8,%9},{%0,%1,%2,%3};"
        : "+f"(c[0]), "+f"(c[1]), "+f"(c[2]), "+f"(c[3])
        : "r"(a[0]), "r"(a[1]), "r"(a[2]), "r"(a[3]), "r"(b[0]), "r"(b[1]));
}

// ----------------------------------------------------------------------------
// Split-bf16 NT GEMM v2: cp.async 3-stage pipeline + ldmatrix fragments.
// C[m,n] = sum_k A[m,k]*B[n,k], A/B as hi/lo bf16; acc = Ah*Bh + Al*Bh + Ah*Bl.
// Block tile 128x128x32, 256 threads (8 warps 2x4), warp tile 64x32.
// EPI 0: C = AB      EPI 1: C = R + AB
// ----------------------------------------------------------------------------
#define STAGES 3
#define PITCH  40                  // 32 + 8 pad: conflict-free ldmatrix rows
#define SEGB   (128 * PITCH * 2)   // bytes per stage per array = 10240

template <int EPI>
__global__ __launch_bounds__(256) void gemm_bf16s(const __nv_bfloat16* __restrict__ Ah,
                                                  const __nv_bfloat16* __restrict__ Al,
                                                  const __nv_bfloat16* __restrict__ Bh,
                                                  const __nv_bfloat16* __restrict__ Bl,
                                                  const float* __restrict__ R,
                                                  float* __restrict__ C,
                                                  int M, int N, int K) {
    extern __shared__ __nv_bfloat16 smem[];
    const uint32_t sbase = (uint32_t)__cvta_generic_to_shared(smem);

    const int tid  = threadIdx.x;
    const int lane = tid & 31;
    const int warp = tid >> 5;
    const int wm   = warp >> 2;       // 0..1
    const int wn   = warp & 3;        // 0..3

    const int m0 = blockIdx.y * 128;
    const int n0 = blockIdx.x * 128;

    // loader mapping: 512 (row, 8-col-chunk) slots, 2 per thread
    const int r0 = tid >> 2;                // 0..63
    const int r1 = r0 + 64;                 // 64..127
    const int c0 = (tid & 3) * 8;           // 0,8,16,24

    const size_t aOff0 = (size_t)(m0 + r0) * K + c0;
    const size_t aOff1 = (size_t)(m0 + r1) * K + c0;
    const size_t bOff0 = (size_t)(n0 + r0) * K + c0;
    const size_t bOff1 = (size_t)(n0 + r1) * K + c0;
    const uint32_t d0 = (uint32_t)(r0 * PITCH + c0) * 2;
    const uint32_t d1 = (uint32_t)(r1 * PITCH + c0) * 2;

    // ldmatrix per-lane row addresses (bytes)
    const uint32_t aRowB = (uint32_t)(((wm * 64 + (lane & 15)) * PITCH
                                       + ((lane >> 4) << 3)) * 2);
    const uint32_t bRowB = (uint32_t)(((wn * 32 + (lane & 7)) * PITCH
                                       + (((lane >> 3) & 1) << 3)) * 2);

    float acc[4][4][4];
    #pragma unroll
    for (int i = 0; i < 4; i++)
        #pragma unroll
        for (int j = 0; j < 4; j++)
            #pragma unroll
            for (int r = 0; r < 4; r++) acc[i][j][r] = 0.0f;

    const int ntiles = K >> 5;

    // issue one stage's loads (4 arrays x 2 copies of 16B per thread)
    auto issue = [&](int st, int t) {
        const int k0 = t * 32;
        const uint32_t sb = sbase + (uint32_t)st * 4 * SEGB;
        cpasync16(sb + 0 * SEGB + d0, Ah + aOff0 + k0);
        cpasync16(sb + 0 * SEGB + d1, Ah + aOff1 + k0);
        cpasync16(sb + 1 * SEGB + d0, Al + aOff0 + k0);
        cpasync16(sb + 1 * SEGB + d1, Al + aOff1 + k0);
        cpasync16(sb + 2 * SEGB + d0, Bh + bOff0 + k0);
        cpasync16(sb + 2 * SEGB + d1, Bh + bOff1 + k0);
        cpasync16(sb + 3 * SEGB + d0, Bl + bOff0 + k0);
        cpasync16(sb + 3 * SEGB + d1, Bl + bOff1 + k0);
        cp_commit();
    };

    // prologue: stages 0 and 1 in flight
    issue(0, 0);
    issue(1, 1);

    int st = 0;
    for (int t = 0; t < ntiles; t++) {
        if (t + 1 < ntiles) {
            asm volatile("cp.async.wait_group 1;");
        } else {
            asm volatile("cp.async.wait_group 0;");
        }
        __syncthreads();
        if (t + 2 < ntiles) {
            const int nst = (st + 2 >= STAGES) ? st + 2 - STAGES : st + 2;  // true mod 3
            issue(nst, t + 2);
        }

        const uint32_t sb  = sbase + (uint32_t)st * 4 * SEGB;
        const uint32_t pAh = sb;
        const uint32_t pAl = sb + 1 * SEGB;
        const uint32_t pBh = sb + 2 * SEGB;
        const uint32_t pBl = sb + 3 * SEGB;

        #pragma unroll
        for (int kc = 0; kc < 2; kc++) {      // k chunks of 16 (byte off kc*32)
            const uint32_t kb = (uint32_t)kc * 32;
            uint32_t ah[4][4], al[4][4], bh[4][2], bl[4][2];
            #pragma unroll
            for (int i = 0; i < 4; i++) {
                const uint32_t ao = aRowB + (uint32_t)i * (16 * PITCH * 2) + kb;
                ldsm4(ah[i], pAh + ao);
                ldsm4(al[i], pAl + ao);
            }
            #pragma unroll
            for (int j = 0; j < 4; j++) {
                const uint32_t bo = bRowB + (uint32_t)j * (8 * PITCH * 2) + kb;
                ldsm2(bh[j], pBh + bo);
                ldsm2(bl[j], pBl + bo);
            }
            // term-outermost: same accumulator reused only every 16 MMAs
            #pragma unroll
            for (int i = 0; i < 4; i++)
                #pragma unroll
                for (int j = 0; j < 4; j++)
                    mma16816(acc[i][j], ah[i], bh[j]);
            #pragma unroll
            for (int i = 0; i < 4; i++)
                #pragma unroll
                for (int j = 0; j < 4; j++)
                    mma16816(acc[i][j], al[i], bh[j]);
            #pragma unroll
            for (int i = 0; i < 4; i++)
                #pragma unroll
                for (int j = 0; j < 4; j++)
                    mma16816(acc[i][j], ah[i], bl[j]);
        }
        st = (st + 1 == STAGES) ? 0 : st + 1;
    }

    // epilogue (unchanged from validated round 3)
    const int g  = lane >> 2;
    #pragma unroll
    for (int i = 0; i < 4; i++) {
        const int row = m0 + wm * 64 + i * 16 + g;
        #pragma unroll
        for (int j = 0; j < 4; j++) {
            const int col = n0 + wn * 32 + j * 8 + (lane & 3) * 2;
            const size_t o0 = (size_t)row * N + col;
            const size_t o1 = (size_t)(row + 8) * N + col;
            float2 v0 = {acc[i][j][0], acc[i][j][1]};
            float2 v1 = {acc[i][j][2], acc[i][j][3]};
            if (EPI == 1) {
                const float2 r0v = *(const float2*)(R + o0);
                const float2 r1v = *(const float2*)(R + o1);
                v0.x += r0v.x; v0.y += r0v.y;
                v1.x += r1v.x; v1.y += r1v.y;
            }
            *(float2*)(C + o0) = v0;
            *(float2*)(C + o1) = v1;
        }
    }
}

// ----------------------------------------------------------------------------
// De-interleave qkv -> split bf16 Q/K ([b,h,s,d], Q pre-scaled 1/8) and
// V^T ([b,h,d,s]).
// ----------------------------------------------------------------------------
__global__ __launch_bounds__(256) void reshape_split(const float* __restrict__ qkv,
                                                     __nv_bfloat16* __restrict__ Qh,
                                                     __nv_bfloat16* __restrict__ Ql,
                                                     __nv_bfloat16* __restrict__ Kh,
                                                     __nv_bfloat16* __restrict__ Kl,
                                                     __nv_bfloat16* __restrict__ Vth,
                                                     __nv_bfloat16* __restrict__ Vtl) {
    const size_t gid = (size_t)blockIdx.x * 256 + threadIdx.x; // t*1024 + h*64 + d
    const int t = (int)(gid >> 10);
    const int r = (int)(gid & 1023);
    const int h = r >> 6;
    const int d = r & 63;
    const int b = t >> 11;
    const int s = t & 2047;
    const float* src = qkv + (size_t)t * QKV3 + h * (DH * 3) + d * 3;
    const float qv = src[0] * 0.125f;
    const float kv = src[1];
    const float vv = src[2];
    const size_t qk = (((size_t)(b * NH + h)) * S + s) * DH + d;
    const size_t vt = (((size_t)(b * NH + h)) * DH + d) * S + s;
    __nv_bfloat16 hh, ll;
    split1(qv, hh, ll); Qh[qk] = hh; Ql[qk] = ll;
    split1(kv, hh, ll); Kh[qk] = hh; Kl[qk] = ll;
    split1(vv, hh, ll); Vth[vt] = hh; Vtl[vt] = ll;
}

// ----------------------------------------------------------------------------
// Tensor-core flash attention, split-bf16 MMAs, FMA-pipe exp.
// ----------------------------------------------------------------------------
#define FP   72
#define FSEG (64 * FP)

__global__ __launch_bounds__(256) void flash_mma(const __nv_bfloat16* __restrict__ Qh,
                                                 const __nv_bfloat16* __restrict__ Ql,
                                                 const __nv_bfloat16* __restrict__ Kh,
                                                 const __nv_bfloat16* __restrict__ Kl,
                                                 const __nv_bfloat16* __restrict__ Vth,
                                                 const __nv_bfloat16* __restrict__ Vtl,
                                                 __nv_bfloat16* __restrict__ Oh,
                                                 __nv_bfloat16* __restrict__ Ol) {
    __shared__ __nv_bfloat16 sKh[FSEG], sKl[FSEG], sVh[FSEG], sVl[FSEG];

    const int tid  = threadIdx.x;
    const int lane = tid & 31;
    const int w    = tid >> 5;
    const int h    = blockIdx.y;
    const int b    = blockIdx.z;
    const int q0   = blockIdx.x * 128;
    const size_t bh  = (size_t)(b * NH + h) * S;
    const size_t bhd = (size_t)(b * NH + h) * DH;
    const int g  = lane >> 2;
    const int kq = (lane & 3) * 2;

    uint32_t qfh[4][4], qfl[4][4];
    {
        const int row = q0 + w * 16 + g;
        const __nv_bfloat16* b0h = Qh + (bh + row) * DH;
        const __nv_bfloat16* b8h = Qh + (bh + row + 8) * DH;
        const __nv_bfloat16* b0l = Ql + (bh + row) * DH;
        const __nv_bfloat16* b8l = Ql + (bh + row + 8) * DH;
        #pragma unroll
        for (int kc = 0; kc < 4; kc++) {
            const int o = kc * 16 + kq;
            qfh[kc][0] = *(const uint32_t*)(b0h + o);
            qfh[kc][1] = *(const uint32_t*)(b8h + o);
            qfh[kc][2] = *(const uint32_t*)(b0h + o + 8);
            qfh[kc][3] = *(const uint32_t*)(b8h + o + 8);
            qfl[kc][0] = *(const uint32_t*)(b0l + o);
            qfl[kc][1] = *(const uint32_t*)(b8l + o);
            qfl[kc][2] = *(const uint32_t*)(b0l + o + 8);
            qfl[kc][3] = *(const uint32_t*)(b8l + o + 8);
        }
    }

    float o[8][4];
    #pragma unroll
    for (int j = 0; j < 8; j++)
        #pragma unroll
        for (int r = 0; r < 4; r++) o[j][r] = 0.0f;
    float m0 = -INFINITY, m1 = -INFINITY;
    float l0 = 0.0f, l1 = 0.0f;

    const int i0 = tid, i1 = tid + 256;
    const int lr0 = i0 >> 3, lc0 = (i0 & 7) * 8;
    const int lr1 = i1 >> 3, lc1 = (i1 & 7) * 8;

    for (int kt = 0; kt < S; kt += 64) {
        __syncthreads();
        *(uint4*)(sKh + lr0 * FP + lc0) = *(const uint4*)(Kh + (bh + kt + lr0) * DH + lc0);
        *(uint4*)(sKh + lr1 * FP + lc1) = *(const uint4*)(Kh + (bh + kt + lr1) * DH + lc1);
        *(uint4*)(sKl + lr0 * FP + lc0) = *(const uint4*)(Kl + (bh + kt + lr0) * DH + lc0);
        *(uint4*)(sKl + lr1 * FP + lc1) = *(const uint4*)(Kl + (bh + kt + lr1) * DH + lc1);
        *(uint4*)(sVh + lr0 * FP + lc0) = *(const uint4*)(Vth + (bhd + lr0) * S + kt + lc0);
        *(uint4*)(sVh + lr1 * FP + lc1) = *(const uint4*)(Vth + (bhd + lr1) * S + kt + lc1);
        *(uint4*)(sVl + lr0 * FP + lc0) = *(const uint4*)(Vtl + (bhd + lr0) * S + kt + lc0);
        *(uint4*)(sVl + lr1 * FP + lc1) = *(const uint4*)(Vtl + (bhd + lr1) * S + kt + lc1);
        __syncthreads();

        float sc[8][4];
        #pragma unroll
        for (int j = 0; j < 8; j++)
            #pragma unroll
            for (int r = 0; r < 4; r++) sc[j][r] = 0.0f;

        #pragma unroll
        for (int kc = 0; kc < 4; kc++) {
            #pragma unroll
            for (int j = 0; j < 8; j++) {
                const int off = (j * 8 + g) * FP + kc * 16 + kq;
                uint32_t kb[2], klo[2];
                kb[0]  = *(const uint32_t*)(sKh + off);
                kb[1]  = *(const uint32_t*)(sKh + off + 8);
                klo[0] = *(const uint32_t*)(sKl + off);
                klo[1] = *(const uint32_t*)(sKl + off + 8);
                mma16816(sc[j], qfh[kc], kb);
                mma16816(sc[j], qfl[kc], kb);
                mma16816(sc[j], qfh[kc], klo);
            }
        }

        float mx0 = sc[0][0], mx1 = sc[0][2];
        #pragma unroll
        for (int j = 0; j < 8; j++) {
            mx0 = fmaxf(mx0, fmaxf(sc[j][0], sc[j][1]));
            mx1 = fmaxf(mx1, fmaxf(sc[j][2], sc[j][3]));
        }
        mx0 = fmaxf(mx0, __shfl_xor_sync(0xffffffffu, mx0, 1));
        mx0 = fmaxf(mx0, __shfl_xor_sync(0xffffffffu, mx0, 2));
        mx1 = fmaxf(mx1, __shfl_xor_sync(0xffffffffu, mx1, 1));
        mx1 = fmaxf(mx1, __shfl_xor_sync(0xffffffffu, mx1, 2));

        const float mn0 = fmaxf(m0, mx0);
        const float mn1 = fmaxf(m1, mx1);
        const float c0 = fexp(m0 - mn0);
        const float c1 = fexp(m1 - mn1);
        m0 = mn0; m1 = mn1;

        float s0 = 0.0f, s1 = 0.0f;
        #pragma unroll
        for (int j = 0; j < 8; j++) {
            sc[j][0] = fexp(sc[j][0] - mn0);
            sc[j][1] = fexp(sc[j][1] - mn0);
            sc[j][2] = fexp(sc[j][2] - mn1);
            sc[j][3] = fexp(sc[j][3] - mn1);
            s0 += sc[j][0] + sc[j][1];
            s1 += sc[j][2] + sc[j][3];
        }
        s0 += __shfl_xor_sync(0xffffffffu, s0, 1);
        s0 += __shfl_xor_sync(0xffffffffu, s0, 2);
        s1 += __shfl_xor_sync(0xffffffffu, s1, 1);
        s1 += __shfl_xor_sync(0xffffffffu, s1, 2);
        l0 = l0 * c0 + s0;
        l1 = l1 * c1 + s1;

        #pragma unroll
        for (int j = 0; j < 8; j++) {
            o[j][0] *= c0; o[j][1] *= c0;
            o[j][2] *= c1; o[j][3] *= c1;
        }

        #pragma unroll
        for (int t2 = 0; t2 < 4; t2++) {
            uint32_t ph[4], pl[4];
            {
                const float* e = sc[2 * t2];
                const float* f = sc[2 * t2 + 1];
                __nv_bfloat16 hv[8], lv[8];
                split1(e[0], hv[0], lv[0]); split1(e[1], hv[1], lv[1]);
                split1(e[2], hv[2], lv[2]); split1(e[3], hv[3], lv[3]);
                split1(f[0], hv[4], lv[4]); split1(f[1], hv[5], lv[5]);
                split1(f[2], hv[6], lv[6]); split1(f[3], hv[7], lv[7]);
                __nv_bfloat162 t0 = __nv_bfloat162(hv[0], hv[1]);
                __nv_bfloat162 t1 = __nv_bfloat162(hv[2], hv[3]);
                __nv_bfloat162 t2v = __nv_bfloat162(hv[4], hv[5]);
                __nv_bfloat162 t3 = __nv_bfloat162(hv[6], hv[7]);
                ph[0] = *(uint32_t*)&t0; ph[1] = *(uint32_t*)&t1;
                ph[2] = *(uint32_t*)&t2v; ph[3] = *(uint32_t*)&t3;
                t0 = __nv_bfloat162(lv[0], lv[1]);
                t1 = __nv_bfloat162(lv[2], lv[3]);
                t2v = __nv_bfloat162(lv[4], lv[5]);
                t3 = __nv_bfloat162(lv[6], lv[7]);
                pl[0] = *(uint32_t*)&t0; pl[1] = *(uint32_t*)&t1;
                pl[2] = *(uint32_t*)&t2v; pl[3] = *(uint32_t*)&t3;
            }
            #pragma unroll
            for (int j = 0; j < 8; j++) {
                const int off = (j * 8 + g) * FP + t2 * 16 + kq;
                uint32_t vh[2], vl[2];
                vh[0] = *(const uint32_t*)(sVh + off);
                vh[1] = *(const uint32_t*)(sVh + off + 8);
                vl[0] = *(const uint32_t*)(sVl + off);
                vl[1] = *(const uint32_t*)(sVl + off + 8);
                mma16816(o[j], ph, vh);
                mma16816(o[j], pl, vh);
                mma16816(o[j], ph, vl);
            }
        }
    }

    const float inv0 = 1.0f / l0;
    const float inv1 = 1.0f / l1;
    const int row = q0 + w * 16 + g;
    const size_t t0 = (size_t)(b * S + row);
    const size_t t8 = t0 + 8;
    #pragma unroll
    for (int j = 0; j < 8; j++) {
        const int col = h * DH + j * 8 + kq;
        float v0 = o[j][0] * inv0, v1 = o[j][1] * inv0;
        float v2 = o[j][2] * inv1, v3 = o[j][3] * inv1;
        __nv_bfloat16 h0, h1, h2, h3, l0b, l1b, l2b, l3b;
        split1(v0, h0, l0b); split1(v1, h1, l1b);
        split1(v2, h2, l2b); split1(v3, h3, l3b);
        *(__nv_bfloat162*)(Oh + t0 * DM + col) = __nv_bfloat162(h0, h1);
        *(__nv_bfloat162*)(Ol + t0 * DM + col) = __nv_bfloat162(l0b, l1b);
        *(__nv_bfloat162*)(Oh + t8 * DM + col) = __nv_bfloat162(h2, h3);
        *(__nv_bfloat162*)(Ol + t8 * DM + col) = __nv_bfloat162(l2b, l3b);
    }
}

// ----------------------------------------------------------------------------
// GEGLU: h = a * g * sigmoid(2 * 0.79788456*(g + 0.044715 g^3)); split output
// ----------------------------------------------------------------------------
__global__ __launch_bounds__(256) void geglu_kernel(const float* __restrict__ u,
                                                    __nv_bfloat16* __restrict__ Hh,
                                                    __nv_bfloat16* __restrict__ Hl) {
    const size_t gid = (size_t)blockIdx.x * 256 + threadIdx.x;
    const size_t row = gid / FFN;
    const size_t col = gid % FFN;
    const float a = u[row * FFN2 + col];
    const float g = u[row * FFN2 + FFN + col];
    const float z = 0.7978845608028654f * (g + 0.044715f * g * g * g);
    const float ew = fexp(-2.0f * z);
    const float v = a * g * frcp(1.0f + ew);
    __nv_bfloat16 h, l;
    split1(v, h, l);
    Hh[gid] = h;
    Hl[gid] = l;
}

// ----------------------------------------------------------------------------
// Launch
// ----------------------------------------------------------------------------
extern "C" void kernel_launch(void* const* d_in, const int* in_sizes, int n_in,
                              void* d_out, int out_size) {
    const float* X     = (const float*)d_in[0];
    const float* W_qkv = (const float*)d_in[1];
    const float* W_o   = (const float*)d_in[2];
    const float* W_fc1 = (const float*)d_in[3];
    const float* W_fc2 = (const float*)d_in[4];
    const float* ln1_w = (const float*)d_in[5];
    const float* ln2_w = (const float*)d_in[6];
    float* out = (float*)d_out;

    float *p_qkv, *p_X1, *p_u;
    __nv_bfloat16 *p_Xnh, *p_Xnl, *p_atth, *p_attl, *p_hh, *p_hl;
    __nv_bfloat16 *p_Wqh, *p_Wql, *p_Woh, *p_Wol, *p_Wf1h, *p_Wf1l, *p_Wf2h, *p_Wf2l;
    __nv_bfloat16 *p_Qh, *p_Ql, *p_Kh, *p_Kl, *p_Vth, *p_Vtl;
    cudaGetSymbolAddress((void**)&p_qkv, g_qkv);
    cudaGetSymbolAddress((void**)&p_X1,  g_X1);
    cudaGetSymbolAddress((void**)&p_u,   g_u);
    cudaGetSymbolAddress((void**)&p_Xnh,  g_Xnh);
    cudaGetSymbolAddress((void**)&p_Xnl,  g_Xnl);
    cudaGetSymbolAddress((void**)&p_atth, g_atth);
    cudaGetSymbolAddress((void**)&p_attl, g_attl);
    cudaGetSymbolAddress((void**)&p_hh,   g_hh);
    cudaGetSymbolAddress((void**)&p_hl,   g_hl);
    cudaGetSymbolAddress((void**)&p_Wqh,  g_Wqh);
    cudaGetSymbolAddress((void**)&p_Wql,  g_Wql);
    cudaGetSymbolAddress((void**)&p_Woh,  g_Woh);
    cudaGetSymbolAddress((void**)&p_Wol,  g_Wol);
    cudaGetSymbolAddress((void**)&p_Wf1h, g_Wf1h);
    cudaGetSymbolAddress((void**)&p_Wf1l, g_Wf1l);
    cudaGetSymbolAddress((void**)&p_Wf2h, g_Wf2h);
    cudaGetSymbolAddress((void**)&p_Wf2l, g_Wf2l);
    cudaGetSymbolAddress((void**)&p_Qh,  g_Qh);
    cudaGetSymbolAddress((void**)&p_Ql,  g_Ql);
    cudaGetSymbolAddress((void**)&p_Kh,  g_Kh);
    cudaGetSymbolAddress((void**)&p_Kl,  g_Kl);
    cudaGetSymbolAddress((void**)&p_Vth, g_Vth);
    cudaGetSymbolAddress((void**)&p_Vtl, g_Vtl);

    const int smemBytes = STAGES * 4 * SEGB; // 122880
    cudaFuncSetAttribute(gemm_bf16s<0>, cudaFuncAttributeMaxDynamicSharedMemorySize, smemBytes);
    cudaFuncSetAttribute(gemm_bf16s<1>, cudaFuncAttributeMaxDynamicSharedMemorySize, smemBytes);

    // weight splits
    split_kernel<<<(QKV3 * DM / 4 + 255) / 256, 256>>>(W_qkv, p_Wqh, p_Wql, QKV3 * DM / 4);
    split_kernel<<<(DM * DM / 4 + 255) / 256, 256>>>(W_o, p_Woh, p_Wol, DM * DM / 4);
    split_kernel<<<(FFN2 * DM / 4 + 255) / 256, 256>>>(W_fc1, p_Wf1h, p_Wf1l, FFN2 * DM / 4);
    split_kernel<<<(DM * FFN / 4 + 255) / 256, 256>>>(W_fc2, p_Wf2h, p_Wf2l, DM * FFN / 4);

    // 1. LN1 (split output)
    ln_split_kernel<<<T, 256>>>(X, ln1_w, p_Xnh, p_Xnl);
    // 2. qkv = Xn @ W_qkv^T
    gemm_bf16s<0><<<dim3(QKV3 / 128, T / 128), 256, smemBytes>>>(
        p_Xnh, p_Xnl, p_Wqh, p_Wql, nullptr, p_qkv, T, QKV3, DM);
    // 3. de-interleave + split (+ V transpose)
    reshape_split<<<(T * DM) / 256, 256>>>(p_qkv, p_Qh, p_Ql, p_Kh, p_Kl, p_Vth, p_Vtl);
    // 4. attention (tensor-core, split output)
    flash_mma<<<dim3(S / 128, NH, B), 256>>>(p_Qh, p_Ql, p_Kh, p_Kl, p_Vth, p_Vtl,
                                             p_atth, p_attl);
    // 5. X1 = X + attn @ W_o^T
    gemm_bf16s<1><<<dim3(DM / 128, T / 128), 256, smemBytes>>>(
        p_atth, p_attl, p_Woh, p_Wol, X, p_X1, T, DM, DM);
    // 6. LN2 (split output)
    ln_split_kernel<<<T, 256>>>(p_X1, ln2_w, p_Xnh, p_Xnl);
    // 7. u = Xn @ W_fc1^T
    gemm_bf16s<0><<<dim3(FFN2 / 128, T / 128), 256, smemBytes>>>(
        p_Xnh, p_Xnl, p_Wf1h, p_Wf1l, nullptr, p_u, T, FFN2, DM);
    // 8. h = a * gelu(g) (split output)
    geglu_kernel<<<((size_t)T * FFN) / 256, 256>>>(p_u, p_hh, p_hl);
    // 9. out = X1 + h @ W_fc2^T
    gemm_bf16s<1><<<dim3(DM / 128, T / 128), 256, smemBytes>>>(
        p_hh, p_hl, p_Wf2h, p_Wf2l, p_X1, out, T, DM, FFN);
}

// round 11
// speedup vs baseline: 2.3827x; 1.0075x over previous
#include <cuda_runtime.h>
#include <cuda_bf16.h>
#include <math.h>
#include <stdint.h>

// ----------------------------------------------------------------------------
// Problem constants
// ----------------------------------------------------------------------------
#define B        4
#define S        2048
#define T        (B * S)          // 8192 tokens
#define DM       1024             // d_model
#define NH       16               // heads
#define DH       64               // head dim
#define QKV3     (3 * NH * DH)    // 3072
#define FFN      4096
#define FFN2     (2 * FFN)        // 8192

// ----------------------------------------------------------------------------
// Scratch (device globals -> no allocation inside kernel_launch)
// ----------------------------------------------------------------------------
__device__ float g_qkv [(size_t)T * QKV3];  // qkv projection (fp32)
__device__ float g_X1  [(size_t)T * DM];    // X + attn @ Wo^T

// bf16 hi/lo split operands
__device__ __nv_bfloat16 g_Xnh [(size_t)T * DM];
__device__ __nv_bfloat16 g_Xnl [(size_t)T * DM];
__device__ __nv_bfloat16 g_atth[(size_t)T * DM];
__device__ __nv_bfloat16 g_attl[(size_t)T * DM];
__device__ __nv_bfloat16 g_hh  [(size_t)T * FFN];
__device__ __nv_bfloat16 g_hl  [(size_t)T * FFN];
__device__ __nv_bfloat16 g_Wqh [(size_t)QKV3 * DM];
__device__ __nv_bfloat16 g_Wql [(size_t)QKV3 * DM];
__device__ __nv_bfloat16 g_Woh [(size_t)DM * DM];
__device__ __nv_bfloat16 g_Wol [(size_t)DM * DM];
__device__ __nv_bfloat16 g_Wf1h[(size_t)FFN2 * DM];   // row-interleaved (a0,g0,a1,g1,...)
__device__ __nv_bfloat16 g_Wf1l[(size_t)FFN2 * DM];
__device__ __nv_bfloat16 g_Wf2h[(size_t)DM * FFN];
__device__ __nv_bfloat16 g_Wf2l[(size_t)DM * FFN];
// attention operands (bf16 hi/lo)
__device__ __nv_bfloat16 g_Qh [(size_t)T * DM];   // [b,h,s,d]  (pre-scaled 1/8)
__device__ __nv_bfloat16 g_Ql [(size_t)T * DM];
__device__ __nv_bfloat16 g_Kh [(size_t)T * DM];   // [b,h,s,d]
__device__ __nv_bfloat16 g_Kl [(size_t)T * DM];
__device__ __nv_bfloat16 g_Vth[(size_t)T * DM];   // [b,h,d,s]  (transposed)
__device__ __nv_bfloat16 g_Vtl[(size_t)T * DM];

// ----------------------------------------------------------------------------
// fp32 -> (hi, lo) bf16 split
// ----------------------------------------------------------------------------
__device__ __forceinline__ void split1(float x, __nv_bfloat16& h, __nv_bfloat16& l) {
    h = __float2bfloat16_rn(x);
    l = __float2bfloat16_rn(x - __bfloat162float(h));
}

// ----------------------------------------------------------------------------
// Fast exp on FMA pipe (no MUFU). rel err < 3e-8 on clamped range.
// ----------------------------------------------------------------------------
__device__ __forceinline__ float fexp(float x) {
    x = fminf(fmaxf(x, -87.0f), 87.0f);
    const float y = x * 1.4426950408889634f;          // log2(e)
    const float z = y + 12582912.0f;                  // 1.5 * 2^23
    const int   n = __float_as_int(z) - 0x4B400000;   // round-to-nearest int
    const float f = y - (z - 12582912.0f);            // f in [-0.5, 0.5]
    float p = 1.5403530393381609e-4f;
    p = fmaf(p, f, 1.3333558146428443e-3f);
    p = fmaf(p, f, 9.6181291076284772e-3f);
    p = fmaf(p, f, 5.5504108664821580e-2f);
    p = fmaf(p, f, 2.4022650695910072e-1f);
    p = fmaf(p, f, 6.9314718055994531e-1f);
    p = fmaf(p, f, 1.0f);
    return __int_as_float(__float_as_int(p) + (n << 23));
}

__device__ __forceinline__ float frcp(float x) {
    float r;
    asm("rcp.approx.f32 %0, %1;" : "=f"(r) : "f"(x));
    return r;
}

// GEGLU scalar: a * g * sigmoid(2 * 0.79788456*(g + 0.044715 g^3))
__device__ __forceinline__ float geglu1(float a, float g) {
    const float z = 0.7978845608028654f * (g + 0.044715f * g * g * g);
    const float ew = fexp(-2.0f * z);
    return a * g * frcp(1.0f + ew);
}

// ----------------------------------------------------------------------------
// Async copy + ldmatrix helpers
// ----------------------------------------------------------------------------
__device__ __forceinline__ void cpasync16(uint32_t dst, const void* src) {
    asm volatile("cp.async.cg.shared.global [%0], [%1], 16;" :: "r"(dst), "l"(src));
}
__device__ __forceinline__ void cp_commit() {
    asm volatile("cp.async.commit_group;");
}
__device__ __forceinline__ void ldsm4(uint32_t* r, uint32_t a) {
    asm volatile("ldmatrix.sync.aligned.m8n8.x4.shared.b16 {%0,%1,%2,%3}, [%4];"
        : "=r"(r[0]), "=r"(r[1]), "=r"(r[2]), "=r"(r[3]) : "r"(a));
}
__device__ __forceinline__ void ldsm2(uint32_t* r, uint32_t a) {
    asm volatile("ldmatrix.sync.aligned.m8n8.x2.shared.b16 {%0,%1}, [%2];"
        : "=r"(r[0]), "=r"(r[1]) : "r"(a));
}

// ----------------------------------------------------------------------------
// Weight split: float4-vectorized
// ----------------------------------------------------------------------------
__global__ __launch_bounds__(256) void split_kernel(const float* __restrict__ X,
                                                    __nv_bfloat16* __restrict__ H,
                                                    __nv_bfloat16* __restrict__ L,
                                                    int n4) {
    const int gid = blockIdx.x * 256 + threadIdx.x;
    if (gid >= n4) return;
    const float4 v = ((const float4*)X)[gid];
    __nv_bfloat16 h0, h1, h2, h3, l0, l1, l2, l3;
    split1(v.x, h0, l0); split1(v.y, h1, l1);
    split1(v.z, h2, l2); split1(v.w, h3, l3);
    __nv_bfloat162* Hp = (__nv_bfloat162*)H;
    __nv_bfloat162* Lp = (__nv_bfloat162*)L;
    Hp[gid * 2]     = __nv_bfloat162(h0, h1);
    Hp[gid * 2 + 1] = __nv_bfloat162(h2, h3);
    Lp[gid * 2]     = __nv_bfloat162(l0, l1);
    Lp[gid * 2 + 1] = __nv_bfloat162(l2, l3);
}

// ----------------------------------------------------------------------------
// W_fc1 split with row interleave: dst row 2j = src row j (a-weights),
// dst row 2j+1 = src row FFN+j (g-weights). Adjacent output cols of the fc1
// GEMM then form (a, g) pairs, enabling fused GEGLU in the epilogue.
// ----------------------------------------------------------------------------
__global__ __launch_bounds__(256) void split_ilv_kernel(const float* __restrict__ X,
                                                        __nv_bfloat16* __restrict__ H,
                                                        __nv_bfloat16* __restrict__ L,
                                                        int n4) {
    const int gid = blockIdx.x * 256 + threadIdx.x;
    if (gid >= n4) return;
    const int e0   = gid * 4;            // element offset in source
    const int srow = e0 >> 10;           // / DM
    const int col  = e0 & 1023;          // % DM
    const int drow = (srow < FFN) ? (srow * 2) : ((srow - FFN) * 2 + 1);
    const float4 v = ((const float4*)X)[gid];
    __nv_bfloat16 h0, h1, h2, h3, l0, l1, l2, l3;
    split1(v.x, h0, l0); split1(v.y, h1, l1);
    split1(v.z, h2, l2); split1(v.w, h3, l3);
    const size_t d4 = ((size_t)drow * DM + col) >> 1;  // bf162 index
    __nv_bfloat162* Hp = (__nv_bfloat162*)H;
    __nv_bfloat162* Lp = (__nv_bfloat162*)L;
    Hp[d4]     = __nv_bfloat162(h0, h1);
    Hp[d4 + 1] = __nv_bfloat162(h2, h3);
    Lp[d4]     = __nv_bfloat162(l0, l1);
    Lp[d4 + 1] = __nv_bfloat162(l2, l3);
}

// ----------------------------------------------------------------------------
// LayerNorm with fused hi/lo split output
// ----------------------------------------------------------------------------
__global__ __launch_bounds__(256) void ln_split_kernel(const float* __restrict__ X,
                                                       const float* __restrict__ w,
                                                       __nv_bfloat16* __restrict__ Hh,
                                                       __nv_bfloat16* __restrict__ Hl) {
    const int row = blockIdx.x;
    const int tid = threadIdx.x;
    const float4* xp = (const float4*)(X + (size_t)row * DM);
    float4 v = xp[tid];

    float s  = v.x + v.y + v.z + v.w;
    float sq = v.x * v.x + v.y * v.y + v.z * v.z + v.w * v.w;

    __shared__ float rs[256];
    __shared__ float rq[256];
    rs[tid] = s; rq[tid] = sq;
    __syncthreads();
    #pragma unroll
    for (int o = 128; o >= 1; o >>= 1) {
        if (tid < o) { rs[tid] += rs[tid + o]; rq[tid] += rq[tid + o]; }
        __syncthreads();
    }
    const float mu   = rs[0] * (1.0f / DM);
    const float var  = rq[0] * (1.0f / DM) - mu * mu;
    const float rstd = rsqrtf(var + 1e-5f);

    const float4 wv = ((const float4*)w)[tid];
    float y0 = (v.x - mu) * rstd * wv.x;
    float y1 = (v.y - mu) * rstd * wv.y;
    float y2 = (v.z - mu) * rstd * wv.z;
    float y3 = (v.w - mu) * rstd * wv.w;

    __nv_bfloat16 h0, h1, h2, h3, l0, l1, l2, l3;
    split1(y0, h0, l0); split1(y1, h1, l1);
    split1(y2, h2, l2); split1(y3, h3, l3);
    __nv_bfloat162* Hp = (__nv_bfloat162*)(Hh + (size_t)row * DM);
    __nv_bfloat162* Lp = (__nv_bfloat162*)(Hl + (size_t)row * DM);
    Hp[tid * 2]     = __nv_bfloat162(h0, h1);
    Hp[tid * 2 + 1] = __nv_bfloat162(h2, h3);
    Lp[tid * 2]     = __nv_bfloat162(l0, l1);
    Lp[tid * 2 + 1] = __nv_bfloat162(l2, l3);
}

// ----------------------------------------------------------------------------
// mma.sync m16n8k16 bf16 -> fp32
// ----------------------------------------------------------------------------
__device__ __forceinline__ void mma16816(float* c, const uint32_t* a, const uint32_t* b) {
    asm volatile(
        "mma.sync.aligned.m16n8k16.row.col.f32.bf16.bf16.f32 "
        "{%0,%1,%2,%3},{%4,%5,%6,%7},{%8,%9},{%0,%1,%2,%3};"
        : "+f"(c[0]), "+f"(c[1]), "+f"(c[2]), "+f"(c[3])
        : "r"(a[0]), "r"(a[1]), "r"(a[2]), "r"(a[3]), "r"(b[0]), "r"(b[1]));
}

// ----------------------------------------------------------------------------
// Split-bf16 NT GEMM: cp.async 3-stage pipeline + ldmatrix fragments.
// acc = Ah*Bh + Al*Bh + Ah*Bl  (fp32).
// Block tile 128x128x32, 256 threads (8 warps 2x4), warp tile 64x32.
// EPI 0: C = AB (fp32)
// EPI 1: C = R + AB (fp32)
// EPI 2: fused GEGLU: B rows interleaved (a,g); out bf16 hi/lo at col/2.
// ----------------------------------------------------------------------------
#define STAGES 3
#define PITCH  40
#define SEGB   (128 * PITCH * 2)   // bytes per stage per array = 10240

template <int EPI>
__global__ __launch_bounds__(256) void gemm_bf16s(const __nv_bfloat16* __restrict__ Ah,
                                                  const __nv_bfloat16* __restrict__ Al,
                                                  const __nv_bfloat16* __restrict__ Bh,
                                                  const __nv_bfloat16* __restrict__ Bl,
                                                  const float* __restrict__ R,
                                                  float* __restrict__ C,
                                                  __nv_bfloat16* __restrict__ Gh,
                                                  __nv_bfloat16* __restrict__ Gl,
                                                  int M, int N, int K) {
    extern __shared__ __nv_bfloat16 smem[];
    const uint32_t sbase = (uint32_t)__cvta_generic_to_shared(smem);

    const int tid  = threadIdx.x;
    const int lane = tid & 31;
    const int warp = tid >> 5;
    const int wm   = warp >> 2;
    const int wn   = warp & 3;

    const int m0 = blockIdx.y * 128;
    const int n0 = blockIdx.x * 128;

    const int r0 = tid >> 2;
    const int r1 = r0 + 64;
    const int c0 = (tid & 3) * 8;

    const size_t aOff0 = (size_t)(m0 + r0) * K + c0;
    const size_t aOff1 = (size_t)(m0 + r1) * K + c0;
    const size_t bOff0 = (size_t)(n0 + r0) * K + c0;
    const size_t bOff1 = (size_t)(n0 + r1) * K + c0;
    const uint32_t d0 = (uint32_t)(r0 * PITCH + c0) * 2;
    const uint32_t d1 = (uint32_t)(r1 * PITCH + c0) * 2;

    const uint32_t aRowB = (uint32_t)(((wm * 64 + (lane & 15)) * PITCH
                                       + ((lane >> 4) << 3)) * 2);
    const uint32_t bRowB = (uint32_t)(((wn * 32 + (lane & 7)) * PITCH
                                       + (((lane >> 3) & 1) << 3)) * 2);

    float acc[4][4][4];
    #pragma unroll
    for (int i = 0; i < 4; i++)
        #pragma unroll
        for (int j = 0; j < 4; j++)
            #pragma unroll
            for (int r = 0; r < 4; r++) acc[i][j][r] = 0.0f;

    const int ntiles = K >> 5;

    auto issue = [&](int st, int t) {
        const int k0 = t * 32;
        const uint32_t sb = sbase + (uint32_t)st * 4 * SEGB;
        cpasync16(sb + 0 * SEGB + d0, Ah + aOff0 + k0);
        cpasync16(sb + 0 * SEGB + d1, Ah + aOff1 + k0);
        cpasync16(sb + 1 * SEGB + d0, Al + aOff0 + k0);
        cpasync16(sb + 1 * SEGB + d1, Al + aOff1 + k0);
        cpasync16(sb + 2 * SEGB + d0, Bh + bOff0 + k0);
        cpasync16(sb + 2 * SEGB + d1, Bh + bOff1 + k0);
        cpasync16(sb + 3 * SEGB + d0, Bl + bOff0 + k0);
        cpasync16(sb + 3 * SEGB + d1, Bl + bOff1 + k0);
        cp_commit();
    };

    issue(0, 0);
    issue(1, 1);

    int st = 0;
    for (int t = 0; t < ntiles; t++) {
        if (t + 1 < ntiles) {
            asm volatile("cp.async.wait_group 1;");
        } else {
            asm volatile("cp.async.wait_group 0;");
        }
        __syncthreads();
        if (t + 2 < ntiles) {
            const int nst = (st + 2 >= STAGES) ? st + 2 - STAGES : st + 2;
            issue(nst, t + 2);
        }

        const uint32_t sb  = sbase + (uint32_t)st * 4 * SEGB;
        const uint32_t pAh = sb;
        const uint32_t pAl = sb + 1 * SEGB;
        const uint32_t pBh = sb + 2 * SEGB;
        const uint32_t pBl = sb + 3 * SEGB;

        #pragma unroll
        for (int kc = 0; kc < 2; kc++) {
            const uint32_t kb = (uint32_t)kc * 32;
            uint32_t ah[4][4], al[4][4], bh[4][2], bl[4][2];
            #pragma unroll
            for (int i = 0; i < 4; i++) {
                const uint32_t ao = aRowB + (uint32_t)i * (16 * PITCH * 2) + kb;
                ldsm4(ah[i], pAh + ao);
                ldsm4(al[i], pAl + ao);
            }
            #pragma unroll
            for (int j = 0; j < 4; j++) {
                const uint32_t bo = bRowB + (uint32_t)j * (8 * PITCH * 2) + kb;
                ldsm2(bh[j], pBh + bo);
                ldsm2(bl[j], pBl + bo);
            }
            #pragma unroll
            for (int i = 0; i < 4; i++)
                #pragma unroll
                for (int j = 0; j < 4; j++)
                    mma16816(acc[i][j], ah[i], bh[j]);
            #pragma unroll
            for (int i = 0; i < 4; i++)
                #pragma unroll
                for (int j = 0; j < 4; j++)
                    mma16816(acc[i][j], al[i], bh[j]);
            #pragma unroll
            for (int i = 0; i < 4; i++)
                #pragma unroll
                for (int j = 0; j < 4; j++)
                    mma16816(acc[i][j], ah[i], bl[j]);
        }
        st = (st + 1 == STAGES) ? 0 : st + 1;
    }

    // epilogue
    const int g = lane >> 2;
    #pragma unroll
    for (int i = 0; i < 4; i++) {
        const int row = m0 + wm * 64 + i * 16 + g;
        #pragma unroll
        for (int j = 0; j < 4; j++) {
            const int col = n0 + wn * 32 + j * 8 + (lane & 3) * 2;
            if (EPI == 2) {
                // fused GEGLU: (acc[.][0], acc[.][1]) = (a, g) for row;
                //              (acc[.][2], acc[.][3]) = (a, g) for row+8.
                const int oc = col >> 1;              // output col in [0, N/2)
                const float v0 = geglu1(acc[i][j][0], acc[i][j][1]);
                const float v1 = geglu1(acc[i][j][2], acc[i][j][3]);
                __nv_bfloat16 h0, l0, h1, l1;
                split1(v0, h0, l0);
                split1(v1, h1, l1);
                const size_t o0 = (size_t)row * (N >> 1) + oc;
                const size_t o1 = (size_t)(row + 8) * (N >> 1) + oc;
                Gh[o0] = h0; Gl[o0] = l0;
                Gh[o1] = h1; Gl[o1] = l1;
            } else {
                const size_t o0 = (size_t)row * N + col;
                const size_t o1 = (size_t)(row + 8) * N + col;
                float2 v0 = {acc[i][j][0], acc[i][j][1]};
                float2 v1 = {acc[i][j][2], acc[i][j][3]};
                if (EPI == 1) {
                    const float2 r0v = *(const float2*)(R + o0);
                    const float2 r1v = *(const float2*)(R + o1);
                    v0.x += r0v.x; v0.y += r0v.y;
                    v1.x += r1v.x; v1.y += r1v.y;
                }
                *(float2*)(C + o0) = v0;
                *(float2*)(C + o1) = v1;
            }
        }
    }
}

// ----------------------------------------------------------------------------
// De-interleave qkv -> split bf16 Q/K ([b,h,s,d], Q pre-scaled 1/8), V^T.
// ----------------------------------------------------------------------------
__global__ __launch_bounds__(256) void reshape_split(const float* __restrict__ qkv,
                                                     __nv_bfloat16* __restrict__ Qh,
                                                     __nv_bfloat16* __restrict__ Ql,
                                                     __nv_bfloat16* __restrict__ Kh,
                                                     __nv_bfloat16* __restrict__ Kl,
                                                     __nv_bfloat16* __restrict__ Vth,
                                                     __nv_bfloat16* __restrict__ Vtl) {
    const size_t gid = (size_t)blockIdx.x * 256 + threadIdx.x;
    const int t = (int)(gid >> 10);
    const int r = (int)(gid & 1023);
    const int h = r >> 6;
    const int d = r & 63;
    const int b = t >> 11;
    const int s = t & 2047;
    const float* src = qkv + (size_t)t * QKV3 + h * (DH * 3) + d * 3;
    const float qv = src[0] * 0.125f;
    const float kv = src[1];
    const float vv = src[2];
    const size_t qk = (((size_t)(b * NH + h)) * S + s) * DH + d;
    const size_t vt = (((size_t)(b * NH + h)) * DH + d) * S + s;
    __nv_bfloat16 hh, ll;
    split1(qv, hh, ll); Qh[qk] = hh; Ql[qk] = ll;
    split1(kv, hh, ll); Kh[qk] = hh; Kl[qk] = ll;
    split1(vv, hh, ll); Vth[vt] = hh; Vtl[vt] = ll;
}

// ----------------------------------------------------------------------------
// Tensor-core flash attention (unchanged, validated)
// ----------------------------------------------------------------------------
#define FP   72
#define FSEG (64 * FP)

__global__ __launch_bounds__(256) void flash_mma(const __nv_bfloat16* __restrict__ Qh,
                                                 const __nv_bfloat16* __restrict__ Ql,
                                                 const __nv_bfloat16* __restrict__ Kh,
                                                 const __nv_bfloat16* __restrict__ Kl,
                                                 const __nv_bfloat16* __restrict__ Vth,
                                                 const __nv_bfloat16* __restrict__ Vtl,
                                                 __nv_bfloat16* __restrict__ Oh,
                                                 __nv_bfloat16* __restrict__ Ol) {
    __shared__ __nv_bfloat16 sKh[FSEG], sKl[FSEG], sVh[FSEG], sVl[FSEG];

    const int tid  = threadIdx.x;
    const int lane = tid & 31;
    const int w    = tid >> 5;
    const int h    = blockIdx.y;
    const int b    = blockIdx.z;
    const int q0   = blockIdx.x * 128;
    const size_t bh  = (size_t)(b * NH + h) * S;
    const size_t bhd = (size_t)(b * NH + h) * DH;
    const int g  = lane >> 2;
    const int kq = (lane & 3) * 2;

    uint32_t qfh[4][4], qfl[4][4];
    {
        const int row = q0 + w * 16 + g;
        const __nv_bfloat16* b0h = Qh + (bh + row) * DH;
        const __nv_bfloat16* b8h = Qh + (bh + row + 8) * DH;
        const __nv_bfloat16* b0l = Ql + (bh + row) * DH;
        const __nv_bfloat16* b8l = Ql + (bh + row + 8) * DH;
        #pragma unroll
        for (int kc = 0; kc < 4; kc++) {
            const int o = kc * 16 + kq;
            qfh[kc][0] = *(const uint32_t*)(b0h + o);
            qfh[kc][1] = *(const uint32_t*)(b8h + o);
            qfh[kc][2] = *(const uint32_t*)(b0h + o + 8);
            qfh[kc][3] = *(const uint32_t*)(b8h + o + 8);
            qfl[kc][0] = *(const uint32_t*)(b0l + o);
            qfl[kc][1] = *(const uint32_t*)(b8l + o);
            qfl[kc][2] = *(const uint32_t*)(b0l + o + 8);
            qfl[kc][3] = *(const uint32_t*)(b8l + o + 8);
        }
    }

    float o[8][4];
    #pragma unroll
    for (int j = 0; j < 8; j++)
        #pragma unroll
        for (int r = 0; r < 4; r++) o[j][r] = 0.0f;
    float m0 = -INFINITY, m1 = -INFINITY;
    float l0 = 0.0f, l1 = 0.0f;

    const int i0 = tid, i1 = tid + 256;
    const int lr0 = i0 >> 3, lc0 = (i0 & 7) * 8;
    const int lr1 = i1 >> 3, lc1 = (i1 & 7) * 8;

    for (int kt = 0; kt < S; kt += 64) {
        __syncthreads();
        *(uint4*)(sKh + lr0 * FP + lc0) = *(const uint4*)(Kh + (bh + kt + lr0) * DH + lc0);
        *(uint4*)(sKh + lr1 * FP + lc1) = *(const uint4*)(Kh + (bh + kt + lr1) * DH + lc1);
        *(uint4*)(sKl + lr0 * FP + lc0) = *(const uint4*)(Kl + (bh + kt + lr0) * DH + lc0);
        *(uint4*)(sKl + lr1 * FP + lc1) = *(const uint4*)(Kl + (bh + kt + lr1) * DH + lc1);
        *(uint4*)(sVh + lr0 * FP + lc0) = *(const uint4*)(Vth + (bhd + lr0) * S + kt + lc0);
        *(uint4*)(sVh + lr1 * FP + lc1) = *(const uint4*)(Vth + (bhd + lr1) * S + kt + lc1);
        *(uint4*)(sVl + lr0 * FP + lc0) = *(const uint4*)(Vtl + (bhd + lr0) * S + kt + lc0);
        *(uint4*)(sVl + lr1 * FP + lc1) = *(const uint4*)(Vtl + (bhd + lr1) * S + kt + lc1);
        __syncthreads();

        float sc[8][4];
        #pragma unroll
        for (int j = 0; j < 8; j++)
            #pragma unroll
            for (int r = 0; r < 4; r++) sc[j][r] = 0.0f;

        #pragma unroll
        for (int kc = 0; kc < 4; kc++) {
            #pragma unroll
            for (int j = 0; j < 8; j++) {
                const int off = (j * 8 + g) * FP + kc * 16 + kq;
                uint32_t kb[2], klo[2];
                kb[0]  = *(const uint32_t*)(sKh + off);
                kb[1]  = *(const uint32_t*)(sKh + off + 8);
                klo[0] = *(const uint32_t*)(sKl + off);
                klo[1] = *(const uint32_t*)(sKl + off + 8);
                mma16816(sc[j], qfh[kc], kb);
                mma16816(sc[j], qfl[kc], kb);
                mma16816(sc[j], qfh[kc], klo);
            }
        }

        float mx0 = sc[0][0], mx1 = sc[0][2];
        #pragma unroll
        for (int j = 0; j < 8; j++) {
            mx0 = fmaxf(mx0, fmaxf(sc[j][0], sc[j][1]));
            mx1 = fmaxf(mx1, fmaxf(sc[j][2], sc[j][3]));
        }
        mx0 = fmaxf(mx0, __shfl_xor_sync(0xffffffffu, mx0, 1));
        mx0 = fmaxf(mx0, __shfl_xor_sync(0xffffffffu, mx0, 2));
        mx1 = fmaxf(mx1, __shfl_xor_sync(0xffffffffu, mx1, 1));
        mx1 = fmaxf(mx1, __shfl_xor_sync(0xffffffffu, mx1, 2));

        const float mn0 = fmaxf(m0, mx0);
        const float mn1 = fmaxf(m1, mx1);
        const float c0 = fexp(m0 - mn0);
        const float c1 = fexp(m1 - mn1);
        m0 = mn0; m1 = mn1;

        float s0 = 0.0f, s1 = 0.0f;
        #pragma unroll
        for (int j = 0; j < 8; j++) {
            sc[j][0] = fexp(sc[j][0] - mn0);
            sc[j][1] = fexp(sc[j][1] - mn0);
            sc[j][2] = fexp(sc[j][2] - mn1);
            sc[j][3] = fexp(sc[j][3] - mn1);
            s0 += sc[j][0] + sc[j][1];
            s1 += sc[j][2] + sc[j][3];
        }
        s0 += __shfl_xor_sync(0xffffffffu, s0, 1);
        s0 += __shfl_xor_sync(0xffffffffu, s0, 2);
        s1 += __shfl_xor_sync(0xffffffffu, s1, 1);
        s1 += __shfl_xor_sync(0xffffffffu, s1, 2);
        l0 = l0 * c0 + s0;
        l1 = l1 * c1 + s1;

        #pragma unroll
        for (int j = 0; j < 8; j++) {
            o[j][0] *= c0; o[j][1] *= c0;
            o[j][2] *= c1; o[j][3] *= c1;
        }

        #pragma unroll
        for (int t2 = 0; t2 < 4; t2++) {
            uint32_t ph[4], pl[4];
            {
                const float* e = sc[2 * t2];
                const float* f = sc[2 * t2 + 1];
                __nv_bfloat16 hv[8], lv[8];
                split1(e[0], hv[0], lv[0]); split1(e[1], hv[1], lv[1]);
                split1(e[2], hv[2], lv[2]); split1(e[3], hv[3], lv[3]);
                split1(f[0], hv[4], lv[4]); split1(f[1], hv[5], lv[5]);
                split1(f[2], hv[6], lv[6]); split1(f[3], hv[7], lv[7]);
                __nv_bfloat162 t0 = __nv_bfloat162(hv[0], hv[1]);
                __nv_bfloat162 t1 = __nv_bfloat162(hv[2], hv[3]);
                __nv_bfloat162 t2v = __nv_bfloat162(hv[4], hv[5]);
                __nv_bfloat162 t3 = __nv_bfloat162(hv[6], hv[7]);
                ph[0] = *(uint32_t*)&t0; ph[1] = *(uint32_t*)&t1;
                ph[2] = *(uint32_t*)&t2v; ph[3] = *(uint32_t*)&t3;
                t0 = __nv_bfloat162(lv[0], lv[1]);
                t1 = __nv_bfloat162(lv[2], lv[3]);
                t2v = __nv_bfloat162(lv[4], lv[5]);
                t3 = __nv_bfloat162(lv[6], lv[7]);
                pl[0] = *(uint32_t*)&t0; pl[1] = *(uint32_t*)&t1;
                pl[2] = *(uint32_t*)&t2v; pl[3] = *(uint32_t*)&t3;
            }
            #pragma unroll
            for (int j = 0; j < 8; j++) {
                const int off = (j * 8 + g) * FP + t2 * 16 + kq;
                uint32_t vh[2], vl[2];
                vh[0] = *(const uint32_t*)(sVh + off);
                vh[1] = *(const uint32_t*)(sVh + off + 8);
                vl[0] = *(const uint32_t*)(sVl + off);
                vl[1] = *(const uint32_t*)(sVl + off + 8);
                mma16816(o[j], ph, vh);
                mma16816(o[j], pl, vh);
                mma16816(o[j], ph, vl);
            }
        }
    }

    const float inv0 = 1.0f / l0;
    const float inv1 = 1.0f / l1;
    const int row = q0 + w * 16 + g;
    const size_t t0 = (size_t)(b * S + row);
    const size_t t8 = t0 + 8;
    #pragma unroll
    for (int j = 0; j < 8; j++) {
        const int col = h * DH + j * 8 + kq;
        float v0 = o[j][0] * inv0, v1 = o[j][1] * inv0;
        float v2 = o[j][2] * inv1, v3 = o[j][3] * inv1;
        __nv_bfloat16 h0, h1, h2, h3, l0b, l1b, l2b, l3b;
        split1(v0, h0, l0b); split1(v1, h1, l1b);
        split1(v2, h2, l2b); split1(v3, h3, l3b);
        *(__nv_bfloat162*)(Oh + t0 * DM + col) = __nv_bfloat162(h0, h1);
        *(__nv_bfloat162*)(Ol + t0 * DM + col) = __nv_bfloat162(l0b, l1b);
        *(__nv_bfloat162*)(Oh + t8 * DM + col) = __nv_bfloat162(h2, h3);
        *(__nv_bfloat162*)(Ol + t8 * DM + col) = __nv_bfloat162(l2b, l3b);
    }
}

// ----------------------------------------------------------------------------
// Launch
// ----------------------------------------------------------------------------
extern "C" void kernel_launch(void* const* d_in, const int* in_sizes, int n_in,
                              void* d_out, int out_size) {
    const float* X     = (const float*)d_in[0];
    const float* W_qkv = (const float*)d_in[1];
    const float* W_o   = (const float*)d_in[2];
    const float* W_fc1 = (const float*)d_in[3];
    const float* W_fc2 = (const float*)d_in[4];
    const float* ln1_w = (const float*)d_in[5];
    const float* ln2_w = (const float*)d_in[6];
    float* out = (float*)d_out;

    float *p_qkv, *p_X1;
    __nv_bfloat16 *p_Xnh, *p_Xnl, *p_atth, *p_attl, *p_hh, *p_hl;
    __nv_bfloat16 *p_Wqh, *p_Wql, *p_Woh, *p_Wol, *p_Wf1h, *p_Wf1l, *p_Wf2h, *p_Wf2l;
    __nv_bfloat16 *p_Qh, *p_Ql, *p_Kh, *p_Kl, *p_Vth, *p_Vtl;
    cudaGetSymbolAddress((void**)&p_qkv, g_qkv);
    cudaGetSymbolAddress((void**)&p_X1,  g_X1);
    cudaGetSymbolAddress((void**)&p_Xnh,  g_Xnh);
    cudaGetSymbolAddress((void**)&p_Xnl,  g_Xnl);
    cudaGetSymbolAddress((void**)&p_atth, g_atth);
    cudaGetSymbolAddress((void**)&p_attl, g_attl);
    cudaGetSymbolAddress((void**)&p_hh,   g_hh);
    cudaGetSymbolAddress((void**)&p_hl,   g_hl);
    cudaGetSymbolAddress((void**)&p_Wqh,  g_Wqh);
    cudaGetSymbolAddress((void**)&p_Wql,  g_Wql);
    cudaGetSymbolAddress((void**)&p_Woh,  g_Woh);
    cudaGetSymbolAddress((void**)&p_Wol,  g_Wol);
    cudaGetSymbolAddress((void**)&p_Wf1h, g_Wf1h);
    cudaGetSymbolAddress((void**)&p_Wf1l, g_Wf1l);
    cudaGetSymbolAddress((void**)&p_Wf2h, g_Wf2h);
    cudaGetSymbolAddress((void**)&p_Wf2l, g_Wf2l);
    cudaGetSymbolAddress((void**)&p_Qh,  g_Qh);
    cudaGetSymbolAddress((void**)&p_Ql,  g_Ql);
    cudaGetSymbolAddress((void**)&p_Kh,  g_Kh);
    cudaGetSymbolAddress((void**)&p_Kl,  g_Kl);
    cudaGetSymbolAddress((void**)&p_Vth, g_Vth);
    cudaGetSymbolAddress((void**)&p_Vtl, g_Vtl);

    const int smemBytes = STAGES * 4 * SEGB; // 122880
    cudaFuncSetAttribute(gemm_bf16s<0>, cudaFuncAttributeMaxDynamicSharedMemorySize, smemBytes);
    cudaFuncSetAttribute(gemm_bf16s<1>, cudaFuncAttributeMaxDynamicSharedMemorySize, smemBytes);
    cudaFuncSetAttribute(gemm_bf16s<2>, cudaFuncAttributeMaxDynamicSharedMemorySize, smemBytes);

    // weight splits (fc1 interleaved for fused GEGLU)
    split_kernel<<<(QKV3 * DM / 4 + 255) / 256, 256>>>(W_qkv, p_Wqh, p_Wql, QKV3 * DM / 4);
    split_kernel<<<(DM * DM / 4 + 255) / 256, 256>>>(W_o, p_Woh, p_Wol, DM * DM / 4);
    split_ilv_kernel<<<(FFN2 * DM / 4 + 255) / 256, 256>>>(W_fc1, p_Wf1h, p_Wf1l, FFN2 * DM / 4);
    split_kernel<<<(DM * FFN / 4 + 255) / 256, 256>>>(W_fc2, p_Wf2h, p_Wf2l, DM * FFN / 4);

    // 1. LN1
    ln_split_kernel<<<T, 256>>>(X, ln1_w, p_Xnh, p_Xnl);
    // 2. qkv = Xn @ W_qkv^T
    gemm_bf16s<0><<<dim3(QKV3 / 128, T / 128), 256, smemBytes>>>(
        p_Xnh, p_Xnl, p_Wqh, p_Wql, nullptr, p_qkv, nullptr, nullptr, T, QKV3, DM);
    // 3. de-interleave + split
    reshape_split<<<(T * DM) / 256, 256>>>(p_qkv, p_Qh, p_Ql, p_Kh, p_Kl, p_Vth, p_Vtl);
    // 4. attention
    flash_mma<<<dim3(S / 128, NH, B), 256>>>(p_Qh, p_Ql, p_Kh, p_Kl, p_Vth, p_Vtl,
                                             p_atth, p_attl);
    // 5. X1 = X + attn @ W_o^T
    gemm_bf16s<1><<<dim3(DM / 128, T / 128), 256, smemBytes>>>(
        p_atth, p_attl, p_Woh, p_Wol, X, p_X1, nullptr, nullptr, T, DM, DM);
    // 6. LN2
    ln_split_kernel<<<T, 256>>>(p_X1, ln2_w, p_Xnh, p_Xnl);
    // 7+8. h = geglu(Xn @ W_fc1_interleaved^T)  — fused epilogue, split output
    gemm_bf16s<2><<<dim3(FFN2 / 128, T / 128), 256, smemBytes>>>(
        p_Xnh, p_Xnl, p_Wf1h, p_Wf1l, nullptr, nullptr, p_hh, p_hl, T, FFN2, DM);
    // 9. out = X1 + h @ W_fc2^T
    gemm_bf16s<1><<<dim3(DM / 128, T / 128), 256, smemBytes>>>(
        p_hh, p_hl, p_Wf2h, p_Wf2l, p_X1, out, nullptr, nullptr, T, DM, FFN);
}

// round 12
// speedup vs baseline: 2.5642x; 1.0761x over previous
#include <cuda_runtime.h>
#include <cuda_bf16.h>
#include <math.h>
#include <stdint.h>

// ----------------------------------------------------------------------------
// Problem constants
// ----------------------------------------------------------------------------
#define B        4
#define S        2048
#define T        (B * S)          // 8192 tokens
#define DM       1024             // d_model
#define NH       16               // heads
#define DH       64               // head dim
#define QKV3     (3 * NH * DH)    // 3072
#define FFN      4096
#define FFN2     (2 * FFN)        // 8192

// ----------------------------------------------------------------------------
// Scratch (device globals -> no allocation inside kernel_launch)
// ----------------------------------------------------------------------------
__device__ float g_qkv [(size_t)T * QKV3];  // qkv projection (fp32)
__device__ float g_X1  [(size_t)T * DM];    // X + attn @ Wo^T

// bf16 hi/lo split operands
__device__ __nv_bfloat16 g_Xnh [(size_t)T * DM];
__device__ __nv_bfloat16 g_Xnl [(size_t)T * DM];
__device__ __nv_bfloat16 g_atth[(size_t)T * DM];
__device__ __nv_bfloat16 g_attl[(size_t)T * DM];
__device__ __nv_bfloat16 g_hh  [(size_t)T * FFN];
__device__ __nv_bfloat16 g_hl  [(size_t)T * FFN];
__device__ __nv_bfloat16 g_Wqh [(size_t)QKV3 * DM];
__device__ __nv_bfloat16 g_Wql [(size_t)QKV3 * DM];
__device__ __nv_bfloat16 g_Woh [(size_t)DM * DM];
__device__ __nv_bfloat16 g_Wol [(size_t)DM * DM];
__device__ __nv_bfloat16 g_Wf1h[(size_t)FFN2 * DM];   // row-interleaved (a0,g0,a1,g1,...)
__device__ __nv_bfloat16 g_Wf1l[(size_t)FFN2 * DM];
__device__ __nv_bfloat16 g_Wf2h[(size_t)DM * FFN];
__device__ __nv_bfloat16 g_Wf2l[(size_t)DM * FFN];
// attention operands (bf16 hi/lo)
__device__ __nv_bfloat16 g_Qh [(size_t)T * DM];   // [b,h,s,d]  (pre-scaled 1/8)
__device__ __nv_bfloat16 g_Ql [(size_t)T * DM];
__device__ __nv_bfloat16 g_Kh [(size_t)T * DM];   // [b,h,s,d]
__device__ __nv_bfloat16 g_Kl [(size_t)T * DM];
__device__ __nv_bfloat16 g_Vth[(size_t)T * DM];   // [b,h,d,s]  (transposed)
__device__ __nv_bfloat16 g_Vtl[(size_t)T * DM];

// ----------------------------------------------------------------------------
// fp32 -> (hi, lo) bf16 split
// ----------------------------------------------------------------------------
__device__ __forceinline__ void split1(float x, __nv_bfloat16& h, __nv_bfloat16& l) {
    h = __float2bfloat16_rn(x);
    l = __float2bfloat16_rn(x - __bfloat162float(h));
}

// ----------------------------------------------------------------------------
// Fast exp on FMA pipe (no MUFU). rel err < 3e-8 on clamped range.
// ----------------------------------------------------------------------------
__device__ __forceinline__ float fexp(float x) {
    x = fminf(fmaxf(x, -87.0f), 87.0f);
    const float y = x * 1.4426950408889634f;          // log2(e)
    const float z = y + 12582912.0f;                  // 1.5 * 2^23
    const int   n = __float_as_int(z) - 0x4B400000;   // round-to-nearest int
    const float f = y - (z - 12582912.0f);            // f in [-0.5, 0.5]
    float p = 1.5403530393381609e-4f;
    p = fmaf(p, f, 1.3333558146428443e-3f);
    p = fmaf(p, f, 9.6181291076284772e-3f);
    p = fmaf(p, f, 5.5504108664821580e-2f);
    p = fmaf(p, f, 2.4022650695910072e-1f);
    p = fmaf(p, f, 6.9314718055994531e-1f);
    p = fmaf(p, f, 1.0f);
    return __int_as_float(__float_as_int(p) + (n << 23));
}

__device__ __forceinline__ float frcp(float x) {
    float r;
    asm("rcp.approx.f32 %0, %1;" : "=f"(r) : "f"(x));
    return r;
}

// GEGLU scalar: a * g * sigmoid(2 * 0.79788456*(g + 0.044715 g^3))
__device__ __forceinline__ float geglu1(float a, float g) {
    const float z = 0.7978845608028654f * (g + 0.044715f * g * g * g);
    const float ew = fexp(-2.0f * z);
    return a * g * frcp(1.0f + ew);
}

// ----------------------------------------------------------------------------
// Async copy + ldmatrix helpers
// ----------------------------------------------------------------------------
__device__ __forceinline__ void cpasync16(uint32_t dst, const void* src) {
    asm volatile("cp.async.cg.shared.global [%0], [%1], 16;" :: "r"(dst), "l"(src));
}
__device__ __forceinline__ void cp_commit() {
    asm volatile("cp.async.commit_group;");
}
__device__ __forceinline__ void ldsm4(uint32_t* r, uint32_t a) {
    asm volatile("ldmatrix.sync.aligned.m8n8.x4.shared.b16 {%0,%1,%2,%3}, [%4];"
        : "=r"(r[0]), "=r"(r[1]), "=r"(r[2]), "=r"(r[3]) : "r"(a));
}
__device__ __forceinline__ void ldsm2(uint32_t* r, uint32_t a) {
    asm volatile("ldmatrix.sync.aligned.m8n8.x2.shared.b16 {%0,%1}, [%2];"
        : "=r"(r[0]), "=r"(r[1]) : "r"(a));
}

// ----------------------------------------------------------------------------
// Weight split: float4-vectorized
// ----------------------------------------------------------------------------
__global__ __launch_bounds__(256) void split_kernel(const float* __restrict__ X,
                                                    __nv_bfloat16* __restrict__ H,
                                                    __nv_bfloat16* __restrict__ L,
                                                    int n4) {
    const int gid = blockIdx.x * 256 + threadIdx.x;
    if (gid >= n4) return;
    const float4 v = ((const float4*)X)[gid];
    __nv_bfloat16 h0, h1, h2, h3, l0, l1, l2, l3;
    split1(v.x, h0, l0); split1(v.y, h1, l1);
    split1(v.z, h2, l2); split1(v.w, h3, l3);
    __nv_bfloat162* Hp = (__nv_bfloat162*)H;
    __nv_bfloat162* Lp = (__nv_bfloat162*)L;
    Hp[gid * 2]     = __nv_bfloat162(h0, h1);
    Hp[gid * 2 + 1] = __nv_bfloat162(h2, h3);
    Lp[gid * 2]     = __nv_bfloat162(l0, l1);
    Lp[gid * 2 + 1] = __nv_bfloat162(l2, l3);
}

// ----------------------------------------------------------------------------
// W_fc1 split with row interleave: dst row 2j = src row j (a), 2j+1 = row FFN+j (g)
// ----------------------------------------------------------------------------
__global__ __launch_bounds__(256) void split_ilv_kernel(const float* __restrict__ X,
                                                        __nv_bfloat16* __restrict__ H,
                                                        __nv_bfloat16* __restrict__ L,
                                                        int n4) {
    const int gid = blockIdx.x * 256 + threadIdx.x;
    if (gid >= n4) return;
    const int e0   = gid * 4;
    const int srow = e0 >> 10;
    const int col  = e0 & 1023;
    const int drow = (srow < FFN) ? (srow * 2) : ((srow - FFN) * 2 + 1);
    const float4 v = ((const float4*)X)[gid];
    __nv_bfloat16 h0, h1, h2, h3, l0, l1, l2, l3;
    split1(v.x, h0, l0); split1(v.y, h1, l1);
    split1(v.z, h2, l2); split1(v.w, h3, l3);
    const size_t d4 = ((size_t)drow * DM + col) >> 1;
    __nv_bfloat162* Hp = (__nv_bfloat162*)H;
    __nv_bfloat162* Lp = (__nv_bfloat162*)L;
    Hp[d4]     = __nv_bfloat162(h0, h1);
    Hp[d4 + 1] = __nv_bfloat162(h2, h3);
    Lp[d4]     = __nv_bfloat162(l0, l1);
    Lp[d4 + 1] = __nv_bfloat162(l2, l3);
}

// ----------------------------------------------------------------------------
// LayerNorm with fused hi/lo split output
// ----------------------------------------------------------------------------
__global__ __launch_bounds__(256) void ln_split_kernel(const float* __restrict__ X,
                                                       const float* __restrict__ w,
                                                       __nv_bfloat16* __restrict__ Hh,
                                                       __nv_bfloat16* __restrict__ Hl) {
    const int row = blockIdx.x;
    const int tid = threadIdx.x;
    const float4* xp = (const float4*)(X + (size_t)row * DM);
    float4 v = xp[tid];

    float s  = v.x + v.y + v.z + v.w;
    float sq = v.x * v.x + v.y * v.y + v.z * v.z + v.w * v.w;

    __shared__ float rs[256];
    __shared__ float rq[256];
    rs[tid] = s; rq[tid] = sq;
    __syncthreads();
    #pragma unroll
    for (int o = 128; o >= 1; o >>= 1) {
        if (tid < o) { rs[tid] += rs[tid + o]; rq[tid] += rq[tid + o]; }
        __syncthreads();
    }
    const float mu   = rs[0] * (1.0f / DM);
    const float var  = rq[0] * (1.0f / DM) - mu * mu;
    const float rstd = rsqrtf(var + 1e-5f);

    const float4 wv = ((const float4*)w)[tid];
    float y0 = (v.x - mu) * rstd * wv.x;
    float y1 = (v.y - mu) * rstd * wv.y;
    float y2 = (v.z - mu) * rstd * wv.z;
    float y3 = (v.w - mu) * rstd * wv.w;

    __nv_bfloat16 h0, h1, h2, h3, l0, l1, l2, l3;
    split1(y0, h0, l0); split1(y1, h1, l1);
    split1(y2, h2, l2); split1(y3, h3, l3);
    __nv_bfloat162* Hp = (__nv_bfloat162*)(Hh + (size_t)row * DM);
    __nv_bfloat162* Lp = (__nv_bfloat162*)(Hl + (size_t)row * DM);
    Hp[tid * 2]     = __nv_bfloat162(h0, h1);
    Hp[tid * 2 + 1] = __nv_bfloat162(h2, h3);
    Lp[tid * 2]     = __nv_bfloat162(l0, l1);
    Lp[tid * 2 + 1] = __nv_bfloat162(l2, l3);
}

// ----------------------------------------------------------------------------
// mma.sync m16n8k16 bf16 -> fp32
// ----------------------------------------------------------------------------
__device__ __forceinline__ void mma16816(float* c, const uint32_t* a, const uint32_t* b) {
    asm volatile(
        "mma.sync.aligned.m16n8k16.row.col.f32.bf16.bf16.f32 "
        "{%0,%1,%2,%3},{%4,%5,%6,%7},{%8,%9},{%0,%1,%2,%3};"
        : "+f"(c[0]), "+f"(c[1]), "+f"(c[2]), "+f"(c[3])
        : "r"(a[0]), "r"(a[1]), "r"(a[2]), "r"(a[3]), "r"(b[0]), "r"(b[1]));
}

// ----------------------------------------------------------------------------
// Split-bf16 NT GEMM: 2-stage cp.async pipeline + ldmatrix, 2 CTAs/SM.
// acc = Ah*Bh + Al*Bh + Ah*Bl  (fp32).
// Block tile 128x128x32, 256 threads (8 warps 2x4), warp tile 64x32.
// EPI 0: C = AB   EPI 1: C = R + AB   EPI 2: fused GEGLU (interleaved B rows)
// ----------------------------------------------------------------------------
#define STAGES 2
#define PITCH  40
#define SEGB   (128 * PITCH * 2)   // bytes per stage per array = 10240

template <int EPI>
__global__ __launch_bounds__(256, 2) void gemm_bf16s(const __nv_bfloat16* __restrict__ Ah,
                                                     const __nv_bfloat16* __restrict__ Al,
                                                     const __nv_bfloat16* __restrict__ Bh,
                                                     const __nv_bfloat16* __restrict__ Bl,
                                                     const float* __restrict__ R,
                                                     float* __restrict__ C,
                                                     __nv_bfloat16* __restrict__ Gh,
                                                     __nv_bfloat16* __restrict__ Gl,
                                                     int M, int N, int K) {
    extern __shared__ __nv_bfloat16 smem[];
    const uint32_t sbase = (uint32_t)__cvta_generic_to_shared(smem);

    const int tid  = threadIdx.x;
    const int lane = tid & 31;
    const int warp = tid >> 5;
    const int wm   = warp >> 2;
    const int wn   = warp & 3;

    const int m0 = blockIdx.y * 128;
    const int n0 = blockIdx.x * 128;

    const int r0 = tid >> 2;
    const int r1 = r0 + 64;
    const int c0 = (tid & 3) * 8;

    const size_t aOff0 = (size_t)(m0 + r0) * K + c0;
    const size_t aOff1 = (size_t)(m0 + r1) * K + c0;
    const size_t bOff0 = (size_t)(n0 + r0) * K + c0;
    const size_t bOff1 = (size_t)(n0 + r1) * K + c0;
    const uint32_t d0 = (uint32_t)(r0 * PITCH + c0) * 2;
    const uint32_t d1 = (uint32_t)(r1 * PITCH + c0) * 2;

    const uint32_t aRowB = (uint32_t)(((wm * 64 + (lane & 15)) * PITCH
                                       + ((lane >> 4) << 3)) * 2);
    const uint32_t bRowB = (uint32_t)(((wn * 32 + (lane & 7)) * PITCH
                                       + (((lane >> 3) & 1) << 3)) * 2);

    float acc[4][4][4];
    #pragma unroll
    for (int i = 0; i < 4; i++)
        #pragma unroll
        for (int j = 0; j < 4; j++)
            #pragma unroll
            for (int r = 0; r < 4; r++) acc[i][j][r] = 0.0f;

    const int ntiles = K >> 5;

    auto issue = [&](int st, int t) {
        const int k0 = t * 32;
        const uint32_t sb = sbase + (uint32_t)st * 4 * SEGB;
        cpasync16(sb + 0 * SEGB + d0, Ah + aOff0 + k0);
        cpasync16(sb + 0 * SEGB + d1, Ah + aOff1 + k0);
        cpasync16(sb + 1 * SEGB + d0, Al + aOff0 + k0);
        cpasync16(sb + 1 * SEGB + d1, Al + aOff1 + k0);
        cpasync16(sb + 2 * SEGB + d0, Bh + bOff0 + k0);
        cpasync16(sb + 2 * SEGB + d1, Bh + bOff1 + k0);
        cpasync16(sb + 3 * SEGB + d0, Bl + bOff0 + k0);
        cpasync16(sb + 3 * SEGB + d1, Bl + bOff1 + k0);
        cp_commit();
    };

    // prologue: both stages in flight
    issue(0, 0);
    if (ntiles > 1) issue(1, 1);

    for (int t = 0; t < ntiles; t++) {
        const int st = t & 1;
        if (t + 1 < ntiles) {
            asm volatile("cp.async.wait_group 1;");
        } else {
            asm volatile("cp.async.wait_group 0;");
        }
        __syncthreads();

        const uint32_t sb  = sbase + (uint32_t)st * 4 * SEGB;
        const uint32_t pAh = sb;
        const uint32_t pAl = sb + 1 * SEGB;
        const uint32_t pBh = sb + 2 * SEGB;
        const uint32_t pBl = sb + 3 * SEGB;

        #pragma unroll
        for (int kc = 0; kc < 2; kc++) {
            const uint32_t kb = (uint32_t)kc * 32;
            uint32_t ah[4][4], al[4][4], bh[4][2], bl[4][2];
            #pragma unroll
            for (int i = 0; i < 4; i++) {
                const uint32_t ao = aRowB + (uint32_t)i * (16 * PITCH * 2) + kb;
                ldsm4(ah[i], pAh + ao);
                ldsm4(al[i], pAl + ao);
            }
            #pragma unroll
            for (int j = 0; j < 4; j++) {
                const uint32_t bo = bRowB + (uint32_t)j * (8 * PITCH * 2) + kb;
                ldsm2(bh[j], pBh + bo);
                ldsm2(bl[j], pBl + bo);
            }
            #pragma unroll
            for (int i = 0; i < 4; i++)
                #pragma unroll
                for (int j = 0; j < 4; j++)
                    mma16816(acc[i][j], ah[i], bh[j]);
            #pragma unroll
            for (int i = 0; i < 4; i++)
                #pragma unroll
                for (int j = 0; j < 4; j++)
                    mma16816(acc[i][j], al[i], bh[j]);
            #pragma unroll
            for (int i = 0; i < 4; i++)
                #pragma unroll
                for (int j = 0; j < 4; j++)
                    mma16816(acc[i][j], ah[i], bl[j]);
        }

        if (t + 2 < ntiles) {
            __syncthreads();              // all reads of stage st complete
            issue(st, t + 2);             // refill st; overlaps compute of t+1
        }
    }

    // epilogue
    const int g = lane >> 2;
    #pragma unroll
    for (int i = 0; i < 4; i++) {
        const int row = m0 + wm * 64 + i * 16 + g;
        #pragma unroll
        for (int j = 0; j < 4; j++) {
            const int col = n0 + wn * 32 + j * 8 + (lane & 3) * 2;
            if (EPI == 2) {
                const int oc = col >> 1;
                const float v0 = geglu1(acc[i][j][0], acc[i][j][1]);
                const float v1 = geglu1(acc[i][j][2], acc[i][j][3]);
                __nv_bfloat16 h0, l0, h1, l1;
                split1(v0, h0, l0);
                split1(v1, h1, l1);
                const size_t o0 = (size_t)row * (N >> 1) + oc;
                const size_t o1 = (size_t)(row + 8) * (N >> 1) + oc;
                Gh[o0] = h0; Gl[o0] = l0;
                Gh[o1] = h1; Gl[o1] = l1;
            } else {
                const size_t o0 = (size_t)row * N + col;
                const size_t o1 = (size_t)(row + 8) * N + col;
                float2 v0 = {acc[i][j][0], acc[i][j][1]};
                float2 v1 = {acc[i][j][2], acc[i][j][3]};
                if (EPI == 1) {
                    const float2 r0v = *(const float2*)(R + o0);
                    const float2 r1v = *(const float2*)(R + o1);
                    v0.x += r0v.x; v0.y += r0v.y;
                    v1.x += r1v.x; v1.y += r1v.y;
                }
                *(float2*)(C + o0) = v0;
                *(float2*)(C + o1) = v1;
            }
        }
    }
}

// ----------------------------------------------------------------------------
// De-interleave qkv -> split bf16 Q/K ([b,h,s,d], Q pre-scaled 1/8), V^T.
// ----------------------------------------------------------------------------
__global__ __launch_bounds__(256) void reshape_split(const float* __restrict__ qkv,
                                                     __nv_bfloat16* __restrict__ Qh,
                                                     __nv_bfloat16* __restrict__ Ql,
                                                     __nv_bfloat16* __restrict__ Kh,
                                                     __nv_bfloat16* __restrict__ Kl,
                                                     __nv_bfloat16* __restrict__ Vth,
                                                     __nv_bfloat16* __restrict__ Vtl) {
    const size_t gid = (size_t)blockIdx.x * 256 + threadIdx.x;
    const int t = (int)(gid >> 10);
    const int r = (int)(gid & 1023);
    const int h = r >> 6;
    const int d = r & 63;
    const int b = t >> 11;
    const int s = t & 2047;
    const float* src = qkv + (size_t)t * QKV3 + h * (DH * 3) + d * 3;
    const float qv = src[0] * 0.125f;
    const float kv = src[1];
    const float vv = src[2];
    const size_t qk = (((size_t)(b * NH + h)) * S + s) * DH + d;
    const size_t vt = (((size_t)(b * NH + h)) * DH + d) * S + s;
    __nv_bfloat16 hh, ll;
    split1(qv, hh, ll); Qh[qk] = hh; Ql[qk] = ll;
    split1(kv, hh, ll); Kh[qk] = hh; Kl[qk] = ll;
    split1(vv, hh, ll); Vth[vt] = hh; Vtl[vt] = ll;
}

// ----------------------------------------------------------------------------
// Tensor-core flash attention (unchanged, validated)
// ----------------------------------------------------------------------------
#define FP   72
#define FSEG (64 * FP)

__global__ __launch_bounds__(256) void flash_mma(const __nv_bfloat16* __restrict__ Qh,
                                                 const __nv_bfloat16* __restrict__ Ql,
                                                 const __nv_bfloat16* __restrict__ Kh,
                                                 const __nv_bfloat16* __restrict__ Kl,
                                                 const __nv_bfloat16* __restrict__ Vth,
                                                 const __nv_bfloat16* __restrict__ Vtl,
                                                 __nv_bfloat16* __restrict__ Oh,
                                                 __nv_bfloat16* __restrict__ Ol) {
    __shared__ __nv_bfloat16 sKh[FSEG], sKl[FSEG], sVh[FSEG], sVl[FSEG];

    const int tid  = threadIdx.x;
    const int lane = tid & 31;
    const int w    = tid >> 5;
    const int h    = blockIdx.y;
    const int b    = blockIdx.z;
    const int q0   = blockIdx.x * 128;
    const size_t bh  = (size_t)(b * NH + h) * S;
    const size_t bhd = (size_t)(b * NH + h) * DH;
    const int g  = lane >> 2;
    const int kq = (lane & 3) * 2;

    uint32_t qfh[4][4], qfl[4][4];
    {
        const int row = q0 + w * 16 + g;
        const __nv_bfloat16* b0h = Qh + (bh + row) * DH;
        const __nv_bfloat16* b8h = Qh + (bh + row + 8) * DH;
        const __nv_bfloat16* b0l = Ql + (bh + row) * DH;
        const __nv_bfloat16* b8l = Ql + (bh + row + 8) * DH;
        #pragma unroll
        for (int kc = 0; kc < 4; kc++) {
            const int o = kc * 16 + kq;
            qfh[kc][0] = *(const uint32_t*)(b0h + o);
            qfh[kc][1] = *(const uint32_t*)(b8h + o);
            qfh[kc][2] = *(const uint32_t*)(b0h + o + 8);
            qfh[kc][3] = *(const uint32_t*)(b8h + o + 8);
            qfl[kc][0] = *(const uint32_t*)(b0l + o);
            qfl[kc][1] = *(const uint32_t*)(b8l + o);
            qfl[kc][2] = *(const uint32_t*)(b0l + o + 8);
            qfl[kc][3] = *(const uint32_t*)(b8l + o + 8);
        }
    }

    float o[8][4];
    #pragma unroll
    for (int j = 0; j < 8; j++)
        #pragma unroll
        for (int r = 0; r < 4; r++) o[j][r] = 0.0f;
    float m0 = -INFINITY, m1 = -INFINITY;
    float l0 = 0.0f, l1 = 0.0f;

    const int i0 = tid, i1 = tid + 256;
    const int lr0 = i0 >> 3, lc0 = (i0 & 7) * 8;
    const int lr1 = i1 >> 3, lc1 = (i1 & 7) * 8;

    for (int kt = 0; kt < S; kt += 64) {
        __syncthreads();
        *(uint4*)(sKh + lr0 * FP + lc0) = *(const uint4*)(Kh + (bh + kt + lr0) * DH + lc0);
        *(uint4*)(sKh + lr1 * FP + lc1) = *(const uint4*)(Kh + (bh + kt + lr1) * DH + lc1);
        *(uint4*)(sKl + lr0 * FP + lc0) = *(const uint4*)(Kl + (bh + kt + lr0) * DH + lc0);
        *(uint4*)(sKl + lr1 * FP + lc1) = *(const uint4*)(Kl + (bh + kt + lr1) * DH + lc1);
        *(uint4*)(sVh + lr0 * FP + lc0) = *(const uint4*)(Vth + (bhd + lr0) * S + kt + lc0);
        *(uint4*)(sVh + lr1 * FP + lc1) = *(const uint4*)(Vth + (bhd + lr1) * S + kt + lc1);
        *(uint4*)(sVl + lr0 * FP + lc0) = *(const uint4*)(Vtl + (bhd + lr0) * S + kt + lc0);
        *(uint4*)(sVl + lr1 * FP + lc1) = *(const uint4*)(Vtl + (bhd + lr1) * S + kt + lc1);
        __syncthreads();

        float sc[8][4];
        #pragma unroll
        for (int j = 0; j < 8; j++)
            #pragma unroll
            for (int r = 0; r < 4; r++) sc[j][r] = 0.0f;

        #pragma unroll
        for (int kc = 0; kc < 4; kc++) {
            #pragma unroll
            for (int j = 0; j < 8; j++) {
                const int off = (j * 8 + g) * FP + kc * 16 + kq;
                uint32_t kb[2], klo[2];
                kb[0]  = *(const uint32_t*)(sKh + off);
                kb[1]  = *(const uint32_t*)(sKh + off + 8);
                klo[0] = *(const uint32_t*)(sKl + off);
                klo[1] = *(const uint32_t*)(sKl + off + 8);
                mma16816(sc[j], qfh[kc], kb);
                mma16816(sc[j], qfl[kc], kb);
                mma16816(sc[j], qfh[kc], klo);
            }
        }

        float mx0 = sc[0][0], mx1 = sc[0][2];
        #pragma unroll
        for (int j = 0; j < 8; j++) {
            mx0 = fmaxf(mx0, fmaxf(sc[j][0], sc[j][1]));
            mx1 = fmaxf(mx1, fmaxf(sc[j][2], sc[j][3]));
        }
        mx0 = fmaxf(mx0, __shfl_xor_sync(0xffffffffu, mx0, 1));
        mx0 = fmaxf(mx0, __shfl_xor_sync(0xffffffffu, mx0, 2));
        mx1 = fmaxf(mx1, __shfl_xor_sync(0xffffffffu, mx1, 1));
        mx1 = fmaxf(mx1, __shfl_xor_sync(0xffffffffu, mx1, 2));

        const float mn0 = fmaxf(m0, mx0);
        const float mn1 = fmaxf(m1, mx1);
        const float c0 = fexp(m0 - mn0);
        const float c1 = fexp(m1 - mn1);
        m0 = mn0; m1 = mn1;

        float s0 = 0.0f, s1 = 0.0f;
        #pragma unroll
        for (int j = 0; j < 8; j++) {
            sc[j][0] = fexp(sc[j][0] - mn0);
            sc[j][1] = fexp(sc[j][1] - mn0);
            sc[j][2] = fexp(sc[j][2] - mn1);
            sc[j][3] = fexp(sc[j][3] - mn1);
            s0 += sc[j][0] + sc[j][1];
            s1 += sc[j][2] + sc[j][3];
        }
        s0 += __shfl_xor_sync(0xffffffffu, s0, 1);
        s0 += __shfl_xor_sync(0xffffffffu, s0, 2);
        s1 += __shfl_xor_sync(0xffffffffu, s1, 1);
        s1 += __shfl_xor_sync(0xffffffffu, s1, 2);
        l0 = l0 * c0 + s0;
        l1 = l1 * c1 + s1;

        #pragma unroll
        for (int j = 0; j < 8; j++) {
            o[j][0] *= c0; o[j][1] *= c0;
            o[j][2] *= c1; o[j][3] *= c1;
        }

        #pragma unroll
        for (int t2 = 0; t2 < 4; t2++) {
            uint32_t ph[4], pl[4];
            {
                const float* e = sc[2 * t2];
                const float* f = sc[2 * t2 + 1];
                __nv_bfloat16 hv[8], lv[8];
                split1(e[0], hv[0], lv[0]); split1(e[1], hv[1], lv[1]);
                split1(e[2], hv[2], lv[2]); split1(e[3], hv[3], lv[3]);
                split1(f[0], hv[4], lv[4]); split1(f[1], hv[5], lv[5]);
                split1(f[2], hv[6], lv[6]); split1(f[3], hv[7], lv[7]);
                __nv_bfloat162 t0 = __nv_bfloat162(hv[0], hv[1]);
                __nv_bfloat162 t1 = __nv_bfloat162(hv[2], hv[3]);
                __nv_bfloat162 t2v = __nv_bfloat162(hv[4], hv[5]);
                __nv_bfloat162 t3 = __nv_bfloat162(hv[6], hv[7]);
                ph[0] = *(uint32_t*)&t0; ph[1] = *(uint32_t*)&t1;
                ph[2] = *(uint32_t*)&t2v; ph[3] = *(uint32_t*)&t3;
                t0 = __nv_bfloat162(lv[0], lv[1]);
                t1 = __nv_bfloat162(lv[2], lv[3]);
                t2v = __nv_bfloat162(lv[4], lv[5]);
                t3 = __nv_bfloat162(lv[6], lv[7]);
                pl[0] = *(uint32_t*)&t0; pl[1] = *(uint32_t*)&t1;
                pl[2] = *(uint32_t*)&t2v; pl[3] = *(uint32_t*)&t3;
            }
            #pragma unroll
            for (int j = 0; j < 8; j++) {
                const int off = (j * 8 + g) * FP + t2 * 16 + kq;
                uint32_t vh[2], vl[2];
                vh[0] = *(const uint32_t*)(sVh + off);
                vh[1] = *(const uint32_t*)(sVh + off + 8);
                vl[0] = *(const uint32_t*)(sVl + off);
                vl[1] = *(const uint32_t*)(sVl + off + 8);
                mma16816(o[j], ph, vh);
                mma16816(o[j], pl, vh);
                mma16816(o[j], ph, vl);
            }
        }
    }

    const float inv0 = 1.0f / l0;
    const float inv1 = 1.0f / l1;
    const int row = q0 + w * 16 + g;
    const size_t t0 = (size_t)(b * S + row);
    const size_t t8 = t0 + 8;
    #pragma unroll
    for (int j = 0; j < 8; j++) {
        const int col = h * DH + j * 8 + kq;
        float v0 = o[j][0] * inv0, v1 = o[j][1] * inv0;
        float v2 = o[j][2] * inv1, v3 = o[j][3] * inv1;
        __nv_bfloat16 h0, h1, h2, h3, l0b, l1b, l2b, l3b;
        split1(v0, h0, l0b); split1(v1, h1, l1b);
        split1(v2, h2, l2b); split1(v3, h3, l3b);
        *(__nv_bfloat162*)(Oh + t0 * DM + col) = __nv_bfloat162(h0, h1);
        *(__nv_bfloat162*)(Ol + t0 * DM + col) = __nv_bfloat162(l0b, l1b);
        *(__nv_bfloat162*)(Oh + t8 * DM + col) = __nv_bfloat162(h2, h3);
        *(__nv_bfloat162*)(Ol + t8 * DM + col) = __nv_bfloat162(l2b, l3b);
    }
}

// ----------------------------------------------------------------------------
// Launch
// ----------------------------------------------------------------------------
extern "C" void kernel_launch(void* const* d_in, const int* in_sizes, int n_in,
                              void* d_out, int out_size) {
    const float* X     = (const float*)d_in[0];
    const float* W_qkv = (const float*)d_in[1];
    const float* W_o   = (const float*)d_in[2];
    const float* W_fc1 = (const float*)d_in[3];
    const float* W_fc2 = (const float*)d_in[4];
    const float* ln1_w = (const float*)d_in[5];
    const float* ln2_w = (const float*)d_in[6];
    float* out = (float*)d_out;

    float *p_qkv, *p_X1;
    __nv_bfloat16 *p_Xnh, *p_Xnl, *p_atth, *p_attl, *p_hh, *p_hl;
    __nv_bfloat16 *p_Wqh, *p_Wql, *p_Woh, *p_Wol, *p_Wf1h, *p_Wf1l, *p_Wf2h, *p_Wf2l;
    __nv_bfloat16 *p_Qh, *p_Ql, *p_Kh, *p_Kl, *p_Vth, *p_Vtl;
    cudaGetSymbolAddress((void**)&p_qkv, g_qkv);
    cudaGetSymbolAddress((void**)&p_X1,  g_X1);
    cudaGetSymbolAddress((void**)&p_Xnh,  g_Xnh);
    cudaGetSymbolAddress((void**)&p_Xnl,  g_Xnl);
    cudaGetSymbolAddress((void**)&p_atth, g_atth);
    cudaGetSymbolAddress((void**)&p_attl, g_attl);
    cudaGetSymbolAddress((void**)&p_hh,   g_hh);
    cudaGetSymbolAddress((void**)&p_hl,   g_hl);
    cudaGetSymbolAddress((void**)&p_Wqh,  g_Wqh);
    cudaGetSymbolAddress((void**)&p_Wql,  g_Wql);
    cudaGetSymbolAddress((void**)&p_Woh,  g_Woh);
    cudaGetSymbolAddress((void**)&p_Wol,  g_Wol);
    cudaGetSymbolAddress((void**)&p_Wf1h, g_Wf1h);
    cudaGetSymbolAddress((void**)&p_Wf1l, g_Wf1l);
    cudaGetSymbolAddress((void**)&p_Wf2h, g_Wf2h);
    cudaGetSymbolAddress((void**)&p_Wf2l, g_Wf2l);
    cudaGetSymbolAddress((void**)&p_Qh,  g_Qh);
    cudaGetSymbolAddress((void**)&p_Ql,  g_Ql);
    cudaGetSymbolAddress((void**)&p_Kh,  g_Kh);
    cudaGetSymbolAddress((void**)&p_Kl,  g_Kl);
    cudaGetSymbolAddress((void**)&p_Vth, g_Vth);
    cudaGetSymbolAddress((void**)&p_Vtl, g_Vtl);

    const int smemBytes = STAGES * 4 * SEGB; // 81920 -> 2 CTAs/SM
    cudaFuncSetAttribute(gemm_bf16s<0>, cudaFuncAttributeMaxDynamicSharedMemorySize, smemBytes);
    cudaFuncSetAttribute(gemm_bf16s<1>, cudaFuncAttributeMaxDynamicSharedMemorySize, smemBytes);
    cudaFuncSetAttribute(gemm_bf16s<2>, cudaFuncAttributeMaxDynamicSharedMemorySize, smemBytes);

    // weight splits (fc1 interleaved for fused GEGLU)
    split_kernel<<<(QKV3 * DM / 4 + 255) / 256, 256>>>(W_qkv, p_Wqh, p_Wql, QKV3 * DM / 4);
    split_kernel<<<(DM * DM / 4 + 255) / 256, 256>>>(W_o, p_Woh, p_Wol, DM * DM / 4);
    split_ilv_kernel<<<(FFN2 * DM / 4 + 255) / 256, 256>>>(W_fc1, p_Wf1h, p_Wf1l, FFN2 * DM / 4);
    split_kernel<<<(DM * FFN / 4 + 255) / 256, 256>>>(W_fc2, p_Wf2h, p_Wf2l, DM * FFN / 4);

    // 1. LN1
    ln_split_kernel<<<T, 256>>>(X, ln1_w, p_Xnh, p_Xnl);
    // 2. qkv = Xn @ W_qkv^T
    gemm_bf16s<0><<<dim3(QKV3 / 128, T / 128), 256, smemBytes>>>(
        p_Xnh, p_Xnl, p_Wqh, p_Wql, nullptr, p_qkv, nullptr, nullptr, T, QKV3, DM);
    // 3. de-interleave + split
    reshape_split<<<(T * DM) / 256, 256>>>(p_qkv, p_Qh, p_Ql, p_Kh, p_Kl, p_Vth, p_Vtl);
    // 4. attention
    flash_mma<<<dim3(S / 128, NH, B), 256>>>(p_Qh, p_Ql, p_Kh, p_Kl, p_Vth, p_Vtl,
                                             p_atth, p_attl);
    // 5. X1 = X + attn @ W_o^T
    gemm_bf16s<1><<<dim3(DM / 128, T / 128), 256, smemBytes>>>(
        p_atth, p_attl, p_Woh, p_Wol, X, p_X1, nullptr, nullptr, T, DM, DM);
    // 6. LN2
    ln_split_kernel<<<T, 256>>>(p_X1, ln2_w, p_Xnh, p_Xnl);
    // 7+8. h = geglu(Xn @ W_fc1_interleaved^T)  — fused epilogue, split output
    gemm_bf16s<2><<<dim3(FFN2 / 128, T / 128), 256, smemBytes>>>(
        p_Xnh, p_Xnl, p_Wf1h, p_Wf1l, nullptr, nullptr, p_hh, p_hl, T, FFN2, DM);
    // 9. out = X1 + h @ W_fc2^T
    gemm_bf16s<1><<<dim3(DM / 128, T / 128), 256, smemBytes>>>(
        p_hh, p_hl, p_Wf2h, p_Wf2l, p_X1, out, nullptr, nullptr, T, DM, FFN);
}

// round 13
// speedup vs baseline: 2.5782x; 1.0055x over previous
#include <cuda_runtime.h>
#include <cuda_bf16.h>
#include <math.h>
#include <stdint.h>

// ----------------------------------------------------------------------------
// Problem constants
// ----------------------------------------------------------------------------
#define B        4
#define S        2048
#define T        (B * S)          // 8192 tokens
#define DM       1024             // d_model
#define NH       16               // heads
#define DH       64               // head dim
#define QKV3     (3 * NH * DH)    // 3072
#define FFN      4096
#define FFN2     (2 * FFN)        // 8192

// ----------------------------------------------------------------------------
// Scratch (device globals -> no allocation inside kernel_launch)
// ----------------------------------------------------------------------------
__device__ float g_X1  [(size_t)T * DM];    // X + attn @ Wo^T

// bf16 hi/lo split operands
__device__ __nv_bfloat16 g_Xnh [(size_t)T * DM];
__device__ __nv_bfloat16 g_Xnl [(size_t)T * DM];
__device__ __nv_bfloat16 g_atth[(size_t)T * DM];
__device__ __nv_bfloat16 g_attl[(size_t)T * DM];
__device__ __nv_bfloat16 g_hh  [(size_t)T * FFN];
__device__ __nv_bfloat16 g_hl  [(size_t)T * FFN];
__device__ __nv_bfloat16 g_Wqh [(size_t)QKV3 * DM];
__device__ __nv_bfloat16 g_Wql [(size_t)QKV3 * DM];
__device__ __nv_bfloat16 g_Woh [(size_t)DM * DM];
__device__ __nv_bfloat16 g_Wol [(size_t)DM * DM];
__device__ __nv_bfloat16 g_Wf1h[(size_t)FFN2 * DM];   // row-interleaved (a0,g0,a1,g1,...)
__device__ __nv_bfloat16 g_Wf1l[(size_t)FFN2 * DM];
__device__ __nv_bfloat16 g_Wf2h[(size_t)DM * FFN];
__device__ __nv_bfloat16 g_Wf2l[(size_t)DM * FFN];
// attention operands (bf16 hi/lo)
__device__ __nv_bfloat16 g_Qh [(size_t)T * DM];   // [b,h,s,d]  (pre-scaled 1/8)
__device__ __nv_bfloat16 g_Ql [(size_t)T * DM];
__device__ __nv_bfloat16 g_Kh [(size_t)T * DM];   // [b,h,s,d]
__device__ __nv_bfloat16 g_Kl [(size_t)T * DM];
__device__ __nv_bfloat16 g_Vth[(size_t)T * DM];   // [b,h,d,s]  (transposed)
__device__ __nv_bfloat16 g_Vtl[(size_t)T * DM];

// ----------------------------------------------------------------------------
// fp32 -> (hi, lo) bf16 split
// ----------------------------------------------------------------------------
__device__ __forceinline__ void split1(float x, __nv_bfloat16& h, __nv_bfloat16& l) {
    h = __float2bfloat16_rn(x);
    l = __float2bfloat16_rn(x - __bfloat162float(h));
}

// ----------------------------------------------------------------------------
// Fast exp on FMA pipe (no MUFU). rel err < 3e-8 on clamped range.
// ----------------------------------------------------------------------------
__device__ __forceinline__ float fexp(float x) {
    x = fminf(fmaxf(x, -87.0f), 87.0f);
    const float y = x * 1.4426950408889634f;          // log2(e)
    const float z = y + 12582912.0f;                  // 1.5 * 2^23
    const int   n = __float_as_int(z) - 0x4B400000;   // round-to-nearest int
    const float f = y - (z - 12582912.0f);            // f in [-0.5, 0.5]
    float p = 1.5403530393381609e-4f;
    p = fmaf(p, f, 1.3333558146428443e-3f);
    p = fmaf(p, f, 9.6181291076284772e-3f);
    p = fmaf(p, f, 5.5504108664821580e-2f);
    p = fmaf(p, f, 2.4022650695910072e-1f);
    p = fmaf(p, f, 6.9314718055994531e-1f);
    p = fmaf(p, f, 1.0f);
    return __int_as_float(__float_as_int(p) + (n << 23));
}

__device__ __forceinline__ float frcp(float x) {
    float r;
    asm("rcp.approx.f32 %0, %1;" : "=f"(r) : "f"(x));
    return r;
}

// GEGLU scalar: a * g * sigmoid(2 * 0.79788456*(g + 0.044715 g^3))
__device__ __forceinline__ float geglu1(float a, float g) {
    const float z = 0.7978845608028654f * (g + 0.044715f * g * g * g);
    const float ew = fexp(-2.0f * z);
    return a * g * frcp(1.0f + ew);
}

// ----------------------------------------------------------------------------
// Async copy + ldmatrix helpers
// ----------------------------------------------------------------------------
__device__ __forceinline__ void cpasync16(uint32_t dst, const void* src) {
    asm volatile("cp.async.cg.shared.global [%0], [%1], 16;" :: "r"(dst), "l"(src));
}
__device__ __forceinline__ void cp_commit() {
    asm volatile("cp.async.commit_group;");
}
__device__ __forceinline__ void ldsm4(uint32_t* r, uint32_t a) {
    asm volatile("ldmatrix.sync.aligned.m8n8.x4.shared.b16 {%0,%1,%2,%3}, [%4];"
        : "=r"(r[0]), "=r"(r[1]), "=r"(r[2]), "=r"(r[3]) : "r"(a));
}
__device__ __forceinline__ void ldsm2(uint32_t* r, uint32_t a) {
    asm volatile("ldmatrix.sync.aligned.m8n8.x2.shared.b16 {%0,%1}, [%2];"
        : "=r"(r[0]), "=r"(r[1]) : "r"(a));
}

// ----------------------------------------------------------------------------
// qkv epilogue scatter: col in [0,3072) -> (head, dim, {q,k,v})
// Same index math as the validated reshape_split kernel.
// ----------------------------------------------------------------------------
__device__ __forceinline__ void scatter_qkv(int t, int cc, float v,
                                            __nv_bfloat16* __restrict__ Qh,
                                            __nv_bfloat16* __restrict__ Ql,
                                            __nv_bfloat16* __restrict__ Kh,
                                            __nv_bfloat16* __restrict__ Kl,
                                            __nv_bfloat16* __restrict__ Vth,
                                            __nv_bfloat16* __restrict__ Vtl) {
    const int h   = cc / 192;
    const int rem = cc - h * 192;
    const int d   = rem / 3;
    const int c   = rem - d * 3;
    const int b   = t >> 11;
    const int s   = t & 2047;
    __nv_bfloat16 hh, ll;
    if (c == 0) {
        split1(v * 0.125f, hh, ll);
        const size_t qk = (((size_t)(b * NH + h)) * S + s) * DH + d;
        Qh[qk] = hh; Ql[qk] = ll;
    } else if (c == 1) {
        split1(v, hh, ll);
        const size_t qk = (((size_t)(b * NH + h)) * S + s) * DH + d;
        Kh[qk] = hh; Kl[qk] = ll;
    } else {
        split1(v, hh, ll);
        const size_t vt = (((size_t)(b * NH + h)) * DH + d) * S + s;
        Vth[vt] = hh; Vtl[vt] = ll;
    }
}

// ----------------------------------------------------------------------------
// Weight split: float4-vectorized
// ----------------------------------------------------------------------------
__global__ __launch_bounds__(256) void split_kernel(const float* __restrict__ X,
                                                    __nv_bfloat16* __restrict__ H,
                                                    __nv_bfloat16* __restrict__ L,
                                                    int n4) {
    const int gid = blockIdx.x * 256 + threadIdx.x;
    if (gid >= n4) return;
    const float4 v = ((const float4*)X)[gid];
    __nv_bfloat16 h0, h1, h2, h3, l0, l1, l2, l3;
    split1(v.x, h0, l0); split1(v.y, h1, l1);
    split1(v.z, h2, l2); split1(v.w, h3, l3);
    __nv_bfloat162* Hp = (__nv_bfloat162*)H;
    __nv_bfloat162* Lp = (__nv_bfloat162*)L;
    Hp[gid * 2]     = __nv_bfloat162(h0, h1);
    Hp[gid * 2 + 1] = __nv_bfloat162(h2, h3);
    Lp[gid * 2]     = __nv_bfloat162(l0, l1);
    Lp[gid * 2 + 1] = __nv_bfloat162(l2, l3);
}

// ----------------------------------------------------------------------------
// W_fc1 split with row interleave: dst row 2j = src row j (a), 2j+1 = row FFN+j (g)
// ----------------------------------------------------------------------------
__global__ __launch_bounds__(256) void split_ilv_kernel(const float* __restrict__ X,
                                                        __nv_bfloat16* __restrict__ H,
                                                        __nv_bfloat16* __restrict__ L,
                                                        int n4) {
    const int gid = blockIdx.x * 256 + threadIdx.x;
    if (gid >= n4) return;
    const int e0   = gid * 4;
    const int srow = e0 >> 10;
    const int col  = e0 & 1023;
    const int drow = (srow < FFN) ? (srow * 2) : ((srow - FFN) * 2 + 1);
    const float4 v = ((const float4*)X)[gid];
    __nv_bfloat16 h0, h1, h2, h3, l0, l1, l2, l3;
    split1(v.x, h0, l0); split1(v.y, h1, l1);
    split1(v.z, h2, l2); split1(v.w, h3, l3);
    const size_t d4 = ((size_t)drow * DM + col) >> 1;
    __nv_bfloat162* Hp = (__nv_bfloat162*)H;
    __nv_bfloat162* Lp = (__nv_bfloat162*)L;
    Hp[d4]     = __nv_bfloat162(h0, h1);
    Hp[d4 + 1] = __nv_bfloat162(h2, h3);
    Lp[d4]     = __nv_bfloat162(l0, l1);
    Lp[d4 + 1] = __nv_bfloat162(l2, l3);
}

// ----------------------------------------------------------------------------
// LayerNorm with fused hi/lo split output
// ----------------------------------------------------------------------------
__global__ __launch_bounds__(256) void ln_split_kernel(const float* __restrict__ X,
                                                       const float* __restrict__ w,
                                                       __nv_bfloat16* __restrict__ Hh,
                                                       __nv_bfloat16* __restrict__ Hl) {
    const int row = blockIdx.x;
    const int tid = threadIdx.x;
    const float4* xp = (const float4*)(X + (size_t)row * DM);
    float4 v = xp[tid];

    float s  = v.x + v.y + v.z + v.w;
    float sq = v.x * v.x + v.y * v.y + v.z * v.z + v.w * v.w;

    __shared__ float rs[256];
    __shared__ float rq[256];
    rs[tid] = s; rq[tid] = sq;
    __syncthreads();
    #pragma unroll
    for (int o = 128; o >= 1; o >>= 1) {
        if (tid < o) { rs[tid] += rs[tid + o]; rq[tid] += rq[tid + o]; }
        __syncthreads();
    }
    const float mu   = rs[0] * (1.0f / DM);
    const float var  = rq[0] * (1.0f / DM) - mu * mu;
    const float rstd = rsqrtf(var + 1e-5f);

    const float4 wv = ((const float4*)w)[tid];
    float y0 = (v.x - mu) * rstd * wv.x;
    float y1 = (v.y - mu) * rstd * wv.y;
    float y2 = (v.z - mu) * rstd * wv.z;
    float y3 = (v.w - mu) * rstd * wv.w;

    __nv_bfloat16 h0, h1, h2, h3, l0, l1, l2, l3;
    split1(y0, h0, l0); split1(y1, h1, l1);
    split1(y2, h2, l2); split1(y3, h3, l3);
    __nv_bfloat162* Hp = (__nv_bfloat162*)(Hh + (size_t)row * DM);
    __nv_bfloat162* Lp = (__nv_bfloat162*)(Hl + (size_t)row * DM);
    Hp[tid * 2]     = __nv_bfloat162(h0, h1);
    Hp[tid * 2 + 1] = __nv_bfloat162(h2, h3);
    Lp[tid * 2]     = __nv_bfloat162(l0, l1);
    Lp[tid * 2 + 1] = __nv_bfloat162(l2, l3);
}

// ----------------------------------------------------------------------------
// mma.sync m16n8k16 bf16 -> fp32
// ----------------------------------------------------------------------------
__device__ __forceinline__ void mma16816(float* c, const uint32_t* a, const uint32_t* b) {
    asm volatile(
        "mma.sync.aligned.m16n8k16.row.col.f32.bf16.bf16.f32 "
        "{%0,%1,%2,%3},{%4,%5,%6,%7},{%8,%9},{%0,%1,%2,%3};"
        : "+f"(c[0]), "+f"(c[1]), "+f"(c[2]), "+f"(c[3])
        : "r"(a[0]), "r"(a[1]), "r"(a[2]), "r"(a[3]), "r"(b[0]), "r"(b[1]));
}

// ----------------------------------------------------------------------------
// Split-bf16 NT GEMM: 2-stage cp.async pipeline + ldmatrix, 2 CTAs/SM.
// acc = Ah*Bh + Al*Bh + Ah*Bl  (fp32).
// Block tile 128x128x32, 256 threads (8 warps 2x4), warp tile 64x32.
// EPI 0: C = AB   EPI 1: C = R + AB   EPI 2: fused GEGLU
// EPI 3: fused qkv reshape/split (scatter to Q/K/V^T hi/lo)
// ----------------------------------------------------------------------------
#define STAGES 2
#define PITCH  40
#define SEGB   (128 * PITCH * 2)   // bytes per stage per array = 10240

template <int EPI>
__global__ __launch_bounds__(256, 2) void gemm_bf16s(const __nv_bfloat16* __restrict__ Ah,
                                                     const __nv_bfloat16* __restrict__ Al,
                                                     const __nv_bfloat16* __restrict__ Bh,
                                                     const __nv_bfloat16* __restrict__ Bl,
                                                     const float* __restrict__ R,
                                                     float* __restrict__ C,
                                                     __nv_bfloat16* __restrict__ P0,
                                                     __nv_bfloat16* __restrict__ P1,
                                                     __nv_bfloat16* __restrict__ P2,
                                                     __nv_bfloat16* __restrict__ P3,
                                                     __nv_bfloat16* __restrict__ P4,
                                                     __nv_bfloat16* __restrict__ P5,
                                                     int M, int N, int K) {
    extern __shared__ __nv_bfloat16 smem[];
    const uint32_t sbase = (uint32_t)__cvta_generic_to_shared(smem);

    const int tid  = threadIdx.x;
    const int lane = tid & 31;
    const int warp = tid >> 5;
    const int wm   = warp >> 2;
    const int wn   = warp & 3;

    const int m0 = blockIdx.y * 128;
    const int n0 = blockIdx.x * 128;

    const int r0 = tid >> 2;
    const int r1 = r0 + 64;
    const int c0 = (tid & 3) * 8;

    const size_t aOff0 = (size_t)(m0 + r0) * K + c0;
    const size_t aOff1 = (size_t)(m0 + r1) * K + c0;
    const size_t bOff0 = (size_t)(n0 + r0) * K + c0;
    const size_t bOff1 = (size_t)(n0 + r1) * K + c0;
    const uint32_t d0 = (uint32_t)(r0 * PITCH + c0) * 2;
    const uint32_t d1 = (uint32_t)(r1 * PITCH + c0) * 2;

    const uint32_t aRowB = (uint32_t)(((wm * 64 + (lane & 15)) * PITCH
                                       + ((lane >> 4) << 3)) * 2);
    const uint32_t bRowB = (uint32_t)(((wn * 32 + (lane & 7)) * PITCH
                                       + (((lane >> 3) & 1) << 3)) * 2);

    float acc[4][4][4];
    #pragma unroll
    for (int i = 0; i < 4; i++)
        #pragma unroll
        for (int j = 0; j < 4; j++)
            #pragma unroll
            for (int r = 0; r < 4; r++) acc[i][j][r] = 0.0f;

    const int ntiles = K >> 5;

    auto issue = [&](int st, int t) {
        const int k0 = t * 32;
        const uint32_t sb = sbase + (uint32_t)st * 4 * SEGB;
        cpasync16(sb + 0 * SEGB + d0, Ah + aOff0 + k0);
        cpasync16(sb + 0 * SEGB + d1, Ah + aOff1 + k0);
        cpasync16(sb + 1 * SEGB + d0, Al + aOff0 + k0);
        cpasync16(sb + 1 * SEGB + d1, Al + aOff1 + k0);
        cpasync16(sb + 2 * SEGB + d0, Bh + bOff0 + k0);
        cpasync16(sb + 2 * SEGB + d1, Bh + bOff1 + k0);
        cpasync16(sb + 3 * SEGB + d0, Bl + bOff0 + k0);
        cpasync16(sb + 3 * SEGB + d1, Bl + bOff1 + k0);
        cp_commit();
    };

    issue(0, 0);
    if (ntiles > 1) issue(1, 1);

    for (int t = 0; t < ntiles; t++) {
        const int st = t & 1;
        if (t + 1 < ntiles) {
            asm volatile("cp.async.wait_group 1;");
        } else {
            asm volatile("cp.async.wait_group 0;");
        }
        __syncthreads();

        const uint32_t sb  = sbase + (uint32_t)st * 4 * SEGB;
        const uint32_t pAh = sb;
        const uint32_t pAl = sb + 1 * SEGB;
        const uint32_t pBh = sb + 2 * SEGB;
        const uint32_t pBl = sb + 3 * SEGB;

        #pragma unroll
        for (int kc = 0; kc < 2; kc++) {
            const uint32_t kb = (uint32_t)kc * 32;
            uint32_t ah[4][4], al[4][4], bh[4][2], bl[4][2];
            #pragma unroll
            for (int i = 0; i < 4; i++) {
                const uint32_t ao = aRowB + (uint32_t)i * (16 * PITCH * 2) + kb;
                ldsm4(ah[i], pAh + ao);
                ldsm4(al[i], pAl + ao);
            }
            #pragma unroll
            for (int j = 0; j < 4; j++) {
                const uint32_t bo = bRowB + (uint32_t)j * (8 * PITCH * 2) + kb;
                ldsm2(bh[j], pBh + bo);
                ldsm2(bl[j], pBl + bo);
            }
            #pragma unroll
            for (int i = 0; i < 4; i++)
                #pragma unroll
                for (int j = 0; j < 4; j++)
                    mma16816(acc[i][j], ah[i], bh[j]);
            #pragma unroll
            for (int i = 0; i < 4; i++)
                #pragma unroll
                for (int j = 0; j < 4; j++)
                    mma16816(acc[i][j], al[i], bh[j]);
            #pragma unroll
            for (int i = 0; i < 4; i++)
                #pragma unroll
                for (int j = 0; j < 4; j++)
                    mma16816(acc[i][j], ah[i], bl[j]);
        }

        if (t + 2 < ntiles) {
            __syncthreads();
            issue(st, t + 2);
        }
    }

    // epilogue
    const int g = lane >> 2;
    #pragma unroll
    for (int i = 0; i < 4; i++) {
        const int row = m0 + wm * 64 + i * 16 + g;
        #pragma unroll
        for (int j = 0; j < 4; j++) {
            const int col = n0 + wn * 32 + j * 8 + (lane & 3) * 2;
            if (EPI == 3) {
                // fused qkv reshape/split (P0..P5 = Qh,Ql,Kh,Kl,Vth,Vtl)
                scatter_qkv(row,     col,     acc[i][j][0], P0, P1, P2, P3, P4, P5);
                scatter_qkv(row,     col + 1, acc[i][j][1], P0, P1, P2, P3, P4, P5);
                scatter_qkv(row + 8, col,     acc[i][j][2], P0, P1, P2, P3, P4, P5);
                scatter_qkv(row + 8, col + 1, acc[i][j][3], P0, P1, P2, P3, P4, P5);
            } else if (EPI == 2) {
                const int oc = col >> 1;
                const float v0 = geglu1(acc[i][j][0], acc[i][j][1]);
                const float v1 = geglu1(acc[i][j][2], acc[i][j][3]);
                __nv_bfloat16 h0, l0, h1, l1;
                split1(v0, h0, l0);
                split1(v1, h1, l1);
                const size_t o0 = (size_t)row * (N >> 1) + oc;
                const size_t o1 = (size_t)(row + 8) * (N >> 1) + oc;
                P0[o0] = h0; P1[o0] = l0;   // P0=Gh, P1=Gl
                P0[o1] = h1; P1[o1] = l1;
            } else {
                const size_t o0 = (size_t)row * N + col;
                const size_t o1 = (size_t)(row + 8) * N + col;
                float2 v0 = {acc[i][j][0], acc[i][j][1]};
                float2 v1 = {acc[i][j][2], acc[i][j][3]};
                if (EPI == 1) {
                    const float2 r0v = *(const float2*)(R + o0);
                    const float2 r1v = *(const float2*)(R + o1);
                    v0.x += r0v.x; v0.y += r0v.y;
                    v1.x += r1v.x; v1.y += r1v.y;
                }
                *(float2*)(C + o0) = v0;
                *(float2*)(C + o1) = v1;
            }
        }
    }
}

// ----------------------------------------------------------------------------
// Tensor-core flash attention (unchanged, validated)
// ----------------------------------------------------------------------------
#define FP   72
#define FSEG (64 * FP)

__global__ __launch_bounds__(256) void flash_mma(const __nv_bfloat16* __restrict__ Qh,
                                                 const __nv_bfloat16* __restrict__ Ql,
                                                 const __nv_bfloat16* __restrict__ Kh,
                                                 const __nv_bfloat16* __restrict__ Kl,
                                                 const __nv_bfloat16* __restrict__ Vth,
                                                 const __nv_bfloat16* __restrict__ Vtl,
                                                 __nv_bfloat16* __restrict__ Oh,
                                                 __nv_bfloat16* __restrict__ Ol) {
    __shared__ __nv_bfloat16 sKh[FSEG], sKl[FSEG], sVh[FSEG], sVl[FSEG];

    const int tid  = threadIdx.x;
    const int lane = tid & 31;
    const int w    = tid >> 5;
    const int h    = blockIdx.y;
    const int b    = blockIdx.z;
    const int q0   = blockIdx.x * 128;
    const size_t bh  = (size_t)(b * NH + h) * S;
    const size_t bhd = (size_t)(b * NH + h) * DH;
    const int g  = lane >> 2;
    const int kq = (lane & 3) * 2;

    uint32_t qfh[4][4], qfl[4][4];
    {
        const int row = q0 + w * 16 + g;
        const __nv_bfloat16* b0h = Qh + (bh + row) * DH;
        const __nv_bfloat16* b8h = Qh + (bh + row + 8) * DH;
        const __nv_bfloat16* b0l = Ql + (bh + row) * DH;
        const __nv_bfloat16* b8l = Ql + (bh + row + 8) * DH;
        #pragma unroll
        for (int kc = 0; kc < 4; kc++) {
            const int o = kc * 16 + kq;
            qfh[kc][0] = *(const uint32_t*)(b0h + o);
            qfh[kc][1] = *(const uint32_t*)(b8h + o);
            qfh[kc][2] = *(const uint32_t*)(b0h + o + 8);
            qfh[kc][3] = *(const uint32_t*)(b8h + o + 8);
            qfl[kc][0] = *(const uint32_t*)(b0l + o);
            qfl[kc][1] = *(const uint32_t*)(b8l + o);
            qfl[kc][2] = *(const uint32_t*)(b0l + o + 8);
            qfl[kc][3] = *(const uint32_t*)(b8l + o + 8);
        }
    }

    float o[8][4];
    #pragma unroll
    for (int j = 0; j < 8; j++)
        #pragma unroll
        for (int r = 0; r < 4; r++) o[j][r] = 0.0f;
    float m0 = -INFINITY, m1 = -INFINITY;
    float l0 = 0.0f, l1 = 0.0f;

    const int i0 = tid, i1 = tid + 256;
    const int lr0 = i0 >> 3, lc0 = (i0 & 7) * 8;
    const int lr1 = i1 >> 3, lc1 = (i1 & 7) * 8;

    for (int kt = 0; kt < S; kt += 64) {
        __syncthreads();
        *(uint4*)(sKh + lr0 * FP + lc0) = *(const uint4*)(Kh + (bh + kt + lr0) * DH + lc0);
        *(uint4*)(sKh + lr1 * FP + lc1) = *(const uint4*)(Kh + (bh + kt + lr1) * DH + lc1);
        *(uint4*)(sKl + lr0 * FP + lc0) = *(const uint4*)(Kl + (bh + kt + lr0) * DH + lc0);
        *(uint4*)(sKl + lr1 * FP + lc1) = *(const uint4*)(Kl + (bh + kt + lr1) * DH + lc1);
        *(uint4*)(sVh + lr0 * FP + lc0) = *(const uint4*)(Vth + (bhd + lr0) * S + kt + lc0);
        *(uint4*)(sVh + lr1 * FP + lc1) = *(const uint4*)(Vth + (bhd + lr1) * S + kt + lc1);
        *(uint4*)(sVl + lr0 * FP + lc0) = *(const uint4*)(Vtl + (bhd + lr0) * S + kt + lc0);
        *(uint4*)(sVl + lr1 * FP + lc1) = *(const uint4*)(Vtl + (bhd + lr1) * S + kt + lc1);
        __syncthreads();

        float sc[8][4];
        #pragma unroll
        for (int j = 0; j < 8; j++)
            #pragma unroll
            for (int r = 0; r < 4; r++) sc[j][r] = 0.0f;

        #pragma unroll
        for (int kc = 0; kc < 4; kc++) {
            #pragma unroll
            for (int j = 0; j < 8; j++) {
                const int off = (j * 8 + g) * FP + kc * 16 + kq;
                uint32_t kb[2], klo[2];
                kb[0]  = *(const uint32_t*)(sKh + off);
                kb[1]  = *(const uint32_t*)(sKh + off + 8);
                klo[0] = *(const uint32_t*)(sKl + off);
                klo[1] = *(const uint32_t*)(sKl + off + 8);
                mma16816(sc[j], qfh[kc], kb);
                mma16816(sc[j], qfl[kc], kb);
                mma16816(sc[j], qfh[kc], klo);
            }
        }

        float mx0 = sc[0][0], mx1 = sc[0][2];
        #pragma unroll
        for (int j = 0; j < 8; j++) {
            mx0 = fmaxf(mx0, fmaxf(sc[j][0], sc[j][1]));
            mx1 = fmaxf(mx1, fmaxf(sc[j][2], sc[j][3]));
        }
        mx0 = fmaxf(mx0, __shfl_xor_sync(0xffffffffu, mx0, 1));
        mx0 = fmaxf(mx0, __shfl_xor_sync(0xffffffffu, mx0, 2));
        mx1 = fmaxf(mx1, __shfl_xor_sync(0xffffffffu, mx1, 1));
        mx1 = fmaxf(mx1, __shfl_xor_sync(0xffffffffu, mx1, 2));

        const float mn0 = fmaxf(m0, mx0);
        const float mn1 = fmaxf(m1, mx1);
        const float c0 = fexp(m0 - mn0);
        const float c1 = fexp(m1 - mn1);
        m0 = mn0; m1 = mn1;

        float s0 = 0.0f, s1 = 0.0f;
        #pragma unroll
        for (int j = 0; j < 8; j++) {
            sc[j][0] = fexp(sc[j][0] - mn0);
            sc[j][1] = fexp(sc[j][1] - mn0);
            sc[j][2] = fexp(sc[j][2] - mn1);
            sc[j][3] = fexp(sc[j][3] - mn1);
            s0 += sc[j][0] + sc[j][1];
            s1 += sc[j][2] + sc[j][3];
        }
        s0 += __shfl_xor_sync(0xffffffffu, s0, 1);
        s0 += __shfl_xor_sync(0xffffffffu, s0, 2);
        s1 += __shfl_xor_sync(0xffffffffu, s1, 1);
        s1 += __shfl_xor_sync(0xffffffffu, s1, 2);
        l0 = l0 * c0 + s0;
        l1 = l1 * c1 + s1;

        #pragma unroll
        for (int j = 0; j < 8; j++) {
            o[j][0] *= c0; o[j][1] *= c0;
            o[j][2] *= c1; o[j][3] *= c1;
        }

        #pragma unroll
        for (int t2 = 0; t2 < 4; t2++) {
            uint32_t ph[4], pl[4];
            {
                const float* e = sc[2 * t2];
                const float* f = sc[2 * t2 + 1];
                __nv_bfloat16 hv[8], lv[8];
                split1(e[0], hv[0], lv[0]); split1(e[1], hv[1], lv[1]);
                split1(e[2], hv[2], lv[2]); split1(e[3], hv[3], lv[3]);
                split1(f[0], hv[4], lv[4]); split1(f[1], hv[5], lv[5]);
                split1(f[2], hv[6], lv[6]); split1(f[3], hv[7], lv[7]);
                __nv_bfloat162 t0 = __nv_bfloat162(hv[0], hv[1]);
                __nv_bfloat162 t1 = __nv_bfloat162(hv[2], hv[3]);
                __nv_bfloat162 t2v = __nv_bfloat162(hv[4], hv[5]);
                __nv_bfloat162 t3 = __nv_bfloat162(hv[6], hv[7]);
                ph[0] = *(uint32_t*)&t0; ph[1] = *(uint32_t*)&t1;
                ph[2] = *(uint32_t*)&t2v; ph[3] = *(uint32_t*)&t3;
                t0 = __nv_bfloat162(lv[0], lv[1]);
                t1 = __nv_bfloat162(lv[2], lv[3]);
                t2v = __nv_bfloat162(lv[4], lv[5]);
                t3 = __nv_bfloat162(lv[6], lv[7]);
                pl[0] = *(uint32_t*)&t0; pl[1] = *(uint32_t*)&t1;
                pl[2] = *(uint32_t*)&t2v; pl[3] = *(uint32_t*)&t3;
            }
            #pragma unroll
            for (int j = 0; j < 8; j++) {
                const int off = (j * 8 + g) * FP + t2 * 16 + kq;
                uint32_t vh[2], vl[2];
                vh[0] = *(const uint32_t*)(sVh + off);
                vh[1] = *(const uint32_t*)(sVh + off + 8);
                vl[0] = *(const uint32_t*)(sVl + off);
                vl[1] = *(const uint32_t*)(sVl + off + 8);
                mma16816(o[j], ph, vh);
                mma16816(o[j], pl, vh);
                mma16816(o[j], ph, vl);
            }
        }
    }

    const float inv0 = 1.0f / l0;
    const float inv1 = 1.0f / l1;
    const int row = q0 + w * 16 + g;
    const size_t t0 = (size_t)(b * S + row);
    const size_t t8 = t0 + 8;
    #pragma unroll
    for (int j = 0; j < 8; j++) {
        const int col = h * DH + j * 8 + kq;
        float v0 = o[j][0] * inv0, v1 = o[j][1] * inv0;
        float v2 = o[j][2] * inv1, v3 = o[j][3] * inv1;
        __nv_bfloat16 h0, h1, h2, h3, l0b, l1b, l2b, l3b;
        split1(v0, h0, l0b); split1(v1, h1, l1b);
        split1(v2, h2, l2b); split1(v3, h3, l3b);
        *(__nv_bfloat162*)(Oh + t0 * DM + col) = __nv_bfloat162(h0, h1);
        *(__nv_bfloat162*)(Ol + t0 * DM + col) = __nv_bfloat162(l0b, l1b);
        *(__nv_bfloat162*)(Oh + t8 * DM + col) = __nv_bfloat162(h2, h3);
        *(__nv_bfloat162*)(Ol + t8 * DM + col) = __nv_bfloat162(l2b, l3b);
    }
}

// ----------------------------------------------------------------------------
// Launch
// ----------------------------------------------------------------------------
extern "C" void kernel_launch(void* const* d_in, const int* in_sizes, int n_in,
                              void* d_out, int out_size) {
    const float* X     = (const float*)d_in[0];
    const float* W_qkv = (const float*)d_in[1];
    const float* W_o   = (const float*)d_in[2];
    const float* W_fc1 = (const float*)d_in[3];
    const float* W_fc2 = (const float*)d_in[4];
    const float* ln1_w = (const float*)d_in[5];
    const float* ln2_w = (const float*)d_in[6];
    float* out = (float*)d_out;

    float *p_X1;
    __nv_bfloat16 *p_Xnh, *p_Xnl, *p_atth, *p_attl, *p_hh, *p_hl;
    __nv_bfloat16 *p_Wqh, *p_Wql, *p_Woh, *p_Wol, *p_Wf1h, *p_Wf1l, *p_Wf2h, *p_Wf2l;
    __nv_bfloat16 *p_Qh, *p_Ql, *p_Kh, *p_Kl, *p_Vth, *p_Vtl;
    cudaGetSymbolAddress((void**)&p_X1,  g_X1);
    cudaGetSymbolAddress((void**)&p_Xnh,  g_Xnh);
    cudaGetSymbolAddress((void**)&p_Xnl,  g_Xnl);
    cudaGetSymbolAddress((void**)&p_atth, g_atth);
    cudaGetSymbolAddress((void**)&p_attl, g_attl);
    cudaGetSymbolAddress((void**)&p_hh,   g_hh);
    cudaGetSymbolAddress((void**)&p_hl,   g_hl);
    cudaGetSymbolAddress((void**)&p_Wqh,  g_Wqh);
    cudaGetSymbolAddress((void**)&p_Wql,  g_Wql);
    cudaGetSymbolAddress((void**)&p_Woh,  g_Woh);
    cudaGetSymbolAddress((void**)&p_Wol,  g_Wol);
    cudaGetSymbolAddress((void**)&p_Wf1h, g_Wf1h);
    cudaGetSymbolAddress((void**)&p_Wf1l, g_Wf1l);
    cudaGetSymbolAddress((void**)&p_Wf2h, g_Wf2h);
    cudaGetSymbolAddress((void**)&p_Wf2l, g_Wf2l);
    cudaGetSymbolAddress((void**)&p_Qh,  g_Qh);
    cudaGetSymbolAddress((void**)&p_Ql,  g_Ql);
    cudaGetSymbolAddress((void**)&p_Kh,  g_Kh);
    cudaGetSymbolAddress((void**)&p_Kl,  g_Kl);
    cudaGetSymbolAddress((void**)&p_Vth, g_Vth);
    cudaGetSymbolAddress((void**)&p_Vtl, g_Vtl);

    const int smemBytes = STAGES * 4 * SEGB; // 81920 -> 2 CTAs/SM
    cudaFuncSetAttribute(gemm_bf16s<1>, cudaFuncAttributeMaxDynamicSharedMemorySize, smemBytes);
    cudaFuncSetAttribute(gemm_bf16s<2>, cudaFuncAttributeMaxDynamicSharedMemorySize, smemBytes);
    cudaFuncSetAttribute(gemm_bf16s<3>, cudaFuncAttributeMaxDynamicSharedMemorySize, smemBytes);

    // weight splits (fc1 interleaved for fused GEGLU)
    split_kernel<<<(QKV3 * DM / 4 + 255) / 256, 256>>>(W_qkv, p_Wqh, p_Wql, QKV3 * DM / 4);
    split_kernel<<<(DM * DM / 4 + 255) / 256, 256>>>(W_o, p_Woh, p_Wol, DM * DM / 4);
    split_ilv_kernel<<<(FFN2 * DM / 4 + 255) / 256, 256>>>(W_fc1, p_Wf1h, p_Wf1l, FFN2 * DM / 4);
    split_kernel<<<(DM * FFN / 4 + 255) / 256, 256>>>(W_fc2, p_Wf2h, p_Wf2l, DM * FFN / 4);

    // 1. LN1
    ln_split_kernel<<<T, 256>>>(X, ln1_w, p_Xnh, p_Xnl);
    // 2+3. qkv GEMM with fused reshape/split epilogue (no fp32 qkv buffer)
    gemm_bf16s<3><<<dim3(QKV3 / 128, T / 128), 256, smemBytes>>>(
        p_Xnh, p_Xnl, p_Wqh, p_Wql, nullptr, nullptr,
        p_Qh, p_Ql, p_Kh, p_Kl, p_Vth, p_Vtl, T, QKV3, DM);
    // 4. attention
    flash_mma<<<dim3(S / 128, NH, B), 256>>>(p_Qh, p_Ql, p_Kh, p_Kl, p_Vth, p_Vtl,
                                             p_atth, p_attl);
    // 5. X1 = X + attn @ W_o^T
    gemm_bf16s<1><<<dim3(DM / 128, T / 128), 256, smemBytes>>>(
        p_atth, p_attl, p_Woh, p_Wol, X, p_X1,
        nullptr, nullptr, nullptr, nullptr, nullptr, nullptr, T, DM, DM);
    // 6. LN2
    ln_split_kernel<<<T, 256>>>(p_X1, ln2_w, p_Xnh, p_Xnl);
    // 7+8. h = geglu(Xn @ W_fc1_interleaved^T)  — fused epilogue, split output
    gemm_bf16s<2><<<dim3(FFN2 / 128, T / 128), 256, smemBytes>>>(
        p_Xnh, p_Xnl, p_Wf1h, p_Wf1l, nullptr, nullptr,
        p_hh, p_hl, nullptr, nullptr, nullptr, nullptr, T, FFN2, DM);
    // 9. out = X1 + h @ W_fc2^T
    gemm_bf16s<1><<<dim3(DM / 128, T / 128), 256, smemBytes>>>(
        p_hh, p_hl, p_Wf2h, p_Wf2l, p_X1, out,
        nullptr, nullptr, nullptr, nullptr, nullptr, nullptr, T, DM, FFN);
}

// round 14
// speedup vs baseline: 2.6489x; 1.0274x over previous
#include <cuda_runtime.h>
#include <cuda_bf16.h>
#include <math.h>
#include <stdint.h>

// ----------------------------------------------------------------------------
// Problem constants
// ----------------------------------------------------------------------------
#define B        4
#define S        2048
#define T        (B * S)          // 8192 tokens
#define DM       1024             // d_model
#define NH       16               // heads
#define DH       64               // head dim
#define QKV3     (3 * NH * DH)    // 3072
#define FFN      4096
#define FFN2     (2 * FFN)        // 8192

// ----------------------------------------------------------------------------
// Scratch (device globals -> no allocation inside kernel_launch)
// ----------------------------------------------------------------------------
__device__ float g_X1  [(size_t)T * DM];    // X + attn @ Wo^T

__device__ __nv_bfloat16 g_Xnh [(size_t)T * DM];
__device__ __nv_bfloat16 g_Xnl [(size_t)T * DM];
__device__ __nv_bfloat16 g_atth[(size_t)T * DM];
__device__ __nv_bfloat16 g_attl[(size_t)T * DM];
__device__ __nv_bfloat16 g_hh  [(size_t)T * FFN];
__device__ __nv_bfloat16 g_hl  [(size_t)T * FFN];
__device__ __nv_bfloat16 g_Wqh [(size_t)QKV3 * DM];
__device__ __nv_bfloat16 g_Wql [(size_t)QKV3 * DM];
__device__ __nv_bfloat16 g_Woh [(size_t)DM * DM];
__device__ __nv_bfloat16 g_Wol [(size_t)DM * DM];
__device__ __nv_bfloat16 g_Wf1h[(size_t)FFN2 * DM];   // row-interleaved (a0,g0,a1,g1,...)
__device__ __nv_bfloat16 g_Wf1l[(size_t)FFN2 * DM];
__device__ __nv_bfloat16 g_Wf2h[(size_t)DM * FFN];
__device__ __nv_bfloat16 g_Wf2l[(size_t)DM * FFN];
__device__ __nv_bfloat16 g_Qh [(size_t)T * DM];   // [b,h,s,d]  (pre-scaled 1/8)
__device__ __nv_bfloat16 g_Ql [(size_t)T * DM];
__device__ __nv_bfloat16 g_Kh [(size_t)T * DM];   // [b,h,s,d]
__device__ __nv_bfloat16 g_Kl [(size_t)T * DM];
__device__ __nv_bfloat16 g_Vth[(size_t)T * DM];   // [b,h,d,s]  (transposed)
__device__ __nv_bfloat16 g_Vtl[(size_t)T * DM];

// ----------------------------------------------------------------------------
// fp32 -> (hi, lo) bf16 split
// ----------------------------------------------------------------------------
__device__ __forceinline__ void split1(float x, __nv_bfloat16& h, __nv_bfloat16& l) {
    h = __float2bfloat16_rn(x);
    l = __float2bfloat16_rn(x - __bfloat162float(h));
}

// ----------------------------------------------------------------------------
// Fast exp on FMA pipe (no MUFU). rel err < 3e-8 on clamped range.
// ----------------------------------------------------------------------------
__device__ __forceinline__ float fexp(float x) {
    x = fminf(fmaxf(x, -87.0f), 87.0f);
    const float y = x * 1.4426950408889634f;
    const float z = y + 12582912.0f;
    const int   n = __float_as_int(z) - 0x4B400000;
    const float f = y - (z - 12582912.0f);
    float p = 1.5403530393381609e-4f;
    p = fmaf(p, f, 1.3333558146428443e-3f);
    p = fmaf(p, f, 9.6181291076284772e-3f);
    p = fmaf(p, f, 5.5504108664821580e-2f);
    p = fmaf(p, f, 2.4022650695910072e-1f);
    p = fmaf(p, f, 6.9314718055994531e-1f);
    p = fmaf(p, f, 1.0f);
    return __int_as_float(__float_as_int(p) + (n << 23));
}

__device__ __forceinline__ float frcp(float x) {
    float r;
    asm("rcp.approx.f32 %0, %1;" : "=f"(r) : "f"(x));
    return r;
}

// GEGLU scalar
__device__ __forceinline__ float geglu1(float a, float g) {
    const float z = 0.7978845608028654f * (g + 0.044715f * g * g * g);
    const float ew = fexp(-2.0f * z);
    return a * g * frcp(1.0f + ew);
}

// ----------------------------------------------------------------------------
// Async copy + ldmatrix helpers
// ----------------------------------------------------------------------------
__device__ __forceinline__ void cpasync16(uint32_t dst, const void* src) {
    asm volatile("cp.async.cg.shared.global [%0], [%1], 16;" :: "r"(dst), "l"(src));
}
__device__ __forceinline__ void cp_commit() {
    asm volatile("cp.async.commit_group;");
}
__device__ __forceinline__ void ldsm4(uint32_t* r, uint32_t a) {
    asm volatile("ldmatrix.sync.aligned.m8n8.x4.shared.b16 {%0,%1,%2,%3}, [%4];"
        : "=r"(r[0]), "=r"(r[1]), "=r"(r[2]), "=r"(r[3]) : "r"(a));
}
__device__ __forceinline__ void ldsm2(uint32_t* r, uint32_t a) {
    asm volatile("ldmatrix.sync.aligned.m8n8.x2.shared.b16 {%0,%1}, [%2];"
        : "=r"(r[0]), "=r"(r[1]) : "r"(a));
}

// ----------------------------------------------------------------------------
// qkv epilogue scatter (validated round 13)
// ----------------------------------------------------------------------------
__device__ __forceinline__ void scatter_qkv(int t, int cc, float v,
                                            __nv_bfloat16* __restrict__ Qh,
                                            __nv_bfloat16* __restrict__ Ql,
                                            __nv_bfloat16* __restrict__ Kh,
                                            __nv_bfloat16* __restrict__ Kl,
                                            __nv_bfloat16* __restrict__ Vth,
                                            __nv_bfloat16* __restrict__ Vtl) {
    const int h   = cc / 192;
    const int rem = cc - h * 192;
    const int d   = rem / 3;
    const int c   = rem - d * 3;
    const int b   = t >> 11;
    const int s   = t & 2047;
    __nv_bfloat16 hh, ll;
    if (c == 0) {
        split1(v * 0.125f, hh, ll);
        const size_t qk = (((size_t)(b * NH + h)) * S + s) * DH + d;
        Qh[qk] = hh; Ql[qk] = ll;
    } else if (c == 1) {
        split1(v, hh, ll);
        const size_t qk = (((size_t)(b * NH + h)) * S + s) * DH + d;
        Kh[qk] = hh; Kl[qk] = ll;
    } else {
        split1(v, hh, ll);
        const size_t vt = (((size_t)(b * NH + h)) * DH + d) * S + s;
        Vth[vt] = hh; Vtl[vt] = ll;
    }
}

// ----------------------------------------------------------------------------
// Weight split: float4-vectorized
// ----------------------------------------------------------------------------
__global__ __launch_bounds__(256) void split_kernel(const float* __restrict__ X,
                                                    __nv_bfloat16* __restrict__ H,
                                                    __nv_bfloat16* __restrict__ L,
                                                    int n4) {
    const int gid = blockIdx.x * 256 + threadIdx.x;
    if (gid >= n4) return;
    const float4 v = ((const float4*)X)[gid];
    __nv_bfloat16 h0, h1, h2, h3, l0, l1, l2, l3;
    split1(v.x, h0, l0); split1(v.y, h1, l1);
    split1(v.z, h2, l2); split1(v.w, h3, l3);
    __nv_bfloat162* Hp = (__nv_bfloat162*)H;
    __nv_bfloat162* Lp = (__nv_bfloat162*)L;
    Hp[gid * 2]     = __nv_bfloat162(h0, h1);
    Hp[gid * 2 + 1] = __nv_bfloat162(h2, h3);
    Lp[gid * 2]     = __nv_bfloat162(l0, l1);
    Lp[gid * 2 + 1] = __nv_bfloat162(l2, l3);
}

// ----------------------------------------------------------------------------
// W_fc1 split with row interleave
// ----------------------------------------------------------------------------
__global__ __launch_bounds__(256) void split_ilv_kernel(const float* __restrict__ X,
                                                        __nv_bfloat16* __restrict__ H,
                                                        __nv_bfloat16* __restrict__ L,
                                                        int n4) {
    const int gid = blockIdx.x * 256 + threadIdx.x;
    if (gid >= n4) return;
    const int e0   = gid * 4;
    const int srow = e0 >> 10;
    const int col  = e0 & 1023;
    const int drow = (srow < FFN) ? (srow * 2) : ((srow - FFN) * 2 + 1);
    const float4 v = ((const float4*)X)[gid];
    __nv_bfloat16 h0, h1, h2, h3, l0, l1, l2, l3;
    split1(v.x, h0, l0); split1(v.y, h1, l1);
    split1(v.z, h2, l2); split1(v.w, h3, l3);
    const size_t d4 = ((size_t)drow * DM + col) >> 1;
    __nv_bfloat162* Hp = (__nv_bfloat162*)H;
    __nv_bfloat162* Lp = (__nv_bfloat162*)L;
    Hp[d4]     = __nv_bfloat162(h0, h1);
    Hp[d4 + 1] = __nv_bfloat162(h2, h3);
    Lp[d4]     = __nv_bfloat162(l0, l1);
    Lp[d4 + 1] = __nv_bfloat162(l2, l3);
}

// ----------------------------------------------------------------------------
// LayerNorm with fused hi/lo split output
// ----------------------------------------------------------------------------
__global__ __launch_bounds__(256) void ln_split_kernel(const float* __restrict__ X,
                                                       const float* __restrict__ w,
                                                       __nv_bfloat16* __restrict__ Hh,
                                                       __nv_bfloat16* __restrict__ Hl) {
    const int row = blockIdx.x;
    const int tid = threadIdx.x;
    const float4* xp = (const float4*)(X + (size_t)row * DM);
    float4 v = xp[tid];

    float s  = v.x + v.y + v.z + v.w;
    float sq = v.x * v.x + v.y * v.y + v.z * v.z + v.w * v.w;

    __shared__ float rs[256];
    __shared__ float rq[256];
    rs[tid] = s; rq[tid] = sq;
    __syncthreads();
    #pragma unroll
    for (int o = 128; o >= 1; o >>= 1) {
        if (tid < o) { rs[tid] += rs[tid + o]; rq[tid] += rq[tid + o]; }
        __syncthreads();
    }
    const float mu   = rs[0] * (1.0f / DM);
    const float var  = rq[0] * (1.0f / DM) - mu * mu;
    const float rstd = rsqrtf(var + 1e-5f);

    const float4 wv = ((const float4*)w)[tid];
    float y0 = (v.x - mu) * rstd * wv.x;
    float y1 = (v.y - mu) * rstd * wv.y;
    float y2 = (v.z - mu) * rstd * wv.z;
    float y3 = (v.w - mu) * rstd * wv.w;

    __nv_bfloat16 h0, h1, h2, h3, l0, l1, l2, l3;
    split1(y0, h0, l0); split1(y1, h1, l1);
    split1(y2, h2, l2); split1(y3, h3, l3);
    __nv_bfloat162* Hp = (__nv_bfloat162*)(Hh + (size_t)row * DM);
    __nv_bfloat162* Lp = (__nv_bfloat162*)(Hl + (size_t)row * DM);
    Hp[tid * 2]     = __nv_bfloat162(h0, h1);
    Hp[tid * 2 + 1] = __nv_bfloat162(h2, h3);
    Lp[tid * 2]     = __nv_bfloat162(l0, l1);
    Lp[tid * 2 + 1] = __nv_bfloat162(l2, l3);
}

// ----------------------------------------------------------------------------
// mma.sync m16n8k16 bf16 -> fp32
// ----------------------------------------------------------------------------
__device__ __forceinline__ void mma16816(float* c, const uint32_t* a, const uint32_t* b) {
    asm volatile(
        "mma.sync.aligned.m16n8k16.row.col.f32.bf16.bf16.f32 "
        "{%0,%1,%2,%3},{%4,%5,%6,%7},{%8,%9},{%0,%1,%2,%3};"
        : "+f"(c[0]), "+f"(c[1]), "+f"(c[2]), "+f"(c[3])
        : "r"(a[0]), "r"(a[1]), "r"(a[2]), "r"(a[3]), "r"(b[0]), "r"(b[1]));
}

// ----------------------------------------------------------------------------
// Split-bf16 NT GEMM: 2-stage cp.async pipeline + ldmatrix, 2 CTAs/SM.
// EPI 0: C=AB  EPI 1: C=R+AB  EPI 2: fused GEGLU  EPI 3: fused qkv scatter
// ----------------------------------------------------------------------------
#define STAGES 2
#define PITCH  40
#define SEGB   (128 * PITCH * 2)   // 10240

template <int EPI>
__global__ __launch_bounds__(256, 2) void gemm_bf16s(const __nv_bfloat16* __restrict__ Ah,
                                                     const __nv_bfloat16* __restrict__ Al,
                                                     const __nv_bfloat16* __restrict__ Bh,
                                                     const __nv_bfloat16* __restrict__ Bl,
                                                     const float* __restrict__ R,
                                                     float* __restrict__ C,
                                                     __nv_bfloat16* __restrict__ P0,
                                                     __nv_bfloat16* __restrict__ P1,
                                                     __nv_bfloat16* __restrict__ P2,
                                                     __nv_bfloat16* __restrict__ P3,
                                                     __nv_bfloat16* __restrict__ P4,
                                                     __nv_bfloat16* __restrict__ P5,
                                                     int M, int N, int K) {
    extern __shared__ __nv_bfloat16 smem[];
    const uint32_t sbase = (uint32_t)__cvta_generic_to_shared(smem);

    const int tid  = threadIdx.x;
    const int lane = tid & 31;
    const int warp = tid >> 5;
    const int wm   = warp >> 2;
    const int wn   = warp & 3;

    const int m0 = blockIdx.y * 128;
    const int n0 = blockIdx.x * 128;

    const int r0 = tid >> 2;
    const int r1 = r0 + 64;
    const int c0 = (tid & 3) * 8;

    const size_t aOff0 = (size_t)(m0 + r0) * K + c0;
    const size_t aOff1 = (size_t)(m0 + r1) * K + c0;
    const size_t bOff0 = (size_t)(n0 + r0) * K + c0;
    const size_t bOff1 = (size_t)(n0 + r1) * K + c0;
    const uint32_t d0 = (uint32_t)(r0 * PITCH + c0) * 2;
    const uint32_t d1 = (uint32_t)(r1 * PITCH + c0) * 2;

    const uint32_t aRowB = (uint32_t)(((wm * 64 + (lane & 15)) * PITCH
                                       + ((lane >> 4) << 3)) * 2);
    const uint32_t bRowB = (uint32_t)(((wn * 32 + (lane & 7)) * PITCH
                                       + (((lane >> 3) & 1) << 3)) * 2);

    float acc[4][4][4];
    #pragma unroll
    for (int i = 0; i < 4; i++)
        #pragma unroll
        for (int j = 0; j < 4; j++)
            #pragma unroll
            for (int r = 0; r < 4; r++) acc[i][j][r] = 0.0f;

    const int ntiles = K >> 5;

    auto issue = [&](int st, int t) {
        const int k0 = t * 32;
        const uint32_t sb = sbase + (uint32_t)st * 4 * SEGB;
        cpasync16(sb + 0 * SEGB + d0, Ah + aOff0 + k0);
        cpasync16(sb + 0 * SEGB + d1, Ah + aOff1 + k0);
        cpasync16(sb + 1 * SEGB + d0, Al + aOff0 + k0);
        cpasync16(sb + 1 * SEGB + d1, Al + aOff1 + k0);
        cpasync16(sb + 2 * SEGB + d0, Bh + bOff0 + k0);
        cpasync16(sb + 2 * SEGB + d1, Bh + bOff1 + k0);
        cpasync16(sb + 3 * SEGB + d0, Bl + bOff0 + k0);
        cpasync16(sb + 3 * SEGB + d1, Bl + bOff1 + k0);
        cp_commit();
    };

    issue(0, 0);
    if (ntiles > 1) issue(1, 1);

    for (int t = 0; t < ntiles; t++) {
        const int st = t & 1;
        if (t + 1 < ntiles) {
            asm volatile("cp.async.wait_group 1;");
        } else {
            asm volatile("cp.async.wait_group 0;");
        }
        __syncthreads();

        const uint32_t sb  = sbase + (uint32_t)st * 4 * SEGB;
        const uint32_t pAh = sb;
        const uint32_t pAl = sb + 1 * SEGB;
        const uint32_t pBh = sb + 2 * SEGB;
        const uint32_t pBl = sb + 3 * SEGB;

        #pragma unroll
        for (int kc = 0; kc < 2; kc++) {
            const uint32_t kb = (uint32_t)kc * 32;
            uint32_t ah[4][4], al[4][4], bh[4][2], bl[4][2];
            #pragma unroll
            for (int i = 0; i < 4; i++) {
                const uint32_t ao = aRowB + (uint32_t)i * (16 * PITCH * 2) + kb;
                ldsm4(ah[i], pAh + ao);
                ldsm4(al[i], pAl + ao);
            }
            #pragma unroll
            for (int j = 0; j < 4; j++) {
                const uint32_t bo = bRowB + (uint32_t)j * (8 * PITCH * 2) + kb;
                ldsm2(bh[j], pBh + bo);
                ldsm2(bl[j], pBl + bo);
            }
            #pragma unroll
            for (int i = 0; i < 4; i++)
                #pragma unroll
                for (int j = 0; j < 4; j++)
                    mma16816(acc[i][j], ah[i], bh[j]);
            #pragma unroll
            for (int i = 0; i < 4; i++)
                #pragma unroll
                for (int j = 0; j < 4; j++)
                    mma16816(acc[i][j], al[i], bh[j]);
            #pragma unroll
            for (int i = 0; i < 4; i++)
                #pragma unroll
                for (int j = 0; j < 4; j++)
                    mma16816(acc[i][j], ah[i], bl[j]);
        }

        if (t + 2 < ntiles) {
            __syncthreads();
            issue(st, t + 2);
        }
    }

    // epilogue
    const int g = lane >> 2;
    #pragma unroll
    for (int i = 0; i < 4; i++) {
        const int row = m0 + wm * 64 + i * 16 + g;
        #pragma unroll
        for (int j = 0; j < 4; j++) {
            const int col = n0 + wn * 32 + j * 8 + (lane & 3) * 2;
            if (EPI == 3) {
                scatter_qkv(row,     col,     acc[i][j][0], P0, P1, P2, P3, P4, P5);
                scatter_qkv(row,     col + 1, acc[i][j][1], P0, P1, P2, P3, P4, P5);
                scatter_qkv(row + 8, col,     acc[i][j][2], P0, P1, P2, P3, P4, P5);
                scatter_qkv(row + 8, col + 1, acc[i][j][3], P0, P1, P2, P3, P4, P5);
            } else if (EPI == 2) {
                const int oc = col >> 1;
                const float v0 = geglu1(acc[i][j][0], acc[i][j][1]);
                const float v1 = geglu1(acc[i][j][2], acc[i][j][3]);
                __nv_bfloat16 h0, l0, h1, l1;
                split1(v0, h0, l0);
                split1(v1, h1, l1);
                const size_t o0 = (size_t)row * (N >> 1) + oc;
                const size_t o1 = (size_t)(row + 8) * (N >> 1) + oc;
                P0[o0] = h0; P1[o0] = l0;
                P0[o1] = h1; P1[o1] = l1;
            } else {
                const size_t o0 = (size_t)row * N + col;
                const size_t o1 = (size_t)(row + 8) * N + col;
                float2 v0 = {acc[i][j][0], acc[i][j][1]};
                float2 v1 = {acc[i][j][2], acc[i][j][3]};
                if (EPI == 1) {
                    const float2 r0v = *(const float2*)(R + o0);
                    const float2 r1v = *(const float2*)(R + o1);
                    v0.x += r0v.x; v0.y += r0v.y;
                    v1.x += r1v.x; v1.y += r1v.y;
                }
                *(float2*)(C + o0) = v0;
                *(float2*)(C + o1) = v1;
            }
        }
    }
}

// ----------------------------------------------------------------------------
// Tensor-core flash attention, now with double-buffered cp.async K/V loads.
// Compute body identical to the validated version; only the load path changed.
// ----------------------------------------------------------------------------
#define FP    72
#define FSEG  (64 * FP)            // elements per array per stage
#define FSEGB (FSEG * 2)           // 9216 bytes
#define FBUFB (4 * FSEGB)          // 36864 bytes per stage
#define FSMEM (2 * FBUFB)          // 73728 bytes total

__global__ __launch_bounds__(256) void flash_mma(const __nv_bfloat16* __restrict__ Qh,
                                                 const __nv_bfloat16* __restrict__ Ql,
                                                 const __nv_bfloat16* __restrict__ Kh,
                                                 const __nv_bfloat16* __restrict__ Kl,
                                                 const __nv_bfloat16* __restrict__ Vth,
                                                 const __nv_bfloat16* __restrict__ Vtl,
                                                 __nv_bfloat16* __restrict__ Oh,
                                                 __nv_bfloat16* __restrict__ Ol) {
    extern __shared__ __nv_bfloat16 fsm[];
    const uint32_t fbase = (uint32_t)__cvta_generic_to_shared(fsm);

    const int tid  = threadIdx.x;
    const int lane = tid & 31;
    const int w    = tid >> 5;
    const int h    = blockIdx.y;
    const int b    = blockIdx.z;
    const int q0   = blockIdx.x * 128;
    const size_t bh  = (size_t)(b * NH + h) * S;
    const size_t bhd = (size_t)(b * NH + h) * DH;
    const int g  = lane >> 2;
    const int kq = (lane & 3) * 2;

    uint32_t qfh[4][4], qfl[4][4];
    {
        const int row = q0 + w * 16 + g;
        const __nv_bfloat16* b0h = Qh + (bh + row) * DH;
        const __nv_bfloat16* b8h = Qh + (bh + row + 8) * DH;
        const __nv_bfloat16* b0l = Ql + (bh + row) * DH;
        const __nv_bfloat16* b8l = Ql + (bh + row + 8) * DH;
        #pragma unroll
        for (int kc = 0; kc < 4; kc++) {
            const int o = kc * 16 + kq;
            qfh[kc][0] = *(const uint32_t*)(b0h + o);
            qfh[kc][1] = *(const uint32_t*)(b8h + o);
            qfh[kc][2] = *(const uint32_t*)(b0h + o + 8);
            qfh[kc][3] = *(const uint32_t*)(b8h + o + 8);
            qfl[kc][0] = *(const uint32_t*)(b0l + o);
            qfl[kc][1] = *(const uint32_t*)(b8l + o);
            qfl[kc][2] = *(const uint32_t*)(b0l + o + 8);
            qfl[kc][3] = *(const uint32_t*)(b8l + o + 8);
        }
    }

    float o[8][4];
    #pragma unroll
    for (int j = 0; j < 8; j++)
        #pragma unroll
        for (int r = 0; r < 4; r++) o[j][r] = 0.0f;
    float m0 = -INFINITY, m1 = -INFINITY;
    float l0 = 0.0f, l1 = 0.0f;

    // loader mapping: 512 uint4 per array, 2 per thread
    const int i0 = tid, i1 = tid + 256;
    const int lr0 = i0 >> 3, lc0 = (i0 & 7) * 8;
    const int lr1 = i1 >> 3, lc1 = (i1 & 7) * 8;
    const uint32_t fd00 = (uint32_t)(lr0 * FP + lc0) * 2;
    const uint32_t fd01 = (uint32_t)(lr1 * FP + lc1) * 2;

    auto issue = [&](int st, int kt) {
        const uint32_t sb = fbase + (uint32_t)st * FBUFB;
        cpasync16(sb + 0 * FSEGB + fd00, Kh + (bh + kt + lr0) * DH + lc0);
        cpasync16(sb + 0 * FSEGB + fd01, Kh + (bh + kt + lr1) * DH + lc1);
        cpasync16(sb + 1 * FSEGB + fd00, Kl + (bh + kt + lr0) * DH + lc0);
        cpasync16(sb + 1 * FSEGB + fd01, Kl + (bh + kt + lr1) * DH + lc1);
        cpasync16(sb + 2 * FSEGB + fd00, Vth + (bhd + lr0) * S + kt + lc0);
        cpasync16(sb + 2 * FSEGB + fd01, Vth + (bhd + lr1) * S + kt + lc1);
        cpasync16(sb + 3 * FSEGB + fd00, Vtl + (bhd + lr0) * S + kt + lc0);
        cpasync16(sb + 3 * FSEGB + fd01, Vtl + (bhd + lr1) * S + kt + lc1);
        cp_commit();
    };

    const int ntiles = S / 64;
    issue(0, 0);
    issue(1, 64);

    for (int t = 0; t < ntiles; t++) {
        const int st = t & 1;
        if (t + 1 < ntiles) {
            asm volatile("cp.async.wait_group 1;");
        } else {
            asm volatile("cp.async.wait_group 0;");
        }
        __syncthreads();

        const __nv_bfloat16* sKh = fsm + (size_t)st * 4 * FSEG;
        const __nv_bfloat16* sKl = sKh + FSEG;
        const __nv_bfloat16* sVh = sKh + 2 * FSEG;
        const __nv_bfloat16* sVl = sKh + 3 * FSEG;

        float sc[8][4];
        #pragma unroll
        for (int j = 0; j < 8; j++)
            #pragma unroll
            for (int r = 0; r < 4; r++) sc[j][r] = 0.0f;

        #pragma unroll
        for (int kc = 0; kc < 4; kc++) {
            #pragma unroll
            for (int j = 0; j < 8; j++) {
                const int off = (j * 8 + g) * FP + kc * 16 + kq;
                uint32_t kb[2], klo[2];
                kb[0]  = *(const uint32_t*)(sKh + off);
                kb[1]  = *(const uint32_t*)(sKh + off + 8);
                klo[0] = *(const uint32_t*)(sKl + off);
                klo[1] = *(const uint32_t*)(sKl + off + 8);
                mma16816(sc[j], qfh[kc], kb);
                mma16816(sc[j], qfl[kc], kb);
                mma16816(sc[j], qfh[kc], klo);
            }
        }

        float mx0 = sc[0][0], mx1 = sc[0][2];
        #pragma unroll
        for (int j = 0; j < 8; j++) {
            mx0 = fmaxf(mx0, fmaxf(sc[j][0], sc[j][1]));
            mx1 = fmaxf(mx1, fmaxf(sc[j][2], sc[j][3]));
        }
        mx0 = fmaxf(mx0, __shfl_xor_sync(0xffffffffu, mx0, 1));
        mx0 = fmaxf(mx0, __shfl_xor_sync(0xffffffffu, mx0, 2));
        mx1 = fmaxf(mx1, __shfl_xor_sync(0xffffffffu, mx1, 1));
        mx1 = fmaxf(mx1, __shfl_xor_sync(0xffffffffu, mx1, 2));

        const float mn0 = fmaxf(m0, mx0);
        const float mn1 = fmaxf(m1, mx1);
        const float c0 = fexp(m0 - mn0);
        const float c1 = fexp(m1 - mn1);
        m0 = mn0; m1 = mn1;

        float s0 = 0.0f, s1 = 0.0f;
        #pragma unroll
        for (int j = 0; j < 8; j++) {
            sc[j][0] = fexp(sc[j][0] - mn0);
            sc[j][1] = fexp(sc[j][1] - mn0);
            sc[j][2] = fexp(sc[j][2] - mn1);
            sc[j][3] = fexp(sc[j][3] - mn1);
            s0 += sc[j][0] + sc[j][1];
            s1 += sc[j][2] + sc[j][3];
        }
        s0 += __shfl_xor_sync(0xffffffffu, s0, 1);
        s0 += __shfl_xor_sync(0xffffffffu, s0, 2);
        s1 += __shfl_xor_sync(0xffffffffu, s1, 1);
        s1 += __shfl_xor_sync(0xffffffffu, s1, 2);
        l0 = l0 * c0 + s0;
        l1 = l1 * c1 + s1;

        #pragma unroll
        for (int j = 0; j < 8; j++) {
            o[j][0] *= c0; o[j][1] *= c0;
            o[j][2] *= c1; o[j][3] *= c1;
        }

        #pragma unroll
        for (int t2 = 0; t2 < 4; t2++) {
            uint32_t ph[4], pl[4];
            {
                const float* e = sc[2 * t2];
                const float* f = sc[2 * t2 + 1];
                __nv_bfloat16 hv[8], lv[8];
                split1(e[0], hv[0], lv[0]); split1(e[1], hv[1], lv[1]);
                split1(e[2], hv[2], lv[2]); split1(e[3], hv[3], lv[3]);
                split1(f[0], hv[4], lv[4]); split1(f[1], hv[5], lv[5]);
                split1(f[2], hv[6], lv[6]); split1(f[3], hv[7], lv[7]);
                __nv_bfloat162 t0 = __nv_bfloat162(hv[0], hv[1]);
                __nv_bfloat162 t1 = __nv_bfloat162(hv[2], hv[3]);
                __nv_bfloat162 t2v = __nv_bfloat162(hv[4], hv[5]);
                __nv_bfloat162 t3 = __nv_bfloat162(hv[6], hv[7]);
                ph[0] = *(uint32_t*)&t0; ph[1] = *(uint32_t*)&t1;
                ph[2] = *(uint32_t*)&t2v; ph[3] = *(uint32_t*)&t3;
                t0 = __nv_bfloat162(lv[0], lv[1]);
                t1 = __nv_bfloat162(lv[2], lv[3]);
                t2v = __nv_bfloat162(lv[4], lv[5]);
                t3 = __nv_bfloat162(lv[6], lv[7]);
                pl[0] = *(uint32_t*)&t0; pl[1] = *(uint32_t*)&t1;
                pl[2] = *(uint32_t*)&t2v; pl[3] = *(uint32_t*)&t3;
            }
            #pragma unroll
            for (int j = 0; j < 8; j++) {
                const int off = (j * 8 + g) * FP + t2 * 16 + kq;
                uint32_t vh[2], vl[2];
                vh[0] = *(const uint32_t*)(sVh + off);
                vh[1] = *(const uint32_t*)(sVh + off + 8);
                vl[0] = *(const uint32_t*)(sVl + off);
                vl[1] = *(const uint32_t*)(sVl + off + 8);
                mma16816(o[j], ph, vh);
                mma16816(o[j], pl, vh);
                mma16816(o[j], ph, vl);
            }
        }

        if (t + 2 < ntiles) {
            __syncthreads();              // all reads of stage st complete
            issue(st, (t + 2) * 64);      // refill; overlaps compute of t+1
        }
    }

    const float inv0 = 1.0f / l0;
    const float inv1 = 1.0f / l1;
    const int row = q0 + w * 16 + g;
    const size_t t0 = (size_t)(b * S + row);
    const size_t t8 = t0 + 8;
    #pragma unroll
    for (int j = 0; j < 8; j++) {
        const int col = h * DH + j * 8 + kq;
        float v0 = o[j][0] * inv0, v1 = o[j][1] * inv0;
        float v2 = o[j][2] * inv1, v3 = o[j][3] * inv1;
        __nv_bfloat16 h0, h1, h2, h3, l0b, l1b, l2b, l3b;
        split1(v0, h0, l0b); split1(v1, h1, l1b);
        split1(v2, h2, l2b); split1(v3, h3, l3b);
        *(__nv_bfloat162*)(Oh + t0 * DM + col) = __nv_bfloat162(h0, h1);
        *(__nv_bfloat162*)(Ol + t0 * DM + col) = __nv_bfloat162(l0b, l1b);
        *(__nv_bfloat162*)(Oh + t8 * DM + col) = __nv_bfloat162(h2, h3);
        *(__nv_bfloat162*)(Ol + t8 * DM + col) = __nv_bfloat162(l2b, l3b);
    }
}

// ----------------------------------------------------------------------------
// Launch
// ----------------------------------------------------------------------------
extern "C" void kernel_launch(void* const* d_in, const int* in_sizes, int n_in,
                              void* d_out, int out_size) {
    const float* X     = (const float*)d_in[0];
    const float* W_qkv = (const float*)d_in[1];
    const float* W_o   = (const float*)d_in[2];
    const float* W_fc1 = (const float*)d_in[3];
    const float* W_fc2 = (const float*)d_in[4];
    const float* ln1_w = (const float*)d_in[5];
    const float* ln2_w = (const float*)d_in[6];
    float* out = (float*)d_out;

    float *p_X1;
    __nv_bfloat16 *p_Xnh, *p_Xnl, *p_atth, *p_attl, *p_hh, *p_hl;
    __nv_bfloat16 *p_Wqh, *p_Wql, *p_Woh, *p_Wol, *p_Wf1h, *p_Wf1l, *p_Wf2h, *p_Wf2l;
    __nv_bfloat16 *p_Qh, *p_Ql, *p_Kh, *p_Kl, *p_Vth, *p_Vtl;
    cudaGetSymbolAddress((void**)&p_X1,  g_X1);
    cudaGetSymbolAddress((void**)&p_Xnh,  g_Xnh);
    cudaGetSymbolAddress((void**)&p_Xnl,  g_Xnl);
    cudaGetSymbolAddress((void**)&p_atth, g_atth);
    cudaGetSymbolAddress((void**)&p_attl, g_attl);
    cudaGetSymbolAddress((void**)&p_hh,   g_hh);
    cudaGetSymbolAddress((void**)&p_hl,   g_hl);
    cudaGetSymbolAddress((void**)&p_Wqh,  g_Wqh);
    cudaGetSymbolAddress((void**)&p_Wql,  g_Wql);
    cudaGetSymbolAddress((void**)&p_Woh,  g_Woh);
    cudaGetSymbolAddress((void**)&p_Wol,  g_Wol);
    cudaGetSymbolAddress((void**)&p_Wf1h, g_Wf1h);
    cudaGetSymbolAddress((void**)&p_Wf1l, g_Wf1l);
    cudaGetSymbolAddress((void**)&p_Wf2h, g_Wf2h);
    cudaGetSymbolAddress((void**)&p_Wf2l, g_Wf2l);
    cudaGetSymbolAddress((void**)&p_Qh,  g_Qh);
    cudaGetSymbolAddress((void**)&p_Ql,  g_Ql);
    cudaGetSymbolAddress((void**)&p_Kh,  g_Kh);
    cudaGetSymbolAddress((void**)&p_Kl,  g_Kl);
    cudaGetSymbolAddress((void**)&p_Vth, g_Vth);
    cudaGetSymbolAddress((void**)&p_Vtl, g_Vtl);

    const int smemBytes = STAGES * 4 * SEGB; // 81920 -> 2 CTAs/SM
    cudaFuncSetAttribute(gemm_bf16s<1>, cudaFuncAttributeMaxDynamicSharedMemorySize, smemBytes);
    cudaFuncSetAttribute(gemm_bf16s<2>, cudaFuncAttributeMaxDynamicSharedMemorySize, smemBytes);
    cudaFuncSetAttribute(gemm_bf16s<3>, cudaFuncAttributeMaxDynamicSharedMemorySize, smemBytes);
    cudaFuncSetAttribute(flash_mma, cudaFuncAttributeMaxDynamicSharedMemorySize, FSMEM);

    // weight splits (fc1 interleaved for fused GEGLU)
    split_kernel<<<(QKV3 * DM / 4 + 255) / 256, 256>>>(W_qkv, p_Wqh, p_Wql, QKV3 * DM / 4);
    split_kernel<<<(DM * DM / 4 + 255) / 256, 256>>>(W_o, p_Woh, p_Wol, DM * DM / 4);
    split_ilv_kernel<<<(FFN2 * DM / 4 + 255) / 256, 256>>>(W_fc1, p_Wf1h, p_Wf1l, FFN2 * DM / 4);
    split_kernel<<<(DM * FFN / 4 + 255) / 256, 256>>>(W_fc2, p_Wf2h, p_Wf2l, DM * FFN / 4);

    // 1. LN1
    ln_split_kernel<<<T, 256>>>(X, ln1_w, p_Xnh, p_Xnl);
    // 2+3. qkv GEMM with fused reshape/split epilogue
    gemm_bf16s<3><<<dim3(QKV3 / 128, T / 128), 256, smemBytes>>>(
        p_Xnh, p_Xnl, p_Wqh, p_Wql, nullptr, nullptr,
        p_Qh, p_Ql, p_Kh, p_Kl, p_Vth, p_Vtl, T, QKV3, DM);
    // 4. attention (pipelined K/V loads)
    flash_mma<<<dim3(S / 128, NH, B), 256, FSMEM>>>(p_Qh, p_Ql, p_Kh, p_Kl, p_Vth, p_Vtl,
                                                    p_atth, p_attl);
    // 5. X1 = X + attn @ W_o^T
    gemm_bf16s<1><<<dim3(DM / 128, T / 128), 256, smemBytes>>>(
        p_atth, p_attl, p_Woh, p_Wol, X, p_X1,
        nullptr, nullptr, nullptr, nullptr, nullptr, nullptr, T, DM, DM);
    // 6. LN2
    ln_split_kernel<<<T, 256>>>(p_X1, ln2_w, p_Xnh, p_Xnl);
    // 7+8. h = geglu(Xn @ W_fc1_interleaved^T)
    gemm_bf16s<2><<<dim3(FFN2 / 128, T / 128), 256, smemBytes>>>(
        p_Xnh, p_Xnl, p_Wf1h, p_Wf1l, nullptr, nullptr,
        p_hh, p_hl, nullptr, nullptr, nullptr, nullptr, T, FFN2, DM);
    // 9. out = X1 + h @ W_fc2^T
    gemm_bf16s<1><<<dim3(DM / 128, T / 128), 256, smemBytes>>>(
        p_hh, p_hl, p_Wf2h, p_Wf2l, p_X1, out,
        nullptr, nullptr, nullptr, nullptr, nullptr, nullptr, T, DM, FFN);
}

// round 16
// speedup vs baseline: 2.7727x; 1.0467x over previous
#include <cuda_runtime.h>
#include <cuda_bf16.h>
#include <math.h>
#include <stdint.h>

// ----------------------------------------------------------------------------
// Problem constants
// ----------------------------------------------------------------------------
#define B        4
#define S        2048
#define T        (B * S)          // 8192 tokens
#define DM       1024             // d_model
#define NH       16               // heads
#define DH       64               // head dim
#define QKV3     (3 * NH * DH)    // 3072
#define FFN      4096
#define FFN2     (2 * FFN)        // 8192

// ----------------------------------------------------------------------------
// Scratch (device globals -> no allocation inside kernel_launch)
// ----------------------------------------------------------------------------
__device__ float g_X1  [(size_t)T * DM];    // X + attn @ Wo^T

__device__ __nv_bfloat16 g_Xnh [(size_t)T * DM];
__device__ __nv_bfloat16 g_Xnl [(size_t)T * DM];
__device__ __nv_bfloat16 g_atth[(size_t)T * DM];
__device__ __nv_bfloat16 g_attl[(size_t)T * DM];
__device__ __nv_bfloat16 g_hh  [(size_t)T * FFN];
__device__ __nv_bfloat16 g_hl  [(size_t)T * FFN];
__device__ __nv_bfloat16 g_Wqh [(size_t)QKV3 * DM];
__device__ __nv_bfloat16 g_Wql [(size_t)QKV3 * DM];
__device__ __nv_bfloat16 g_Woh [(size_t)DM * DM];
__device__ __nv_bfloat16 g_Wol [(size_t)DM * DM];
__device__ __nv_bfloat16 g_Wf1h[(size_t)FFN2 * DM];   // row-interleaved (a0,g0,a1,g1,...)
__device__ __nv_bfloat16 g_Wf1l[(size_t)FFN2 * DM];
__device__ __nv_bfloat16 g_Wf2h[(size_t)DM * FFN];
__device__ __nv_bfloat16 g_Wf2l[(size_t)DM * FFN];
__device__ __nv_bfloat16 g_Qh [(size_t)T * DM];   // [b,h,s,d]  (pre-scaled 1/8)
__device__ __nv_bfloat16 g_Ql [(size_t)T * DM];
__device__ __nv_bfloat16 g_Kh [(size_t)T * DM];   // [b,h,s,d]
__device__ __nv_bfloat16 g_Kl [(size_t)T * DM];
__device__ __nv_bfloat16 g_Vth[(size_t)T * DM];   // [b,h,d,s]  (transposed)
__device__ __nv_bfloat16 g_Vtl[(size_t)T * DM];

// ----------------------------------------------------------------------------
// fp32 -> (hi, lo) bf16 split
// ----------------------------------------------------------------------------
__device__ __forceinline__ void split1(float x, __nv_bfloat16& h, __nv_bfloat16& l) {
    h = __float2bfloat16_rn(x);
    l = __float2bfloat16_rn(x - __bfloat162float(h));
}

// ----------------------------------------------------------------------------
// Fast exp on FMA pipe (no MUFU). rel err < 3e-8 on clamped range.
// ----------------------------------------------------------------------------
__device__ __forceinline__ float fexp(float x) {
    x = fminf(fmaxf(x, -87.0f), 87.0f);
    const float y = x * 1.4426950408889634f;
    const float z = y + 12582912.0f;
    const int   n = __float_as_int(z) - 0x4B400000;
    const float f = y - (z - 12582912.0f);
    float p = 1.5403530393381609e-4f;
    p = fmaf(p, f, 1.3333558146428443e-3f);
    p = fmaf(p, f, 9.6181291076284772e-3f);
    p = fmaf(p, f, 5.5504108664821580e-2f);
    p = fmaf(p, f, 2.4022650695910072e-1f);
    p = fmaf(p, f, 6.9314718055994531e-1f);
    p = fmaf(p, f, 1.0f);
    return __int_as_float(__float_as_int(p) + (n << 23));
}

__device__ __forceinline__ float frcp(float x) {
    float r;
    asm("rcp.approx.f32 %0, %1;" : "=f"(r) : "f"(x));
    return r;
}

// GEGLU scalar
__device__ __forceinline__ float geglu1(float a, float g) {
    const float z = 0.7978845608028654f * (g + 0.044715f * g * g * g);
    const float ew = fexp(-2.0f * z);
    return a * g * frcp(1.0f + ew);
}

// ----------------------------------------------------------------------------
// Async copy + ldmatrix helpers
// ----------------------------------------------------------------------------
__device__ __forceinline__ void cpasync16(uint32_t dst, const void* src) {
    asm volatile("cp.async.cg.shared.global [%0], [%1], 16;" :: "r"(dst), "l"(src));
}
__device__ __forceinline__ void cp_commit() {
    asm volatile("cp.async.commit_group;");
}
__device__ __forceinline__ void ldsm4(uint32_t* r, uint32_t a) {
    asm volatile("ldmatrix.sync.aligned.m8n8.x4.shared.b16 {%0,%1,%2,%3}, [%4];"
        : "=r"(r[0]), "=r"(r[1]), "=r"(r[2]), "=r"(r[3]) : "r"(a));
}

// ----------------------------------------------------------------------------
// qkv epilogue scatter (validated round 13)
// ----------------------------------------------------------------------------
__device__ __forceinline__ void scatter_qkv(int t, int cc, float v,
                                            __nv_bfloat16* __restrict__ Qh,
                                            __nv_bfloat16* __restrict__ Ql,
                                            __nv_bfloat16* __restrict__ Kh,
                                            __nv_bfloat16* __restrict__ Kl,
                                            __nv_bfloat16* __restrict__ Vth,
                                            __nv_bfloat16* __restrict__ Vtl) {
    const int h   = cc / 192;
    const int rem = cc - h * 192;
    const int d   = rem / 3;
    const int c   = rem - d * 3;
    const int b   = t >> 11;
    const int s   = t & 2047;
    __nv_bfloat16 hh, ll;
    if (c == 0) {
        split1(v * 0.125f, hh, ll);
        const size_t qk = (((size_t)(b * NH + h)) * S + s) * DH + d;
        Qh[qk] = hh; Ql[qk] = ll;
    } else if (c == 1) {
        split1(v, hh, ll);
        const size_t qk = (((size_t)(b * NH + h)) * S + s) * DH + d;
        Kh[qk] = hh; Kl[qk] = ll;
    } else {
        split1(v, hh, ll);
        const size_t vt = (((size_t)(b * NH + h)) * DH + d) * S + s;
        Vth[vt] = hh; Vtl[vt] = ll;
    }
}

// ----------------------------------------------------------------------------
// Weight split: float4-vectorized
// ----------------------------------------------------------------------------
__global__ __launch_bounds__(256) void split_kernel(const float* __restrict__ X,
                                                    __nv_bfloat16* __restrict__ H,
                                                    __nv_bfloat16* __restrict__ L,
                                                    int n4) {
    const int gid = blockIdx.x * 256 + threadIdx.x;
    if (gid >= n4) return;
    const float4 v = ((const float4*)X)[gid];
    __nv_bfloat16 h0, h1, h2, h3, l0, l1, l2, l3;
    split1(v.x, h0, l0); split1(v.y, h1, l1);
    split1(v.z, h2, l2); split1(v.w, h3, l3);
    __nv_bfloat162* Hp = (__nv_bfloat162*)H;
    __nv_bfloat162* Lp = (__nv_bfloat162*)L;
    Hp[gid * 2]     = __nv_bfloat162(h0, h1);
    Hp[gid * 2 + 1] = __nv_bfloat162(h2, h3);
    Lp[gid * 2]     = __nv_bfloat162(l0, l1);
    Lp[gid * 2 + 1] = __nv_bfloat162(l2, l3);
}

// ----------------------------------------------------------------------------
// W_fc1 split with row interleave
// ----------------------------------------------------------------------------
__global__ __launch_bounds__(256) void split_ilv_kernel(const float* __restrict__ X,
                                                        __nv_bfloat16* __restrict__ H,
                                                        __nv_bfloat16* __restrict__ L,
                                                        int n4) {
    const int gid = blockIdx.x * 256 + threadIdx.x;
    if (gid >= n4) return;
    const int e0   = gid * 4;
    const int srow = e0 >> 10;
    const int col  = e0 & 1023;
    const int drow = (srow < FFN) ? (srow * 2) : ((srow - FFN) * 2 + 1);
    const float4 v = ((const float4*)X)[gid];
    __nv_bfloat16 h0, h1, h2, h3, l0, l1, l2, l3;
    split1(v.x, h0, l0); split1(v.y, h1, l1);
    split1(v.z, h2, l2); split1(v.w, h3, l3);
    const size_t d4 = ((size_t)drow * DM + col) >> 1;
    __nv_bfloat162* Hp = (__nv_bfloat162*)H;
    __nv_bfloat162* Lp = (__nv_bfloat162*)L;
    Hp[d4]     = __nv_bfloat162(h0, h1);
    Hp[d4 + 1] = __nv_bfloat162(h2, h3);
    Lp[d4]     = __nv_bfloat162(l0, l1);
    Lp[d4 + 1] = __nv_bfloat162(l2, l3);
}

// ----------------------------------------------------------------------------
// LayerNorm with fused hi/lo split output
// ----------------------------------------------------------------------------
__global__ __launch_bounds__(256) void ln_split_kernel(const float* __restrict__ X,
                                                       const float* __restrict__ w,
                                                       __nv_bfloat16* __restrict__ Hh,
                                                       __nv_bfloat16* __restrict__ Hl) {
    const int row = blockIdx.x;
    const int tid = threadIdx.x;
    const float4* xp = (const float4*)(X + (size_t)row * DM);
    float4 v = xp[tid];

    float s  = v.x + v.y + v.z + v.w;
    float sq = v.x * v.x + v.y * v.y + v.z * v.z + v.w * v.w;

    __shared__ float rs[256];
    __shared__ float rq[256];
    rs[tid] = s; rq[tid] = sq;
    __syncthreads();
    #pragma unroll
    for (int o = 128; o >= 1; o >>= 1) {
        if (tid < o) { rs[tid] += rs[tid + o]; rq[tid] += rq[tid + o]; }
        __syncthreads();
    }
    const float mu   = rs[0] * (1.0f / DM);
    const float var  = rq[0] * (1.0f / DM) - mu * mu;
    const float rstd = rsqrtf(var + 1e-5f);

    const float4 wv = ((const float4*)w)[tid];
    float y0 = (v.x - mu) * rstd * wv.x;
    float y1 = (v.y - mu) * rstd * wv.y;
    float y2 = (v.z - mu) * rstd * wv.z;
    float y3 = (v.w - mu) * rstd * wv.w;

    __nv_bfloat16 h0, h1, h2, h3, l0, l1, l2, l3;
    split1(y0, h0, l0); split1(y1, h1, l1);
    split1(y2, h2, l2); split1(y3, h3, l3);
    __nv_bfloat162* Hp = (__nv_bfloat162*)(Hh + (size_t)row * DM);
    __nv_bfloat162* Lp = (__nv_bfloat162*)(Hl + (size_t)row * DM);
    Hp[tid * 2]     = __nv_bfloat162(h0, h1);
    Hp[tid * 2 + 1] = __nv_bfloat162(h2, h3);
    Lp[tid * 2]     = __nv_bfloat162(l0, l1);
    Lp[tid * 2 + 1] = __nv_bfloat162(l2, l3);
}

// ----------------------------------------------------------------------------
// mma.sync m16n8k16 bf16 -> fp32
// ----------------------------------------------------------------------------
__device__ __forceinline__ void mma16816(float* c, const uint32_t* a, const uint32_t* b) {
    asm volatile(
        "mma.sync.aligned.m16n8k16.row.col.f32.bf16.bf16.f32 "
        "{%0,%1,%2,%3},{%4,%5,%6,%7},{%8,%9},{%0,%1,%2,%3};"
        : "+f"(c[0]), "+f"(c[1]), "+f"(c[2]), "+f"(c[3])
        : "r"(a[0]), "r"(a[1]), "r"(a[2]), "r"(a[3]), "r"(b[0]), "r"(b[1]));
}

// ----------------------------------------------------------------------------
// Split-bf16 NT GEMM: 2-stage cp.async pipeline + ldmatrix, 2 CTAs/SM.
// B fragments via ldsm4 (paired j-tiles): 4 LDSM instead of 8 per chunk.
// EPI 0: C=AB  EPI 1: C=R+AB  EPI 2: fused GEGLU  EPI 3: fused qkv scatter
// ----------------------------------------------------------------------------
#define STAGES 2
#define PITCH  40
#define SEGB   (128 * PITCH * 2)   // 10240

template <int EPI>
__global__ __launch_bounds__(256, 2) void gemm_bf16s(const __nv_bfloat16* __restrict__ Ah,
                                                     const __nv_bfloat16* __restrict__ Al,
                                                     const __nv_bfloat16* __restrict__ Bh,
                                                     const __nv_bfloat16* __restrict__ Bl,
                                                     const float* __restrict__ R,
                                                     float* __restrict__ C,
                                                     __nv_bfloat16* __restrict__ P0,
                                                     __nv_bfloat16* __restrict__ P1,
                                                     __nv_bfloat16* __restrict__ P2,
                                                     __nv_bfloat16* __restrict__ P3,
                                                     __nv_bfloat16* __restrict__ P4,
                                                     __nv_bfloat16* __restrict__ P5,
                                                     int M, int N, int K) {
    extern __shared__ __nv_bfloat16 smem[];
    const uint32_t sbase = (uint32_t)__cvta_generic_to_shared(smem);

    const int tid  = threadIdx.x;
    const int lane = tid & 31;
    const int warp = tid >> 5;
    const int wm   = warp >> 2;
    const int wn   = warp & 3;

    const int m0 = blockIdx.y * 128;
    const int n0 = blockIdx.x * 128;

    const int r0 = tid >> 2;
    const int r1 = r0 + 64;
    const int c0 = (tid & 3) * 8;

    const size_t aOff0 = (size_t)(m0 + r0) * K + c0;
    const size_t aOff1 = (size_t)(m0 + r1) * K + c0;
    const size_t bOff0 = (size_t)(n0 + r0) * K + c0;
    const size_t bOff1 = (size_t)(n0 + r1) * K + c0;
    const uint32_t d0 = (uint32_t)(r0 * PITCH + c0) * 2;
    const uint32_t d1 = (uint32_t)(r1 * PITCH + c0) * 2;

    const uint32_t aRowB = (uint32_t)(((wm * 64 + (lane & 15)) * PITCH
                                       + ((lane >> 4) << 3)) * 2);
    const uint32_t bRow4B = (uint32_t)(((wn * 32 + (lane & 7) + (((lane >> 4) & 1) << 3)) * PITCH
                                        + (((lane >> 3) & 1) << 3)) * 2);

    float acc[4][4][4];
    #pragma unroll
    for (int i = 0; i < 4; i++)
        #pragma unroll
        for (int j = 0; j < 4; j++)
            #pragma unroll
            for (int r = 0; r < 4; r++) acc[i][j][r] = 0.0f;

    const int ntiles = K >> 5;

    auto issue = [&](int st, int t) {
        const int k0 = t * 32;
        const uint32_t sb = sbase + (uint32_t)st * 4 * SEGB;
        cpasync16(sb + 0 * SEGB + d0, Ah + aOff0 + k0);
        cpasync16(sb + 0 * SEGB + d1, Ah + aOff1 + k0);
        cpasync16(sb + 1 * SEGB + d0, Al + aOff0 + k0);
        cpasync16(sb + 1 * SEGB + d1, Al + aOff1 + k0);
        cpasync16(sb + 2 * SEGB + d0, Bh + bOff0 + k0);
        cpasync16(sb + 2 * SEGB + d1, Bh + bOff1 + k0);
        cpasync16(sb + 3 * SEGB + d0, Bl + bOff0 + k0);
        cpasync16(sb + 3 * SEGB + d1, Bl + bOff1 + k0);
        cp_commit();
    };

    issue(0, 0);
    if (ntiles > 1) issue(1, 1);

    for (int t = 0; t < ntiles; t++) {
        const int st = t & 1;
        if (t + 1 < ntiles) {
            asm volatile("cp.async.wait_group 1;");
        } else {
            asm volatile("cp.async.wait_group 0;");
        }
        __syncthreads();

        const uint32_t sb  = sbase + (uint32_t)st * 4 * SEGB;
        const uint32_t pAh = sb;
        const uint32_t pAl = sb + 1 * SEGB;
        const uint32_t pBh = sb + 2 * SEGB;
        const uint32_t pBl = sb + 3 * SEGB;

        #pragma unroll
        for (int kc = 0; kc < 2; kc++) {
            const uint32_t kb = (uint32_t)kc * 32;
            uint32_t ah[4][4], al[4][4];
            uint32_t bfh[2][4], bfl[2][4];   // [j-pair][{j:k0, j:k8, j+1:k0, j+1:k8}]
            #pragma unroll
            for (int i = 0; i < 4; i++) {
                const uint32_t ao = aRowB + (uint32_t)i * (16 * PITCH * 2) + kb;
                ldsm4(ah[i], pAh + ao);
                ldsm4(al[i], pAl + ao);
            }
            #pragma unroll
            for (int jj = 0; jj < 2; jj++) {
                const uint32_t bo = bRow4B + (uint32_t)jj * (16 * PITCH * 2) + kb;
                ldsm4(bfh[jj], pBh + bo);
                ldsm4(bfl[jj], pBl + bo);
            }
            #pragma unroll
            for (int i = 0; i < 4; i++)
                #pragma unroll
                for (int j = 0; j < 4; j++)
                    mma16816(acc[i][j], ah[i], &bfh[j >> 1][(j & 1) * 2]);
            #pragma unroll
            for (int i = 0; i < 4; i++)
                #pragma unroll
                for (int j = 0; j < 4; j++)
                    mma16816(acc[i][j], al[i], &bfh[j >> 1][(j & 1) * 2]);
            #pragma unroll
            for (int i = 0; i < 4; i++)
                #pragma unroll
                for (int j = 0; j < 4; j++)
                    mma16816(acc[i][j], ah[i], &bfl[j >> 1][(j & 1) * 2]);
        }

        if (t + 2 < ntiles) {
            __syncthreads();
            issue(st, t + 2);
        }
    }

    // epilogue
    const int g = lane >> 2;
    #pragma unroll
    for (int i = 0; i < 4; i++) {
        const int row = m0 + wm * 64 + i * 16 + g;
        #pragma unroll
        for (int j = 0; j < 4; j++) {
            const int col = n0 + wn * 32 + j * 8 + (lane & 3) * 2;
            if (EPI == 3) {
                scatter_qkv(row,     col,     acc[i][j][0], P0, P1, P2, P3, P4, P5);
                scatter_qkv(row,     col + 1, acc[i][j][1], P0, P1, P2, P3, P4, P5);
                scatter_qkv(row + 8, col,     acc[i][j][2], P0, P1, P2, P3, P4, P5);
                scatter_qkv(row + 8, col + 1, acc[i][j][3], P0, P1, P2, P3, P4, P5);
            } else if (EPI == 2) {
                const int oc = col >> 1;
                const float v0 = geglu1(acc[i][j][0], acc[i][j][1]);
                const float v1 = geglu1(acc[i][j][2], acc[i][j][3]);
                __nv_bfloat16 h0, l0, h1, l1;
                split1(v0, h0, l0);
                split1(v1, h1, l1);
                const size_t o0 = (size_t)row * (N >> 1) + oc;
                const size_t o1 = (size_t)(row + 8) * (N >> 1) + oc;
                P0[o0] = h0; P1[o0] = l0;
                P0[o1] = h1; P1[o1] = l1;
            } else {
                const size_t o0 = (size_t)row * N + col;
                const size_t o1 = (size_t)(row + 8) * N + col;
                float2 v0 = {acc[i][j][0], acc[i][j][1]};
                float2 v1 = {acc[i][j][2], acc[i][j][3]};
                if (EPI == 1) {
                    const float2 r0v = *(const float2*)(R + o0);
                    const float2 r1v = *(const float2*)(R + o1);
                    v0.x += r0v.x; v0.y += r0v.y;
                    v1.x += r1v.x; v1.y += r1v.y;
                }
                *(float2*)(C + o0) = v0;
                *(float2*)(C + o1) = v1;
            }
        }
    }
}

// ----------------------------------------------------------------------------
// Tensor-core flash attention with double-buffered cp.async K/V loads
// (validated round 14).
// ----------------------------------------------------------------------------
#define FP    72
#define FSEG  (64 * FP)            // elements per array per stage
#define FSEGB (FSEG * 2)           // 9216 bytes
#define FBUFB (4 * FSEGB)          // 36864 bytes per stage
#define FSMEM (2 * FBUFB)          // 73728 bytes total

__global__ __launch_bounds__(256) void flash_mma(const __nv_bfloat16* __restrict__ Qh,
                                                 const __nv_bfloat16* __restrict__ Ql,
                                                 const __nv_bfloat16* __restrict__ Kh,
                                                 const __nv_bfloat16* __restrict__ Kl,
                                                 const __nv_bfloat16* __restrict__ Vth,
                                                 const __nv_bfloat16* __restrict__ Vtl,
                                                 __nv_bfloat16* __restrict__ Oh,
                                                 __nv_bfloat16* __restrict__ Ol) {
    extern __shared__ __nv_bfloat16 fsm[];
    const uint32_t fbase = (uint32_t)__cvta_generic_to_shared(fsm);

    const int tid  = threadIdx.x;
    const int lane = tid & 31;
    const int w    = tid >> 5;
    const int h    = blockIdx.y;
    const int b    = blockIdx.z;
    const int q0   = blockIdx.x * 128;
    const size_t bh  = (size_t)(b * NH + h) * S;
    const size_t bhd = (size_t)(b * NH + h) * DH;
    const int g  = lane >> 2;
    const int kq = (lane & 3) * 2;

    uint32_t qfh[4][4], qfl[4][4];
    {
        const int row = q0 + w * 16 + g;
        const __nv_bfloat16* b0h = Qh + (bh + row) * DH;
        const __nv_bfloat16* b8h = Qh + (bh + row + 8) * DH;
        const __nv_bfloat16* b0l = Ql + (bh + row) * DH;
        const __nv_bfloat16* b8l = Ql + (bh + row + 8) * DH;
        #pragma unroll
        for (int kc = 0; kc < 4; kc++) {
            const int o = kc * 16 + kq;
            qfh[kc][0] = *(const uint32_t*)(b0h + o);
            qfh[kc][1] = *(const uint32_t*)(b8h + o);
            qfh[kc][2] = *(const uint32_t*)(b0h + o + 8);
            qfh[kc][3] = *(const uint32_t*)(b8h + o + 8);
            qfl[kc][0] = *(const uint32_t*)(b0l + o);
            qfl[kc][1] = *(const uint32_t*)(b8l + o);
            qfl[kc][2] = *(const uint32_t*)(b0l + o + 8);
            qfl[kc][3] = *(const uint32_t*)(b8l + o + 8);
        }
    }

    float o[8][4];
    #pragma unroll
    for (int j = 0; j < 8; j++)
        #pragma unroll
        for (int r = 0; r < 4; r++) o[j][r] = 0.0f;
    float m0 = -INFINITY, m1 = -INFINITY;
    float l0 = 0.0f, l1 = 0.0f;

    const int i0 = tid, i1 = tid + 256;
    const int lr0 = i0 >> 3, lc0 = (i0 & 7) * 8;
    const int lr1 = i1 >> 3, lc1 = (i1 & 7) * 8;
    const uint32_t fd00 = (uint32_t)(lr0 * FP + lc0) * 2;
    const uint32_t fd01 = (uint32_t)(lr1 * FP + lc1) * 2;

    auto issue = [&](int st, int kt) {
        const uint32_t sb = fbase + (uint32_t)st * FBUFB;
        cpasync16(sb + 0 * FSEGB + fd00, Kh + (bh + kt + lr0) * DH + lc0);
        cpasync16(sb + 0 * FSEGB + fd01, Kh + (bh + kt + lr1) * DH + lc1);
        cpasync16(sb + 1 * FSEGB + fd00, Kl + (bh + kt + lr0) * DH + lc0);
        cpasync16(sb + 1 * FSEGB + fd01, Kl + (bh + kt + lr1) * DH + lc1);
        cpasync16(sb + 2 * FSEGB + fd00, Vth + (bhd + lr0) * S + kt + lc0);
        cpasync16(sb + 2 * FSEGB + fd01, Vth + (bhd + lr1) * S + kt + lc1);
        cpasync16(sb + 3 * FSEGB + fd00, Vtl + (bhd + lr0) * S + kt + lc0);
        cpasync16(sb + 3 * FSEGB + fd01, Vtl + (bhd + lr1) * S + kt + lc1);
        cp_commit();
    };

    const int ntiles = S / 64;
    issue(0, 0);
    issue(1, 64);

    for (int t = 0; t < ntiles; t++) {
        const int st = t & 1;
        if (t + 1 < ntiles) {
            asm volatile("cp.async.wait_group 1;");
        } else {
            asm volatile("cp.async.wait_group 0;");
        }
        __syncthreads();

        const __nv_bfloat16* sKh = fsm + (size_t)st * 4 * FSEG;
        const __nv_bfloat16* sKl = sKh + FSEG;
        const __nv_bfloat16* sVh = sKh + 2 * FSEG;
        const __nv_bfloat16* sVl = sKh + 3 * FSEG;

        float sc[8][4];
        #pragma unroll
        for (int j = 0; j < 8; j++)
            #pragma unroll
            for (int r = 0; r < 4; r++) sc[j][r] = 0.0f;

        #pragma unroll
        for (int kc = 0; kc < 4; kc++) {
            #pragma unroll
            for (int j = 0; j < 8; j++) {
                const int off = (j * 8 + g) * FP + kc * 16 + kq;
                uint32_t kb[2], klo[2];
                kb[0]  = *(const uint32_t*)(sKh + off);
                kb[1]  = *(const uint32_t*)(sKh + off + 8);
                klo[0] = *(const uint32_t*)(sKl + off);
                klo[1] = *(const uint32_t*)(sKl + off + 8);
                mma16816(sc[j], qfh[kc], kb);
                mma16816(sc[j], qfl[kc], kb);
                mma16816(sc[j], qfh[kc], klo);
            }
        }

        float mx0 = sc[0][0], mx1 = sc[0][2];
        #pragma unroll
        for (int j = 0; j < 8; j++) {
            mx0 = fmaxf(mx0, fmaxf(sc[j][0], sc[j][1]));
            mx1 = fmaxf(mx1, fmaxf(sc[j][2], sc[j][3]));
        }
        mx0 = fmaxf(mx0, __shfl_xor_sync(0xffffffffu, mx0, 1));
        mx0 = fmaxf(mx0, __shfl_xor_sync(0xffffffffu, mx0, 2));
        mx1 = fmaxf(mx1, __shfl_xor_sync(0xffffffffu, mx1, 1));
        mx1 = fmaxf(mx1, __shfl_xor_sync(0xffffffffu, mx1, 2));

        const float mn0 = fmaxf(m0, mx0);
        const float mn1 = fmaxf(m1, mx1);
        const float c0 = fexp(m0 - mn0);
        const float c1 = fexp(m1 - mn1);
        m0 = mn0; m1 = mn1;

        float s0 = 0.0f, s1 = 0.0f;
        #pragma unroll
        for (int j = 0; j < 8; j++) {
            sc[j][0] = fexp(sc[j][0] - mn0);
            sc[j][1] = fexp(sc[j][1] - mn0);
            sc[j][2] = fexp(sc[j][2] - mn1);
            sc[j][3] = fexp(sc[j][3] - mn1);
            s0 += sc[j][0] + sc[j][1];
            s1 += sc[j][2] + sc[j][3];
        }
        s0 += __shfl_xor_sync(0xffffffffu, s0, 1);
        s0 += __shfl_xor_sync(0xffffffffu, s0, 2);
        s1 += __shfl_xor_sync(0xffffffffu, s1, 1);
        s1 += __shfl_xor_sync(0xffffffffu, s1, 2);
        l0 = l0 * c0 + s0;
        l1 = l1 * c1 + s1;

        #pragma unroll
        for (int j = 0; j < 8; j++) {
            o[j][0] *= c0; o[j][1] *= c0;
            o[j][2] *= c1; o[j][3] *= c1;
        }

        #pragma unroll
        for (int t2 = 0; t2 < 4; t2++) {
            uint32_t ph[4], pl[4];
            {
                const float* e = sc[2 * t2];
                const float* f = sc[2 * t2 + 1];
                __nv_bfloat16 hv[8], lv[8];
                split1(e[0], hv[0], lv[0]); split1(e[1], hv[1], lv[1]);
                split1(e[2], hv[2], lv[2]); split1(e[3], hv[3], lv[3]);
                split1(f[0], hv[4], lv[4]); split1(f[1], hv[5], lv[5]);
                split1(f[2], hv[6], lv[6]); split1(f[3], hv[7], lv[7]);
                __nv_bfloat162 t0 = __nv_bfloat162(hv[0], hv[1]);
                __nv_bfloat162 t1 = __nv_bfloat162(hv[2], hv[3]);
                __nv_bfloat162 t2v = __nv_bfloat162(hv[4], hv[5]);
                __nv_bfloat162 t3 = __nv_bfloat162(hv[6], hv[7]);
                ph[0] = *(uint32_t*)&t0; ph[1] = *(uint32_t*)&t1;
                ph[2] = *(uint32_t*)&t2v; ph[3] = *(uint32_t*)&t3;
                t0 = __nv_bfloat162(lv[0], lv[1]);
                t1 = __nv_bfloat162(lv[2], lv[3]);
                t2v = __nv_bfloat162(lv[4], lv[5]);
                t3 = __nv_bfloat162(lv[6], lv[7]);
                pl[0] = *(uint32_t*)&t0; pl[1] = *(uint32_t*)&t1;
                pl[2] = *(uint32_t*)&t2v; pl[3] = *(uint32_t*)&t3;
            }
            #pragma unroll
            for (int j = 0; j < 8; j++) {
                const int off = (j * 8 + g) * FP + t2 * 16 + kq;
                uint32_t vh[2], vl[2];
                vh[0] = *(const uint32_t*)(sVh + off);
                vh[1] = *(const uint32_t*)(sVh + off + 8);
                vl[0] = *(const uint32_t*)(sVl + off);
                vl[1] = *(const uint32_t*)(sVl + off + 8);
                mma16816(o[j], ph, vh);
                mma16816(o[j], pl, vh);
                mma16816(o[j], ph, vl);
            }
        }

        if (t + 2 < ntiles) {
            __syncthreads();
            issue(st, (t + 2) * 64);
        }
    }

    const float inv0 = 1.0f / l0;
    const float inv1 = 1.0f / l1;
    const int row = q0 + w * 16 + g;
    const size_t t0 = (size_t)(b * S + row);
    const size_t t8 = t0 + 8;
    #pragma unroll
    for (int j = 0; j < 8; j++) {
        const int col = h * DH + j * 8 + kq;
        float v0 = o[j][0] * inv0, v1 = o[j][1] * inv0;
        float v2 = o[j][2] * inv1, v3 = o[j][3] * inv1;
        __nv_bfloat16 h0, h1, h2, h3, l0b, l1b, l2b, l3b;
        split1(v0, h0, l0b); split1(v1, h1, l1b);
        split1(v2, h2, l2b); split1(v3, h3, l3b);
        *(__nv_bfloat162*)(Oh + t0 * DM + col) = __nv_bfloat162(h0, h1);
        *(__nv_bfloat162*)(Ol + t0 * DM + col) = __nv_bfloat162(l0b, l1b);
        *(__nv_bfloat162*)(Oh + t8 * DM + col) = __nv_bfloat162(h2, h3);
        *(__nv_bfloat162*)(Ol + t8 * DM + col) = __nv_bfloat162(l2b, l3b);
    }
}

// ----------------------------------------------------------------------------
// Launch
// ----------------------------------------------------------------------------
extern "C" void kernel_launch(void* const* d_in, const int* in_sizes, int n_in,
                              void* d_out, int out_size) {
    const float* X     = (const float*)d_in[0];
    const float* W_qkv = (const float*)d_in[1];
    const float* W_o   = (const float*)d_in[2];
    const float* W_fc1 = (const float*)d_in[3];
    const float* W_fc2 = (const float*)d_in[4];
    const float* ln1_w = (const float*)d_in[5];
    const float* ln2_w = (const float*)d_in[6];
    float* out = (float*)d_out;

    float *p_X1;
    __nv_bfloat16 *p_Xnh, *p_Xnl, *p_atth, *p_attl, *p_hh, *p_hl;
    __nv_bfloat16 *p_Wqh, *p_Wql, *p_Woh, *p_Wol, *p_Wf1h, *p_Wf1l, *p_Wf2h, *p_Wf2l;
    __nv_bfloat16 *p_Qh, *p_Ql, *p_Kh, *p_Kl, *p_Vth, *p_Vtl;
    cudaGetSymbolAddress((void**)&p_X1,  g_X1);
    cudaGetSymbolAddress((void**)&p_Xnh,  g_Xnh);
    cudaGetSymbolAddress((void**)&p_Xnl,  g_Xnl);
    cudaGetSymbolAddress((void**)&p_atth, g_atth);
    cudaGetSymbolAddress((void**)&p_attl, g_attl);
    cudaGetSymbolAddress((void**)&p_hh,   g_hh);
    cudaGetSymbolAddress((void**)&p_hl,   g_hl);
    cudaGetSymbolAddress((void**)&p_Wqh,  g_Wqh);
    cudaGetSymbolAddress((void**)&p_Wql,  g_Wql);
    cudaGetSymbolAddress((void**)&p_Woh,  g_Woh);
    cudaGetSymbolAddress((void**)&p_Wol,  g_Wol);
    cudaGetSymbolAddress((void**)&p_Wf1h, g_Wf1h);
    cudaGetSymbolAddress((void**)&p_Wf1l, g_Wf1l);
    cudaGetSymbolAddress((void**)&p_Wf2h, g_Wf2h);
    cudaGetSymbolAddress((void**)&p_Wf2l, g_Wf2l);
    cudaGetSymbolAddress((void**)&p_Qh,  g_Qh);
    cudaGetSymbolAddress((void**)&p_Ql,  g_Ql);
    cudaGetSymbolAddress((void**)&p_Kh,  g_Kh);
    cudaGetSymbolAddress((void**)&p_Kl,  g_Kl);
    cudaGetSymbolAddress((void**)&p_Vth, g_Vth);
    cudaGetSymbolAddress((void**)&p_Vtl, g_Vtl);

    const int smemBytes = STAGES * 4 * SEGB; // 81920 -> 2 CTAs/SM
    cudaFuncSetAttribute(gemm_bf16s<1>, cudaFuncAttributeMaxDynamicSharedMemorySize, smemBytes);
    cudaFuncSetAttribute(gemm_bf16s<2>, cudaFuncAttributeMaxDynamicSharedMemorySize, smemBytes);
    cudaFuncSetAttribute(gemm_bf16s<3>, cudaFuncAttributeMaxDynamicSharedMemorySize, smemBytes);
    cudaFuncSetAttribute(flash_mma, cudaFuncAttributeMaxDynamicSharedMemorySize, FSMEM);

    // weight splits (fc1 interleaved for fused GEGLU)
    split_kernel<<<(QKV3 * DM / 4 + 255) / 256, 256>>>(W_qkv, p_Wqh, p_Wql, QKV3 * DM / 4);
    split_kernel<<<(DM * DM / 4 + 255) / 256, 256>>>(W_o, p_Woh, p_Wol, DM * DM / 4);
    split_ilv_kernel<<<(FFN2 * DM / 4 + 255) / 256, 256>>>(W_fc1, p_Wf1h, p_Wf1l, FFN2 * DM / 4);
    split_kernel<<<(DM * FFN / 4 + 255) / 256, 256>>>(W_fc2, p_Wf2h, p_Wf2l, DM * FFN / 4);

    // 1. LN1
    ln_split_kernel<<<T, 256>>>(X, ln1_w, p_Xnh, p_Xnl);
    // 2+3. qkv GEMM with fused reshape/split epilogue
    gemm_bf16s<3><<<dim3(QKV3 / 128, T / 128), 256, smemBytes>>>(
        p_Xnh, p_Xnl, p_Wqh, p_Wql, nullptr, nullptr,
        p_Qh, p_Ql, p_Kh, p_Kl, p_Vth, p_Vtl, T, QKV3, DM);
    // 4. attention (pipelined K/V loads)
    flash_mma<<<dim3(S / 128, NH, B), 256, FSMEM>>>(p_Qh, p_Ql, p_Kh, p_Kl, p_Vth, p_Vtl,
                                                    p_atth, p_attl);
    // 5. X1 = X + attn @ W_o^T
    gemm_bf16s<1><<<dim3(DM / 128, T / 128), 256, smemBytes>>>(
        p_atth, p_attl, p_Woh, p_Wol, X, p_X1,
        nullptr, nullptr, nullptr, nullptr, nullptr, nullptr, T, DM, DM);
    // 6. LN2
    ln_split_kernel<<<T, 256>>>(p_X1, ln2_w, p_Xnh, p_Xnl);
    // 7+8. h = geglu(Xn @ W_fc1_interleaved^T)
    gemm_bf16s<2><<<dim3(FFN2 / 128, T / 128), 256, smemBytes>>>(
        p_Xnh, p_Xnl, p_Wf1h, p_Wf1l, nullptr, nullptr,
        p_hh, p_hl, nullptr, nullptr, nullptr, nullptr, T, FFN2, DM);
    // 9. out = X1 + h @ W_fc2^T
    gemm_bf16s<1><<<dim3(DM / 128, T / 128), 256, smemBytes>>>(
        p_hh, p_hl, p_Wf2h, p_Wf2l, p_X1, out,
        nullptr, nullptr, nullptr, nullptr, nullptr, nullptr, T, DM, FFN);
}

// round 17
// speedup vs baseline: 2.8760x; 1.0373x over previous
#include <cuda_runtime.h>
#include <cuda_bf16.h>
#include <math.h>
#include <stdint.h>

// ----------------------------------------------------------------------------
// Problem constants
// ----------------------------------------------------------------------------
#define B        4
#define S        2048
#define T        (B * S)          // 8192 tokens
#define DM       1024             // d_model
#define NH       16               // heads
#define DH       64               // head dim
#define QKV3     (3 * NH * DH)    // 3072
#define FFN      4096
#define FFN2     (2 * FFN)        // 8192

// ----------------------------------------------------------------------------
// Scratch (device globals -> no allocation inside kernel_launch)
// ----------------------------------------------------------------------------
__device__ float g_X1  [(size_t)T * DM];    // X + attn @ Wo^T

__device__ __nv_bfloat16 g_Xnh [(size_t)T * DM];
__device__ __nv_bfloat16 g_Xnl [(size_t)T * DM];
__device__ __nv_bfloat16 g_atth[(size_t)T * DM];
__device__ __nv_bfloat16 g_attl[(size_t)T * DM];
__device__ __nv_bfloat16 g_hh  [(size_t)T * FFN];
__device__ __nv_bfloat16 g_hl  [(size_t)T * FFN];
__device__ __nv_bfloat16 g_Wqh [(size_t)QKV3 * DM];
__device__ __nv_bfloat16 g_Wql [(size_t)QKV3 * DM];
__device__ __nv_bfloat16 g_Woh [(size_t)DM * DM];
__device__ __nv_bfloat16 g_Wol [(size_t)DM * DM];
__device__ __nv_bfloat16 g_Wf1h[(size_t)FFN2 * DM];   // row-interleaved (a0,g0,a1,g1,...)
__device__ __nv_bfloat16 g_Wf1l[(size_t)FFN2 * DM];
__device__ __nv_bfloat16 g_Wf2h[(size_t)DM * FFN];
__device__ __nv_bfloat16 g_Wf2l[(size_t)DM * FFN];
__device__ __nv_bfloat16 g_Qh [(size_t)T * DM];   // [b,h,s,d]  (pre-scaled 1/8)
__device__ __nv_bfloat16 g_Ql [(size_t)T * DM];
__device__ __nv_bfloat16 g_Kh [(size_t)T * DM];   // [b,h,s,d]
__device__ __nv_bfloat16 g_Kl [(size_t)T * DM];
__device__ __nv_bfloat16 g_Vth[(size_t)T * DM];   // [b,h,d,s]  (transposed)
__device__ __nv_bfloat16 g_Vtl[(size_t)T * DM];

// ----------------------------------------------------------------------------
// fp32 -> (hi, lo) bf16 split
// ----------------------------------------------------------------------------
__device__ __forceinline__ void split1(float x, __nv_bfloat16& h, __nv_bfloat16& l) {
    h = __float2bfloat16_rn(x);
    l = __float2bfloat16_rn(x - __bfloat162float(h));
}

// ----------------------------------------------------------------------------
// Fast exp on FMA pipe (no MUFU). rel err < 3e-8 on clamped range.
// ----------------------------------------------------------------------------
__device__ __forceinline__ float fexp(float x) {
    x = fminf(fmaxf(x, -87.0f), 87.0f);
    const float y = x * 1.4426950408889634f;
    const float z = y + 12582912.0f;
    const int   n = __float_as_int(z) - 0x4B400000;
    const float f = y - (z - 12582912.0f);
    float p = 1.5403530393381609e-4f;
    p = fmaf(p, f, 1.3333558146428443e-3f);
    p = fmaf(p, f, 9.6181291076284772e-3f);
    p = fmaf(p, f, 5.5504108664821580e-2f);
    p = fmaf(p, f, 2.4022650695910072e-1f);
    p = fmaf(p, f, 6.9314718055994531e-1f);
    p = fmaf(p, f, 1.0f);
    return __int_as_float(__float_as_int(p) + (n << 23));
}

__device__ __forceinline__ float frcp(float x) {
    float r;
    asm("rcp.approx.f32 %0, %1;" : "=f"(r) : "f"(x));
    return r;
}

// GEGLU scalar
__device__ __forceinline__ float geglu1(float a, float g) {
    const float z = 0.7978845608028654f * (g + 0.044715f * g * g * g);
    const float ew = fexp(-2.0f * z);
    return a * g * frcp(1.0f + ew);
}

// ----------------------------------------------------------------------------
// Async copy + ldmatrix helpers
// ----------------------------------------------------------------------------
__device__ __forceinline__ void cpasync16(uint32_t dst, const void* src) {
    asm volatile("cp.async.cg.shared.global [%0], [%1], 16;" :: "r"(dst), "l"(src));
}
__device__ __forceinline__ void cp_commit() {
    asm volatile("cp.async.commit_group;");
}
__device__ __forceinline__ void ldsm4(uint32_t* r, uint32_t a) {
    asm volatile("ldmatrix.sync.aligned.m8n8.x4.shared.b16 {%0,%1,%2,%3}, [%4];"
        : "=r"(r[0]), "=r"(r[1]), "=r"(r[2]), "=r"(r[3]) : "r"(a));
}

// ----------------------------------------------------------------------------
// qkv epilogue scatter (validated round 13)
// ----------------------------------------------------------------------------
__device__ __forceinline__ void scatter_qkv(int t, int cc, float v,
                                            __nv_bfloat16* __restrict__ Qh,
                                            __nv_bfloat16* __restrict__ Ql,
                                            __nv_bfloat16* __restrict__ Kh,
                                            __nv_bfloat16* __restrict__ Kl,
                                            __nv_bfloat16* __restrict__ Vth,
                                            __nv_bfloat16* __restrict__ Vtl) {
    const int h   = cc / 192;
    const int rem = cc - h * 192;
    const int d   = rem / 3;
    const int c   = rem - d * 3;
    const int b   = t >> 11;
    const int s   = t & 2047;
    __nv_bfloat16 hh, ll;
    if (c == 0) {
        split1(v * 0.125f, hh, ll);
        const size_t qk = (((size_t)(b * NH + h)) * S + s) * DH + d;
        Qh[qk] = hh; Ql[qk] = ll;
    } else if (c == 1) {
        split1(v, hh, ll);
        const size_t qk = (((size_t)(b * NH + h)) * S + s) * DH + d;
        Kh[qk] = hh; Kl[qk] = ll;
    } else {
        split1(v, hh, ll);
        const size_t vt = (((size_t)(b * NH + h)) * DH + d) * S + s;
        Vth[vt] = hh; Vtl[vt] = ll;
    }
}

// ----------------------------------------------------------------------------
// Weight split: float4-vectorized
// ----------------------------------------------------------------------------
__global__ __launch_bounds__(256) void split_kernel(const float* __restrict__ X,
                                                    __nv_bfloat16* __restrict__ H,
                                                    __nv_bfloat16* __restrict__ L,
                                                    int n4) {
    const int gid = blockIdx.x * 256 + threadIdx.x;
    if (gid >= n4) return;
    const float4 v = ((const float4*)X)[gid];
    __nv_bfloat16 h0, h1, h2, h3, l0, l1, l2, l3;
    split1(v.x, h0, l0); split1(v.y, h1, l1);
    split1(v.z, h2, l2); split1(v.w, h3, l3);
    __nv_bfloat162* Hp = (__nv_bfloat162*)H;
    __nv_bfloat162* Lp = (__nv_bfloat162*)L;
    Hp[gid * 2]     = __nv_bfloat162(h0, h1);
    Hp[gid * 2 + 1] = __nv_bfloat162(h2, h3);
    Lp[gid * 2]     = __nv_bfloat162(l0, l1);
    Lp[gid * 2 + 1] = __nv_bfloat162(l2, l3);
}

// ----------------------------------------------------------------------------
// W_fc1 split with row interleave
// ----------------------------------------------------------------------------
__global__ __launch_bounds__(256) void split_ilv_kernel(const float* __restrict__ X,
                                                        __nv_bfloat16* __restrict__ H,
                                                        __nv_bfloat16* __restrict__ L,
                                                        int n4) {
    const int gid = blockIdx.x * 256 + threadIdx.x;
    if (gid >= n4) return;
    const int e0   = gid * 4;
    const int srow = e0 >> 10;
    const int col  = e0 & 1023;
    const int drow = (srow < FFN) ? (srow * 2) : ((srow - FFN) * 2 + 1);
    const float4 v = ((const float4*)X)[gid];
    __nv_bfloat16 h0, h1, h2, h3, l0, l1, l2, l3;
    split1(v.x, h0, l0); split1(v.y, h1, l1);
    split1(v.z, h2, l2); split1(v.w, h3, l3);
    const size_t d4 = ((size_t)drow * DM + col) >> 1;
    __nv_bfloat162* Hp = (__nv_bfloat162*)H;
    __nv_bfloat162* Lp = (__nv_bfloat162*)L;
    Hp[d4]     = __nv_bfloat162(h0, h1);
    Hp[d4 + 1] = __nv_bfloat162(h2, h3);
    Lp[d4]     = __nv_bfloat162(l0, l1);
    Lp[d4 + 1] = __nv_bfloat162(l2, l3);
}

// ----------------------------------------------------------------------------
// LayerNorm with fused hi/lo split output
// ----------------------------------------------------------------------------
__global__ __launch_bounds__(256) void ln_split_kernel(const float* __restrict__ X,
                                                       const float* __restrict__ w,
                                                       __nv_bfloat16* __restrict__ Hh,
                                                       __nv_bfloat16* __restrict__ Hl) {
    const int row = blockIdx.x;
    const int tid = threadIdx.x;
    const float4* xp = (const float4*)(X + (size_t)row * DM);
    float4 v = xp[tid];

    float s  = v.x + v.y + v.z + v.w;
    float sq = v.x * v.x + v.y * v.y + v.z * v.z + v.w * v.w;

    __shared__ float rs[256];
    __shared__ float rq[256];
    rs[tid] = s; rq[tid] = sq;
    __syncthreads();
    #pragma unroll
    for (int o = 128; o >= 1; o >>= 1) {
        if (tid < o) { rs[tid] += rs[tid + o]; rq[tid] += rq[tid + o]; }
        __syncthreads();
    }
    const float mu   = rs[0] * (1.0f / DM);
    const float var  = rq[0] * (1.0f / DM) - mu * mu;
    const float rstd = rsqrtf(var + 1e-5f);

    const float4 wv = ((const float4*)w)[tid];
    float y0 = (v.x - mu) * rstd * wv.x;
    float y1 = (v.y - mu) * rstd * wv.y;
    float y2 = (v.z - mu) * rstd * wv.z;
    float y3 = (v.w - mu) * rstd * wv.w;

    __nv_bfloat16 h0, h1, h2, h3, l0, l1, l2, l3;
    split1(y0, h0, l0); split1(y1, h1, l1);
    split1(y2, h2, l2); split1(y3, h3, l3);
    __nv_bfloat162* Hp = (__nv_bfloat162*)(Hh + (size_t)row * DM);
    __nv_bfloat162* Lp = (__nv_bfloat162*)(Hl + (size_t)row * DM);
    Hp[tid * 2]     = __nv_bfloat162(h0, h1);
    Hp[tid * 2 + 1] = __nv_bfloat162(h2, h3);
    Lp[tid * 2]     = __nv_bfloat162(l0, l1);
    Lp[tid * 2 + 1] = __nv_bfloat162(l2, l3);
}

// ----------------------------------------------------------------------------
// mma.sync m16n8k16 bf16 -> fp32
// ----------------------------------------------------------------------------
__device__ __forceinline__ void mma16816(float* c, const uint32_t* a, const uint32_t* b) {
    asm volatile(
        "mma.sync.aligned.m16n8k16.row.col.f32.bf16.bf16.f32 "
        "{%0,%1,%2,%3},{%4,%5,%6,%7},{%8,%9},{%0,%1,%2,%3};"
        : "+f"(c[0]), "+f"(c[1]), "+f"(c[2]), "+f"(c[3])
        : "r"(a[0]), "r"(a[1]), "r"(a[2]), "r"(a[3]), "r"(b[0]), "r"(b[1]));
}

// ----------------------------------------------------------------------------
// Split-bf16 NT GEMM: 2-stage cp.async pipeline + ldmatrix, 2 CTAs/SM.
// B fragments via ldsm4 (paired j-tiles).  (validated round 16)
// EPI 0: C=AB  EPI 1: C=R+AB  EPI 2: fused GEGLU  EPI 3: fused qkv scatter
// ----------------------------------------------------------------------------
#define STAGES 2
#define PITCH  40
#define SEGB   (128 * PITCH * 2)   // 10240

template <int EPI>
__global__ __launch_bounds__(256, 2) void gemm_bf16s(const __nv_bfloat16* __restrict__ Ah,
                                                     const __nv_bfloat16* __restrict__ Al,
                                                     const __nv_bfloat16* __restrict__ Bh,
                                                     const __nv_bfloat16* __restrict__ Bl,
                                                     const float* __restrict__ R,
                                                     float* __restrict__ C,
                                                     __nv_bfloat16* __restrict__ P0,
                                                     __nv_bfloat16* __restrict__ P1,
                                                     __nv_bfloat16* __restrict__ P2,
                                                     __nv_bfloat16* __restrict__ P3,
                                                     __nv_bfloat16* __restrict__ P4,
                                                     __nv_bfloat16* __restrict__ P5,
                                                     int M, int N, int K) {
    extern __shared__ __nv_bfloat16 smem[];
    const uint32_t sbase = (uint32_t)__cvta_generic_to_shared(smem);

    const int tid  = threadIdx.x;
    const int lane = tid & 31;
    const int warp = tid >> 5;
    const int wm   = warp >> 2;
    const int wn   = warp & 3;

    const int m0 = blockIdx.y * 128;
    const int n0 = blockIdx.x * 128;

    const int r0 = tid >> 2;
    const int r1 = r0 + 64;
    const int c0 = (tid & 3) * 8;

    const size_t aOff0 = (size_t)(m0 + r0) * K + c0;
    const size_t aOff1 = (size_t)(m0 + r1) * K + c0;
    const size_t bOff0 = (size_t)(n0 + r0) * K + c0;
    const size_t bOff1 = (size_t)(n0 + r1) * K + c0;
    const uint32_t d0 = (uint32_t)(r0 * PITCH + c0) * 2;
    const uint32_t d1 = (uint32_t)(r1 * PITCH + c0) * 2;

    const uint32_t aRowB = (uint32_t)(((wm * 64 + (lane & 15)) * PITCH
                                       + ((lane >> 4) << 3)) * 2);
    const uint32_t bRow4B = (uint32_t)(((wn * 32 + (lane & 7) + (((lane >> 4) & 1) << 3)) * PITCH
                                        + (((lane >> 3) & 1) << 3)) * 2);

    float acc[4][4][4];
    #pragma unroll
    for (int i = 0; i < 4; i++)
        #pragma unroll
        for (int j = 0; j < 4; j++)
            #pragma unroll
            for (int r = 0; r < 4; r++) acc[i][j][r] = 0.0f;

    const int ntiles = K >> 5;

    auto issue = [&](int st, int t) {
        const int k0 = t * 32;
        const uint32_t sb = sbase + (uint32_t)st * 4 * SEGB;
        cpasync16(sb + 0 * SEGB + d0, Ah + aOff0 + k0);
        cpasync16(sb + 0 * SEGB + d1, Ah + aOff1 + k0);
        cpasync16(sb + 1 * SEGB + d0, Al + aOff0 + k0);
        cpasync16(sb + 1 * SEGB + d1, Al + aOff1 + k0);
        cpasync16(sb + 2 * SEGB + d0, Bh + bOff0 + k0);
        cpasync16(sb + 2 * SEGB + d1, Bh + bOff1 + k0);
        cpasync16(sb + 3 * SEGB + d0, Bl + bOff0 + k0);
        cpasync16(sb + 3 * SEGB + d1, Bl + bOff1 + k0);
        cp_commit();
    };

    issue(0, 0);
    if (ntiles > 1) issue(1, 1);

    for (int t = 0; t < ntiles; t++) {
        const int st = t & 1;
        if (t + 1 < ntiles) {
            asm volatile("cp.async.wait_group 1;");
        } else {
            asm volatile("cp.async.wait_group 0;");
        }
        __syncthreads();

        const uint32_t sb  = sbase + (uint32_t)st * 4 * SEGB;
        const uint32_t pAh = sb;
        const uint32_t pAl = sb + 1 * SEGB;
        const uint32_t pBh = sb + 2 * SEGB;
        const uint32_t pBl = sb + 3 * SEGB;

        #pragma unroll
        for (int kc = 0; kc < 2; kc++) {
            const uint32_t kb = (uint32_t)kc * 32;
            uint32_t ah[4][4], al[4][4];
            uint32_t bfh[2][4], bfl[2][4];   // [j-pair][{j:k0, j:k8, j+1:k0, j+1:k8}]
            #pragma unroll
            for (int i = 0; i < 4; i++) {
                const uint32_t ao = aRowB + (uint32_t)i * (16 * PITCH * 2) + kb;
                ldsm4(ah[i], pAh + ao);
                ldsm4(al[i], pAl + ao);
            }
            #pragma unroll
            for (int jj = 0; jj < 2; jj++) {
                const uint32_t bo = bRow4B + (uint32_t)jj * (16 * PITCH * 2) + kb;
                ldsm4(bfh[jj], pBh + bo);
                ldsm4(bfl[jj], pBl + bo);
            }
            #pragma unroll
            for (int i = 0; i < 4; i++)
                #pragma unroll
                for (int j = 0; j < 4; j++)
                    mma16816(acc[i][j], ah[i], &bfh[j >> 1][(j & 1) * 2]);
            #pragma unroll
            for (int i = 0; i < 4; i++)
                #pragma unroll
                for (int j = 0; j < 4; j++)
                    mma16816(acc[i][j], al[i], &bfh[j >> 1][(j & 1) * 2]);
            #pragma unroll
            for (int i = 0; i < 4; i++)
                #pragma unroll
                for (int j = 0; j < 4; j++)
                    mma16816(acc[i][j], ah[i], &bfl[j >> 1][(j & 1) * 2]);
        }

        if (t + 2 < ntiles) {
            __syncthreads();
            issue(st, t + 2);
        }
    }

    // epilogue
    const int g = lane >> 2;
    #pragma unroll
    for (int i = 0; i < 4; i++) {
        const int row = m0 + wm * 64 + i * 16 + g;
        #pragma unroll
        for (int j = 0; j < 4; j++) {
            const int col = n0 + wn * 32 + j * 8 + (lane & 3) * 2;
            if (EPI == 3) {
                scatter_qkv(row,     col,     acc[i][j][0], P0, P1, P2, P3, P4, P5);
                scatter_qkv(row,     col + 1, acc[i][j][1], P0, P1, P2, P3, P4, P5);
                scatter_qkv(row + 8, col,     acc[i][j][2], P0, P1, P2, P3, P4, P5);
                scatter_qkv(row + 8, col + 1, acc[i][j][3], P0, P1, P2, P3, P4, P5);
            } else if (EPI == 2) {
                const int oc = col >> 1;
                const float v0 = geglu1(acc[i][j][0], acc[i][j][1]);
                const float v1 = geglu1(acc[i][j][2], acc[i][j][3]);
                __nv_bfloat16 h0, l0, h1, l1;
                split1(v0, h0, l0);
                split1(v1, h1, l1);
                const size_t o0 = (size_t)row * (N >> 1) + oc;
                const size_t o1 = (size_t)(row + 8) * (N >> 1) + oc;
                P0[o0] = h0; P1[o0] = l0;
                P0[o1] = h1; P1[o1] = l1;
            } else {
                const size_t o0 = (size_t)row * N + col;
                const size_t o1 = (size_t)(row + 8) * N + col;
                float2 v0 = {acc[i][j][0], acc[i][j][1]};
                float2 v1 = {acc[i][j][2], acc[i][j][3]};
                if (EPI == 1) {
                    const float2 r0v = *(const float2*)(R + o0);
                    const float2 r1v = *(const float2*)(R + o1);
                    v0.x += r0v.x; v0.y += r0v.y;
                    v1.x += r1v.x; v1.y += r1v.y;
                }
                *(float2*)(C + o0) = v0;
                *(float2*)(C + o1) = v1;
            }
        }
    }
}

// ----------------------------------------------------------------------------
// Tensor-core flash attention: cp.async K/V double-buffer (round 14) +
// ldsm4 K/V fragment loads (this round). Softmax/pack/epilogue unchanged.
// ----------------------------------------------------------------------------
#define FP    72
#define FSEG  (64 * FP)            // elements per array per stage
#define FSEGB (FSEG * 2)           // 9216 bytes
#define FBUFB (4 * FSEGB)          // 36864 bytes per stage
#define FSMEM (2 * FBUFB)          // 73728 bytes total

__global__ __launch_bounds__(256) void flash_mma(const __nv_bfloat16* __restrict__ Qh,
                                                 const __nv_bfloat16* __restrict__ Ql,
                                                 const __nv_bfloat16* __restrict__ Kh,
                                                 const __nv_bfloat16* __restrict__ Kl,
                                                 const __nv_bfloat16* __restrict__ Vth,
                                                 const __nv_bfloat16* __restrict__ Vtl,
                                                 __nv_bfloat16* __restrict__ Oh,
                                                 __nv_bfloat16* __restrict__ Ol) {
    extern __shared__ __nv_bfloat16 fsm[];
    const uint32_t fbase = (uint32_t)__cvta_generic_to_shared(fsm);

    const int tid  = threadIdx.x;
    const int lane = tid & 31;
    const int w    = tid >> 5;
    const int h    = blockIdx.y;
    const int b    = blockIdx.z;
    const int q0   = blockIdx.x * 128;
    const size_t bh  = (size_t)(b * NH + h) * S;
    const size_t bhd = (size_t)(b * NH + h) * DH;
    const int g  = lane >> 2;
    const int kq = (lane & 3) * 2;

    uint32_t qfh[4][4], qfl[4][4];
    {
        const int row = q0 + w * 16 + g;
        const __nv_bfloat16* b0h = Qh + (bh + row) * DH;
        const __nv_bfloat16* b8h = Qh + (bh + row + 8) * DH;
        const __nv_bfloat16* b0l = Ql + (bh + row) * DH;
        const __nv_bfloat16* b8l = Ql + (bh + row + 8) * DH;
        #pragma unroll
        for (int kc = 0; kc < 4; kc++) {
            const int o = kc * 16 + kq;
            qfh[kc][0] = *(const uint32_t*)(b0h + o);
            qfh[kc][1] = *(const uint32_t*)(b8h + o);
            qfh[kc][2] = *(const uint32_t*)(b0h + o + 8);
            qfh[kc][3] = *(const uint32_t*)(b8h + o + 8);
            qfl[kc][0] = *(const uint32_t*)(b0l + o);
            qfl[kc][1] = *(const uint32_t*)(b8l + o);
            qfl[kc][2] = *(const uint32_t*)(b0l + o + 8);
            qfl[kc][3] = *(const uint32_t*)(b8l + o + 8);
        }
    }

    float o[8][4];
    #pragma unroll
    for (int j = 0; j < 8; j++)
        #pragma unroll
        for (int r = 0; r < 4; r++) o[j][r] = 0.0f;
    float m0 = -INFINITY, m1 = -INFINITY;
    float l0 = 0.0f, l1 = 0.0f;

    const int i0 = tid, i1 = tid + 256;
    const int lr0 = i0 >> 3, lc0 = (i0 & 7) * 8;
    const int lr1 = i1 >> 3, lc1 = (i1 & 7) * 8;
    const uint32_t fd00 = (uint32_t)(lr0 * FP + lc0) * 2;
    const uint32_t fd01 = (uint32_t)(lr1 * FP + lc1) * 2;

    // ldsm4 per-lane row address within a K/V tile (j-paired, byte offset):
    // lanes 0-7: rows jj*16+0..7 col 0; 8-15: col +8; 16-23: rows +8; 24-31: both
    const uint32_t fRow4B = (uint32_t)((((lane & 7) + (((lane >> 4) & 1) << 3)) * FP
                                        + (((lane >> 3) & 1) << 3)) * 2);

    auto issue = [&](int st, int kt) {
        const uint32_t sb = fbase + (uint32_t)st * FBUFB;
        cpasync16(sb + 0 * FSEGB + fd00, Kh + (bh + kt + lr0) * DH + lc0);
        cpasync16(sb + 0 * FSEGB + fd01, Kh + (bh + kt + lr1) * DH + lc1);
        cpasync16(sb + 1 * FSEGB + fd00, Kl + (bh + kt + lr0) * DH + lc0);
        cpasync16(sb + 1 * FSEGB + fd01, Kl + (bh + kt + lr1) * DH + lc1);
        cpasync16(sb + 2 * FSEGB + fd00, Vth + (bhd + lr0) * S + kt + lc0);
        cpasync16(sb + 2 * FSEGB + fd01, Vth + (bhd + lr1) * S + kt + lc1);
        cpasync16(sb + 3 * FSEGB + fd00, Vtl + (bhd + lr0) * S + kt + lc0);
        cpasync16(sb + 3 * FSEGB + fd01, Vtl + (bhd + lr1) * S + kt + lc1);
        cp_commit();
    };

    const int ntiles = S / 64;
    issue(0, 0);
    issue(1, 64);

    for (int t = 0; t < ntiles; t++) {
        const int st = t & 1;
        if (t + 1 < ntiles) {
            asm volatile("cp.async.wait_group 1;");
        } else {
            asm volatile("cp.async.wait_group 0;");
        }
        __syncthreads();

        const uint32_t sb  = fbase + (uint32_t)st * FBUFB;
        const uint32_t pKh = sb;
        const uint32_t pKl = sb + 1 * FSEGB;
        const uint32_t pVh = sb + 2 * FSEGB;
        const uint32_t pVl = sb + 3 * FSEGB;

        // S = Q K^T  (ldsm4 K fragments, j-paired)
        float sc[8][4];
        #pragma unroll
        for (int j = 0; j < 8; j++)
            #pragma unroll
            for (int r = 0; r < 4; r++) sc[j][r] = 0.0f;

        #pragma unroll
        for (int kc = 0; kc < 4; kc++) {
            #pragma unroll
            for (int jj = 0; jj < 4; jj++) {
                const uint32_t ko = fRow4B + (uint32_t)jj * (16 * FP * 2)
                                  + (uint32_t)kc * 32;
                uint32_t k4h[4], k4l[4];
                ldsm4(k4h, pKh + ko);
                ldsm4(k4l, pKl + ko);
                mma16816(sc[2 * jj],     qfh[kc], &k4h[0]);
                mma16816(sc[2 * jj],     qfl[kc], &k4h[0]);
                mma16816(sc[2 * jj],     qfh[kc], &k4l[0]);
                mma16816(sc[2 * jj + 1], qfh[kc], &k4h[2]);
                mma16816(sc[2 * jj + 1], qfl[kc], &k4h[2]);
                mma16816(sc[2 * jj + 1], qfh[kc], &k4l[2]);
            }
        }

        float mx0 = sc[0][0], mx1 = sc[0][2];
        #pragma unroll
        for (int j = 0; j < 8; j++) {
            mx0 = fmaxf(mx0, fmaxf(sc[j][0], sc[j][1]));
            mx1 = fmaxf(mx1, fmaxf(sc[j][2], sc[j][3]));
        }
        mx0 = fmaxf(mx0, __shfl_xor_sync(0xffffffffu, mx0, 1));
        mx0 = fmaxf(mx0, __shfl_xor_sync(0xffffffffu, mx0, 2));
        mx1 = fmaxf(mx1, __shfl_xor_sync(0xffffffffu, mx1, 1));
        mx1 = fmaxf(mx1, __shfl_xor_sync(0xffffffffu, mx1, 2));

        const float mn0 = fmaxf(m0, mx0);
        const float mn1 = fmaxf(m1, mx1);
        const float c0 = fexp(m0 - mn0);
        const float c1 = fexp(m1 - mn1);
        m0 = mn0; m1 = mn1;

        float s0 = 0.0f, s1 = 0.0f;
        #pragma unroll
        for (int j = 0; j < 8; j++) {
            sc[j][0] = fexp(sc[j][0] - mn0);
            sc[j][1] = fexp(sc[j][1] - mn0);
            sc[j][2] = fexp(sc[j][2] - mn1);
            sc[j][3] = fexp(sc[j][3] - mn1);
            s0 += sc[j][0] + sc[j][1];
            s1 += sc[j][2] + sc[j][3];
        }
        s0 += __shfl_xor_sync(0xffffffffu, s0, 1);
        s0 += __shfl_xor_sync(0xffffffffu, s0, 2);
        s1 += __shfl_xor_sync(0xffffffffu, s1, 1);
        s1 += __shfl_xor_sync(0xffffffffu, s1, 2);
        l0 = l0 * c0 + s0;
        l1 = l1 * c1 + s1;

        #pragma unroll
        for (int j = 0; j < 8; j++) {
            o[j][0] *= c0; o[j][1] *= c0;
            o[j][2] *= c1; o[j][3] *= c1;
        }

        // O += P V  (P split hi/lo in registers; ldsm4 V fragments, j-paired)
        #pragma unroll
        for (int t2 = 0; t2 < 4; t2++) {
            uint32_t ph[4], pl[4];
            {
                const float* e = sc[2 * t2];
                const float* f = sc[2 * t2 + 1];
                __nv_bfloat16 hv[8], lv[8];
                split1(e[0], hv[0], lv[0]); split1(e[1], hv[1], lv[1]);
                split1(e[2], hv[2], lv[2]); split1(e[3], hv[3], lv[3]);
                split1(f[0], hv[4], lv[4]); split1(f[1], hv[5], lv[5]);
                split1(f[2], hv[6], lv[6]); split1(f[3], hv[7], lv[7]);
                __nv_bfloat162 t0 = __nv_bfloat162(hv[0], hv[1]);
                __nv_bfloat162 t1 = __nv_bfloat162(hv[2], hv[3]);
                __nv_bfloat162 t2v = __nv_bfloat162(hv[4], hv[5]);
                __nv_bfloat162 t3 = __nv_bfloat162(hv[6], hv[7]);
                ph[0] = *(uint32_t*)&t0; ph[1] = *(uint32_t*)&t1;
                ph[2] = *(uint32_t*)&t2v; ph[3] = *(uint32_t*)&t3;
                t0 = __nv_bfloat162(lv[0], lv[1]);
                t1 = __nv_bfloat162(lv[2], lv[3]);
                t2v = __nv_bfloat162(lv[4], lv[5]);
                t3 = __nv_bfloat162(lv[6], lv[7]);
                pl[0] = *(uint32_t*)&t0; pl[1] = *(uint32_t*)&t1;
                pl[2] = *(uint32_t*)&t2v; pl[3] = *(uint32_t*)&t3;
            }
            #pragma unroll
            for (int jj = 0; jj < 4; jj++) {
                const uint32_t vo = fRow4B + (uint32_t)jj * (16 * FP * 2)
                                  + (uint32_t)t2 * 32;
                uint32_t v4h[4], v4l[4];
                ldsm4(v4h, pVh + vo);
                ldsm4(v4l, pVl + vo);
                mma16816(o[2 * jj],     ph, &v4h[0]);
                mma16816(o[2 * jj],     pl, &v4h[0]);
                mma16816(o[2 * jj],     ph, &v4l[0]);
                mma16816(o[2 * jj + 1], ph, &v4h[2]);
                mma16816(o[2 * jj + 1], pl, &v4h[2]);
                mma16816(o[2 * jj + 1], ph, &v4l[2]);
            }
        }

        if (t + 2 < ntiles) {
            __syncthreads();
            issue(st, (t + 2) * 64);
        }
    }

    const float inv0 = 1.0f / l0;
    const float inv1 = 1.0f / l1;
    const int row = q0 + w * 16 + g;
    const size_t t0 = (size_t)(b * S + row);
    const size_t t8 = t0 + 8;
    #pragma unroll
    for (int j = 0; j < 8; j++) {
        const int col = h * DH + j * 8 + kq;
        float v0 = o[j][0] * inv0, v1 = o[j][1] * inv0;
        float v2 = o[j][2] * inv1, v3 = o[j][3] * inv1;
        __nv_bfloat16 h0, h1, h2, h3, l0b, l1b, l2b, l3b;
        split1(v0, h0, l0b); split1(v1, h1, l1b);
        split1(v2, h2, l2b); split1(v3, h3, l3b);
        *(__nv_bfloat162*)(Oh + t0 * DM + col) = __nv_bfloat162(h0, h1);
        *(__nv_bfloat162*)(Ol + t0 * DM + col) = __nv_bfloat162(l0b, l1b);
        *(__nv_bfloat162*)(Oh + t8 * DM + col) = __nv_bfloat162(h2, h3);
        *(__nv_bfloat162*)(Ol + t8 * DM + col) = __nv_bfloat162(l2b, l3b);
    }
}

// ----------------------------------------------------------------------------
// Launch
// ----------------------------------------------------------------------------
extern "C" void kernel_launch(void* const* d_in, const int* in_sizes, int n_in,
                              void* d_out, int out_size) {
    const float* X     = (const float*)d_in[0];
    const float* W_qkv = (const float*)d_in[1];
    const float* W_o   = (const float*)d_in[2];
    const float* W_fc1 = (const float*)d_in[3];
    const float* W_fc2 = (const float*)d_in[4];
    const float* ln1_w = (const float*)d_in[5];
    const float* ln2_w = (const float*)d_in[6];
    float* out = (float*)d_out;

    float *p_X1;
    __nv_bfloat16 *p_Xnh, *p_Xnl, *p_atth, *p_attl, *p_hh, *p_hl;
    __nv_bfloat16 *p_Wqh, *p_Wql, *p_Woh, *p_Wol, *p_Wf1h, *p_Wf1l, *p_Wf2h, *p_Wf2l;
    __nv_bfloat16 *p_Qh, *p_Ql, *p_Kh, *p_Kl, *p_Vth, *p_Vtl;
    cudaGetSymbolAddress((void**)&p_X1,  g_X1);
    cudaGetSymbolAddress((void**)&p_Xnh,  g_Xnh);
    cudaGetSymbolAddress((void**)&p_Xnl,  g_Xnl);
    cudaGetSymbolAddress((void**)&p_atth, g_atth);
    cudaGetSymbolAddress((void**)&p_attl, g_attl);
    cudaGetSymbolAddress((void**)&p_hh,   g_hh);
    cudaGetSymbolAddress((void**)&p_hl,   g_hl);
    cudaGetSymbolAddress((void**)&p_Wqh,  g_Wqh);
    cudaGetSymbolAddress((void**)&p_Wql,  g_Wql);
    cudaGetSymbolAddress((void**)&p_Woh,  g_Woh);
    cudaGetSymbolAddress((void**)&p_Wol,  g_Wol);
    cudaGetSymbolAddress((void**)&p_Wf1h, g_Wf1h);
    cudaGetSymbolAddress((void**)&p_Wf1l, g_Wf1l);
    cudaGetSymbolAddress((void**)&p_Wf2h, g_Wf2h);
    cudaGetSymbolAddress((void**)&p_Wf2l, g_Wf2l);
    cudaGetSymbolAddress((void**)&p_Qh,  g_Qh);
    cudaGetSymbolAddress((void**)&p_Ql,  g_Ql);
    cudaGetSymbolAddress((void**)&p_Kh,  g_Kh);
    cudaGetSymbolAddress((void**)&p_Kl,  g_Kl);
    cudaGetSymbolAddress((void**)&p_Vth, g_Vth);
    cudaGetSymbolAddress((void**)&p_Vtl, g_Vtl);

    const int smemBytes = STAGES * 4 * SEGB; // 81920 -> 2 CTAs/SM
    cudaFuncSetAttribute(gemm_bf16s<1>, cudaFuncAttributeMaxDynamicSharedMemorySize, smemBytes);
    cudaFuncSetAttribute(gemm_bf16s<2>, cudaFuncAttributeMaxDynamicSharedMemorySize, smemBytes);
    cudaFuncSetAttribute(gemm_bf16s<3>, cudaFuncAttributeMaxDynamicSharedMemorySize, smemBytes);
    cudaFuncSetAttribute(flash_mma, cudaFuncAttributeMaxDynamicSharedMemorySize, FSMEM);

    // weight splits (fc1 interleaved for fused GEGLU)
    split_kernel<<<(QKV3 * DM / 4 + 255) / 256, 256>>>(W_qkv, p_Wqh, p_Wql, QKV3 * DM / 4);
    split_kernel<<<(DM * DM / 4 + 255) / 256, 256>>>(W_o, p_Woh, p_Wol, DM * DM / 4);
    split_ilv_kernel<<<(FFN2 * DM / 4 + 255) / 256, 256>>>(W_fc1, p_Wf1h, p_Wf1l, FFN2 * DM / 4);
    split_kernel<<<(DM * FFN / 4 + 255) / 256, 256>>>(W_fc2, p_Wf2h, p_Wf2l, DM * FFN / 4);

    // 1. LN1
    ln_split_kernel<<<T, 256>>>(X, ln1_w, p_Xnh, p_Xnl);
    // 2+3. qkv GEMM with fused reshape/split epilogue
    gemm_bf16s<3><<<dim3(QKV3 / 128, T / 128), 256, smemBytes>>>(
        p_Xnh, p_Xnl, p_Wqh, p_Wql, nullptr, nullptr,
        p_Qh, p_Ql, p_Kh, p_Kl, p_Vth, p_Vtl, T, QKV3, DM);
    // 4. attention (pipelined K/V loads + ldsm4 fragments)
    flash_mma<<<dim3(S / 128, NH, B), 256, FSMEM>>>(p_Qh, p_Ql, p_Kh, p_Kl, p_Vth, p_Vtl,
                                                    p_atth, p_attl);
    // 5. X1 = X + attn @ W_o^T
    gemm_bf16s<1><<<dim3(DM / 128, T / 128), 256, smemBytes>>>(
        p_atth, p_attl, p_Woh, p_Wol, X, p_X1,
        nullptr, nullptr, nullptr, nullptr, nullptr, nullptr, T, DM, DM);
    // 6. LN2
    ln_split_kernel<<<T, 256>>>(p_X1, ln2_w, p_Xnh, p_Xnl);
    // 7+8. h = geglu(Xn @ W_fc1_interleaved^T)
    gemm_bf16s<2><<<dim3(FFN2 / 128, T / 128), 256, smemBytes>>>(
        p_Xnh, p_Xnl, p_Wf1h, p_Wf1l, nullptr, nullptr,
        p_hh, p_hl, nullptr, nullptr, nullptr, nullptr, T, FFN2, DM);
    // 9. out = X1 + h @ W_fc2^T
    gemm_bf16s<1><<<dim3(DM / 128, T / 128), 256, smemBytes>>>(
        p_hh, p_hl, p_Wf2h, p_Wf2l, p_X1, out,
        nullptr, nullptr, nullptr, nullptr, nullptr, nullptr, T, DM, FFN);
}